// round 10
// baseline (speedup 1.0000x reference)
#include <cuda_runtime.h>
#include <cuda_bf16.h>
#include <cstdint>
#include <math.h>

#define Dm 1024
#define Hh 16
#define DHd 64
#define Bb 4
#define Ss 2048
#define NROWS (Bb*Ss)   // 8192
#define LOG2E 1.4426950408889634f

// ---------------- static device scratch ----------------
__device__ float g_mu[3*NROWS];
__device__ float g_rs[3*NROWS];
__device__ __nv_bfloat16 g_xh_q[NROWS*Dm]; __device__ __nv_bfloat16 g_xl_q[NROWS*Dm];
__device__ __nv_bfloat16 g_xh_k[NROWS*Dm]; __device__ __nv_bfloat16 g_xl_k[NROWS*Dm];
__device__ __nv_bfloat16 g_xh_v[NROWS*Dm]; __device__ __nv_bfloat16 g_xl_v[NROWS*Dm];
__device__ __nv_bfloat16 g_wh[4*Dm*Dm];
__device__ __nv_bfloat16 g_wl[4*Dm*Dm];
__device__ float g_c1[3*Dm];
__device__ float g_c2[3*Dm];
__device__ __nv_bfloat16 g_qh[NROWS*Dm], g_ql[NROWS*Dm];  // [bh][s][d], *LOG2E
__device__ __nv_bfloat16 g_kh[NROWS*Dm], g_kl[NROWS*Dm];  // [bh][s][d]
__device__ __nv_bfloat16 g_vh[NROWS*Dm], g_vl[NROWS*Dm];  // [bh][d][s]
__device__ __nv_bfloat16 g_aoh[NROWS*Dm], g_aol[NROWS*Dm]; // [b*s][D]

// ---------------- helpers ----------------
__device__ __forceinline__ uint32_t smem_u32(const void* p) {
    uint32_t a;
    asm("{ .reg .u64 t; cvta.to.shared.u64 t, %1; cvt.u32.u64 %0, t; }" : "=r"(a) : "l"(p));
    return a;
}
__device__ __forceinline__ void cp16(uint32_t s, const void* g) {
    asm volatile("cp.async.cg.shared.global [%0], [%1], 16;\n" :: "r"(s), "l"(g));
}
__device__ __forceinline__ void ldmA(uint32_t addr, uint32_t& r0, uint32_t& r1,
                                     uint32_t& r2, uint32_t& r3) {
    asm volatile("ldmatrix.sync.aligned.m8n8.x4.shared.b16 {%0,%1,%2,%3}, [%4];"
                 : "=r"(r0), "=r"(r1), "=r"(r2), "=r"(r3) : "r"(addr));
}
__device__ __forceinline__ void mma16816(float* c, const uint32_t* a,
                                         uint32_t b0, uint32_t b1) {
    asm volatile("mma.sync.aligned.m16n8k16.row.col.f32.bf16.bf16.f32 "
                 "{%0,%1,%2,%3}, {%4,%5,%6,%7}, {%8,%9}, {%0,%1,%2,%3};"
                 : "+f"(c[0]), "+f"(c[1]), "+f"(c[2]), "+f"(c[3])
                 : "r"(a[0]), "r"(a[1]), "r"(a[2]), "r"(a[3]), "r"(b0), "r"(b1));
}
__device__ __forceinline__ float ex2f(float x) {
    float r; asm("ex2.approx.f32 %0, %1;" : "=f"(r) : "f"(x)); return r;
}
__device__ __forceinline__ float exp2poly(float z) {
    z = fmaxf(z, -126.f);
    float t = z + 12582912.f;
    int n = __float_as_int(t) - 0x4B400000;
    float f = z - (t - 12582912.f);
    float p = fmaf(0.0096181291f, f, 0.055504109f);
    p = fmaf(p, f, 0.24022651f);
    p = fmaf(p, f, 0.69314718f);
    p = fmaf(p, f, 1.0f);
    return __int_as_float(__float_as_int(p) + (n << 23));
}
__device__ __forceinline__ uint32_t packbf2(float a, float b) {
    __nv_bfloat162 t;
    t.x = __float2bfloat16(a);
    t.y = __float2bfloat16(b);
    return *(uint32_t*)&t;
}

// ============================================================
// 1) LN stats + bf16 hi/lo split — warp per row
// ============================================================
__global__ void ln_split_kernel(const float* __restrict__ Q,
                                const float* __restrict__ K,
                                const float* __restrict__ V) {
    int wid = threadIdx.x >> 5, lane = threadIdx.x & 31;
    int row = blockIdx.x * 8 + wid;
    int which = row >> 13;
    int r = row & (NROWS - 1);
    const float* x; __nv_bfloat16* xh; __nv_bfloat16* xl;
    if (which == 0)      { x = Q; xh = g_xh_q; xl = g_xl_q; }
    else if (which == 1) { x = K; xh = g_xh_k; xl = g_xl_k; }
    else                 { x = V; xh = g_xh_v; xl = g_xl_v; }
    const float4* xr = (const float4*)(x + (size_t)r * Dm);

    float4 v[8];
    float s = 0.f, s2 = 0.f;
    #pragma unroll
    for (int i = 0; i < 8; i++) {
        v[i] = xr[lane + i * 32];
        s  += v[i].x + v[i].y + v[i].z + v[i].w;
        s2 += v[i].x * v[i].x + v[i].y * v[i].y + v[i].z * v[i].z + v[i].w * v[i].w;
    }
    #pragma unroll
    for (int o = 16; o > 0; o >>= 1) {
        s  += __shfl_xor_sync(0xffffffffu, s,  o);
        s2 += __shfl_xor_sync(0xffffffffu, s2, o);
    }
    float muv = s / (float)Dm;
    float var = s2 / (float)Dm - muv * muv;
    if (lane == 0) {
        g_mu[row] = muv;
        g_rs[row] = rsqrtf(var + 1e-6f);
    }
    uint2* xhp = (uint2*)(xh + (size_t)r * Dm);
    uint2* xlp = (uint2*)(xl + (size_t)r * Dm);
    #pragma unroll
    for (int i = 0; i < 8; i++) {
        __nv_bfloat16 h0 = __float2bfloat16(v[i].x), h1 = __float2bfloat16(v[i].y);
        __nv_bfloat16 h2 = __float2bfloat16(v[i].z), h3 = __float2bfloat16(v[i].w);
        uint2 hv, lv;
        __nv_bfloat162 p01, p23;
        p01.x = h0; p01.y = h1; p23.x = h2; p23.y = h3;
        hv.x = *(uint32_t*)&p01; hv.y = *(uint32_t*)&p23;
        lv.x = packbf2(v[i].x - __bfloat162float(h0), v[i].y - __bfloat162float(h1));
        lv.y = packbf2(v[i].z - __bfloat162float(h2), v[i].w - __bfloat162float(h3));
        xhp[lane + i * 32] = hv;
        xlp[lane + i * 32] = lv;
    }
}

// ============================================================
// 2) weight prep + fused column constants (c1/c2 pre-zeroed)
// ============================================================
__global__ void wprep_kernel(const float* __restrict__ Wq, const float* __restrict__ Wk,
                             const float* __restrict__ Wv, const float* __restrict__ Wo,
                             const float* __restrict__ gamma, const float* __restrict__ beta,
                             const float* __restrict__ bq, const float* __restrict__ bk,
                             const float* __restrict__ bv) {
    int w = blockIdx.z;
    const float* W = (w == 0) ? Wq : (w == 1) ? Wk : (w == 2) ? Wv : Wo;
    const float* b = (w == 0) ? bq : (w == 1) ? bk : bv;
    __shared__ float ts[64][65];
    int n0 = blockIdx.x * 64, k0 = blockIdx.y * 64;
    int tx = threadIdx.x & 63, ty = threadIdx.x >> 6;

    float s1 = 0.f, s2 = 0.f;
    #pragma unroll
    for (int l = 0; l < 16; l++) {
        int k = ty + l * 4;
        float wv = W[(size_t)(k0 + k) * Dm + n0 + tx];
        float g = (w < 3) ? gamma[k0 + k] : 1.f;
        float gw = g * wv;
        ts[k][tx] = gw;
        if (w < 3) { s1 += gw; s2 += beta[k0 + k] * wv; }
    }
    if (w < 3) {
        if (k0 == 0 && ty == 0) s2 += b[n0 + tx];
        atomicAdd(&g_c1[w * Dm + n0 + tx], s1);
        atomicAdd(&g_c2[w * Dm + n0 + tx], s2);
    }
    __syncthreads();
    __nv_bfloat16* whp = g_wh + (size_t)w * Dm * Dm;
    __nv_bfloat16* wlp = g_wl + (size_t)w * Dm * Dm;
    #pragma unroll
    for (int l = 0; l < 16; l++) {
        int n = ty + l * 4;
        float val = ts[tx][n];
        __nv_bfloat16 h = __float2bfloat16(val);
        size_t o = (size_t)(n0 + n) * Dm + k0 + tx;
        whp[o] = h;
        wlp[o] = __float2bfloat16(val - __bfloat162float(h));
    }
}

// ============================================================
// 3) bf16 mma GEMM (unchanged from round 9 — at HMMA ceiling)
// ============================================================
#define BM 128
#define BN 128
#define BK 32
#define KBYTES 64
#define STG   32768
#define NSTG  3
#define NT    32

#define SW(r, kc) ((uint32_t)((r) * KBYTES + ((((kc) ^ (((r) >> 1) & 3))) << 4)))

template<int MODE>
__global__ void __launch_bounds__(256, 2) gemm_mma_kernel(
    const __nv_bfloat16* __restrict__ Ah, const __nv_bfloat16* __restrict__ Al,
    const __nv_bfloat16* __restrict__ Bh, const __nv_bfloat16* __restrict__ Bl,
    const float* __restrict__ c1, const float* __restrict__ c2,
    const float* __restrict__ rs, const float* __restrict__ mu,
    const float* __restrict__ resid,
    float* __restrict__ outF,
    __nv_bfloat16* __restrict__ outH, __nv_bfloat16* __restrict__ outL)
{
    extern __shared__ char smem[];
    uint32_t sbase = smem_u32(smem);
    int tid = threadIdx.x, lane = tid & 31, wid = tid >> 5;
    int warpM = wid & 1, warpN = wid >> 1;
    int m0 = blockIdx.y * BM, n0 = blockIdx.x * BN;

    float acc[4][4][4] = {};

    auto prefetch = [&](int t) {
        int s = t % NSTG;
        int kb = t * BK;
        uint32_t st = sbase + s * STG;
        #pragma unroll
        for (int l = 0; l < 8; l++) {
            int e = tid + l * 256;
            int tile = e >> 9;
            int idx = e & 511;
            int r = idx >> 2, kc = idx & 3;
            const __nv_bfloat16* p = (tile == 0) ? Ah : (tile == 1) ? Al
                                   : (tile == 2) ? Bh : Bl;
            int rb = (tile < 2) ? m0 : n0;
            cp16(st + tile * 8192 + SW(r, kc), p + (size_t)(rb + r) * Dm + kb + kc * 8);
        }
    };

    prefetch(0); asm volatile("cp.async.commit_group;\n" ::: "memory");
    prefetch(1); asm volatile("cp.async.commit_group;\n" ::: "memory");

    for (int t = 0; t < NT; t++) {
        asm volatile("cp.async.wait_group 1;\n" ::: "memory");
        __syncthreads();
        if (t + 2 < NT) prefetch(t + 2);
        asm volatile("cp.async.commit_group;\n" ::: "memory");

        uint32_t st = sbase + (t % NSTG) * STG;
        uint32_t sAh = st, sAl = st + 8192, sBh = st + 16384, sBl = st + 24576;
        #pragma unroll
        for (int ks = 0; ks < 2; ks++) {
            uint32_t ah[4][4], al[4][4];
            #pragma unroll
            for (int mf = 0; mf < 4; mf++) {
                int row = warpM * 64 + mf * 16 + (lane & 15);
                int ch = ks * 2 + (lane >> 4);
                uint32_t sw = SW(row, ch);
                ldmA(sAh + sw, ah[mf][0], ah[mf][1], ah[mf][2], ah[mf][3]);
                ldmA(sAl + sw, al[mf][0], al[mf][1], al[mf][2], al[mf][3]);
            }
            #pragma unroll
            for (int nf2 = 0; nf2 < 2; nf2++) {
                int nrow = warpN * 32 + nf2 * 16 + (lane & 7) + ((lane >> 4) << 3);
                int ch = ks * 2 + ((lane >> 3) & 1);
                uint32_t swb = SW(nrow, ch);
                uint32_t r0, r1, r2, r3;
                ldmA(sBh + swb, r0, r1, r2, r3);
                #pragma unroll
                for (int mf = 0; mf < 4; mf++) {
                    mma16816(acc[mf][2*nf2],   ah[mf], r0, r1);
                    mma16816(acc[mf][2*nf2+1], ah[mf], r2, r3);
                    mma16816(acc[mf][2*nf2],   al[mf], r0, r1);
                    mma16816(acc[mf][2*nf2+1], al[mf], r2, r3);
                }
                ldmA(sBl + swb, r0, r1, r2, r3);
                #pragma unroll
                for (int mf = 0; mf < 4; mf++) {
                    mma16816(acc[mf][2*nf2],   ah[mf], r0, r1);
                    mma16816(acc[mf][2*nf2+1], ah[mf], r2, r3);
                }
            }
        }
    }

    int groupID = lane >> 2, tg = lane & 3;
    #pragma unroll
    for (int mf = 0; mf < 4; mf++) {
        #pragma unroll
        for (int half = 0; half < 2; half++) {
            int r = m0 + warpM * 64 + mf * 16 + groupID + half * 8;
            float rsv = 1.f, muv = 0.f;
            if (MODE != 1) { rsv = rs[r]; muv = mu[r]; }
            int b = r >> 11, srow = r & 2047;
            #pragma unroll
            for (int nf = 0; nf < 4; nf++) {
                int c = n0 + warpN * 32 + nf * 8 + 2 * tg;
                float x0 = acc[mf][nf][2 * half + 0];
                float x1 = acc[mf][nf][2 * half + 1];
                if (MODE == 1) {
                    float2 bo2 = *(const float2*)(c2 + c);
                    float2 q2  = *(const float2*)(resid + (size_t)r * Dm + c);
                    float2 o;
                    o.x = x0 + bo2.x + q2.x;
                    o.y = x1 + bo2.y + q2.y;
                    *(float2*)(outF + (size_t)r * Dm + c) = o;
                } else {
                    float2 c1v = *(const float2*)(c1 + c);
                    float2 c2v = *(const float2*)(c2 + c);
                    float o0 = rsv * (x0 - muv * c1v.x) + c2v.x;
                    float o1 = rsv * (x1 - muv * c1v.y) + c2v.y;
                    if (MODE == 0) { o0 *= LOG2E; o1 *= LOG2E; }
                    __nv_bfloat16 h0 = __float2bfloat16(o0);
                    __nv_bfloat16 h1 = __float2bfloat16(o1);
                    float l0 = o0 - __bfloat162float(h0);
                    float l1 = o1 - __bfloat162float(h1);
                    int hd = c >> 6, dd = c & 63;
                    int bh = b * Hh + hd;
                    if (MODE == 2) {
                        size_t a0 = ((size_t)(bh * DHd + dd)) * Ss + srow;
                        size_t a1 = ((size_t)(bh * DHd + dd + 1)) * Ss + srow;
                        outH[a0] = h0; outH[a1] = h1;
                        outL[a0] = __float2bfloat16(l0);
                        outL[a1] = __float2bfloat16(l1);
                    } else {
                        size_t ad = ((size_t)(bh * Ss + srow)) * DHd + dd;
                        __nv_bfloat162 hp; hp.x = h0; hp.y = h1;
                        *(uint32_t*)(outH + ad) = *(uint32_t*)&hp;
                        *(uint32_t*)(outL + ad) = packbf2(l0, l1);
                    }
                }
            }
        }
    }
}

// ============================================================
// 4) tensor-core causal attention — 2 CTAs/SM.
//    ql re-loaded from smem per kv-tile (frees 16 regs for the
//    128-reg cap); qh persistent.
// ============================================================
__device__ __forceinline__ void loadKV(int bh, int t, uint32_t base, int tid) {
    int kt = t * 64;
    const __nv_bfloat16* khp = g_kh + ((size_t)bh * Ss + kt) * DHd;
    const __nv_bfloat16* klp = g_kl + ((size_t)bh * Ss + kt) * DHd;
    const __nv_bfloat16* vhp = g_vh + (size_t)bh * DHd * Ss + kt;
    const __nv_bfloat16* vlp = g_vl + (size_t)bh * DHd * Ss + kt;
    #pragma unroll
    for (int l = 0; l < 2; l++) {
        int e = tid + l * 256;
        int row = e >> 3, c = e & 7;
        uint32_t d = row * 128 + ((c ^ (row & 7)) << 4);
        cp16(base + d,         khp + (size_t)row * DHd + c * 8);
        cp16(base + 8192 + d,  klp + (size_t)row * DHd + c * 8);
        cp16(base + 16384 + d, vhp + (size_t)row * Ss + c * 8);
        cp16(base + 24576 + d, vlp + (size_t)row * Ss + c * 8);
    }
}

__global__ void __launch_bounds__(256, 2) attn_mma_kernel() {
    extern __shared__ char smraw[];
    uint32_t sb = smem_u32(smraw);
    const uint32_t QHs = sb;
    const uint32_t KVs = sb + 32768;
    int tid = threadIdx.x, lane = tid & 31, wid = tid >> 5;
    int groupID = lane >> 2, tg = lane & 3;
    int bh = blockIdx.y;
    int mt = (int)(gridDim.x - 1) - (int)blockIdx.x;
    int q0 = mt * 128;
    int numt = 2 * mt + 2;

    const __nv_bfloat16* qhp = g_qh + ((size_t)bh * Ss + q0) * DHd;
    const __nv_bfloat16* qlp = g_ql + ((size_t)bh * Ss + q0) * DHd;

    #pragma unroll
    for (int l = 0; l < 4; l++) {
        int e = tid + l * 256;
        int row = e >> 3, c = e & 7;
        uint32_t d = row * 128 + ((c ^ (row & 7)) << 4);
        cp16(QHs + d,         qhp + (size_t)row * DHd + c * 8);
        cp16(QHs + 16384 + d, qlp + (size_t)row * DHd + c * 8);
    }
    asm volatile("cp.async.commit_group;\n" ::: "memory");
    loadKV(bh, 0, KVs, tid);
    asm volatile("cp.async.commit_group;\n" ::: "memory");
    asm volatile("cp.async.wait_group 1;\n" ::: "memory");
    __syncthreads();

    uint32_t qh[4][4];
    #pragma unroll
    for (int kf = 0; kf < 4; kf++) {
        int row = wid * 16 + (lane & 15);
        int ch = 2 * kf + (lane >> 4);
        uint32_t ad = QHs + row * 128 + ((ch ^ (row & 7)) << 4);
        ldmA(ad, qh[kf][0], qh[kf][1], qh[kf][2], qh[kf][3]);
    }

    float m[2] = {-1e30f, -1e30f}, lsum[2] = {0.f, 0.f};
    float oacc[8][4] = {};

    for (int t = 0; t < numt; t++) {
        if (t + 1 < numt) loadKV(bh, t + 1, KVs + ((t + 1) & 1) * 32768, tid);
        asm volatile("cp.async.commit_group;\n" ::: "memory");
        asm volatile("cp.async.wait_group 1;\n" ::: "memory");
        __syncthreads();
        uint32_t KB = KVs + (t & 1) * 32768;

        // ---- S = Q K^T (qh*Kh + ql*Kh + qh*Kl) ----
        float sacc[8][4] = {};
        #pragma unroll
        for (int kf = 0; kf < 4; kf++) {
            // re-load ql fragment for this kf from Q smem
            uint32_t qlf[4];
            {
                int row = wid * 16 + (lane & 15);
                int ch = 2 * kf + (lane >> 4);
                uint32_t ad = QHs + 16384 + row * 128 + ((ch ^ (row & 7)) << 4);
                ldmA(ad, qlf[0], qlf[1], qlf[2], qlf[3]);
            }
            #pragma unroll
            for (int nf2 = 0; nf2 < 4; nf2++) {
                int row = nf2 * 16 + (lane & 15);
                int ch = 2 * kf + (lane >> 4);
                uint32_t sw = row * 128 + ((ch ^ (row & 7)) << 4);
                uint32_t r0, r1, r2, r3;
                ldmA(KB + sw, r0, r1, r2, r3);               // Kh
                mma16816(sacc[2 * nf2],     qh[kf], r0, r2);
                mma16816(sacc[2 * nf2 + 1], qh[kf], r1, r3);
                mma16816(sacc[2 * nf2],     qlf,    r0, r2);
                mma16816(sacc[2 * nf2 + 1], qlf,    r1, r3);
                ldmA(KB + 8192 + sw, r0, r1, r2, r3);        // Kl
                mma16816(sacc[2 * nf2],     qh[kf], r0, r2);
                mma16816(sacc[2 * nf2 + 1], qh[kf], r1, r3);
            }
        }

        if (t >= numt - 2) {
            int kt = t * 64;
            int qrow = q0 + wid * 16 + groupID;
            #pragma unroll
            for (int nf = 0; nf < 8; nf++) {
                int k0 = kt + nf * 8 + 2 * tg;
                if (k0     > qrow)     sacc[nf][0] = -1e30f;
                if (k0 + 1 > qrow)     sacc[nf][1] = -1e30f;
                if (k0     > qrow + 8) sacc[nf][2] = -1e30f;
                if (k0 + 1 > qrow + 8) sacc[nf][3] = -1e30f;
            }
        }

        float alpha[2];
        #pragma unroll
        for (int h = 0; h < 2; h++) {
            float rm = -1e30f;
            #pragma unroll
            for (int nf = 0; nf < 8; nf++)
                rm = fmaxf(rm, fmaxf(sacc[nf][2 * h], sacc[nf][2 * h + 1]));
            rm = fmaxf(rm, __shfl_xor_sync(0xffffffffu, rm, 1));
            rm = fmaxf(rm, __shfl_xor_sync(0xffffffffu, rm, 2));
            float mn = fmaxf(m[h], rm);
            alpha[h] = ex2f(m[h] - mn);
            m[h] = mn;
            float ls = 0.f;
            #pragma unroll
            for (int nf = 0; nf < 8; nf++) {
                float p0 = exp2poly(sacc[nf][2 * h]     - mn);
                float p1 = exp2poly(sacc[nf][2 * h + 1] - mn);
                sacc[nf][2 * h] = p0; sacc[nf][2 * h + 1] = p1;
                ls += p0 + p1;
            }
            lsum[h] = lsum[h] * alpha[h] + ls;
        }
        #pragma unroll
        for (int nd = 0; nd < 8; nd++) {
            oacc[nd][0] *= alpha[0]; oacc[nd][1] *= alpha[0];
            oacc[nd][2] *= alpha[1]; oacc[nd][3] *= alpha[1];
        }

        uint32_t pah[4][4], pal[4][4];
        #pragma unroll
        for (int kf = 0; kf < 4; kf++) {
            #pragma unroll
            for (int q = 0; q < 4; q++) {
                int nf = 2 * kf + (q >> 1);
                float x0 = sacc[nf][(q & 1) * 2], x1 = sacc[nf][(q & 1) * 2 + 1];
                __nv_bfloat16 h0 = __float2bfloat16(x0), h1 = __float2bfloat16(x1);
                __nv_bfloat162 hp; hp.x = h0; hp.y = h1;
                pah[kf][q] = *(uint32_t*)&hp;
                pal[kf][q] = packbf2(x0 - __bfloat162float(h0), x1 - __bfloat162float(h1));
            }
        }

        // ---- O += P V (pah*Vh + pal*Vh + pah*Vl) ----
        #pragma unroll
        for (int kf = 0; kf < 4; kf++) {
            #pragma unroll
            for (int nd2 = 0; nd2 < 4; nd2++) {
                int row = nd2 * 16 + (lane & 15);
                int ch = 2 * kf + (lane >> 4);
                uint32_t sw = row * 128 + ((ch ^ (row & 7)) << 4);
                uint32_t r0, r1, r2, r3;
                ldmA(KB + 16384 + sw, r0, r1, r2, r3);        // Vh
                mma16816(oacc[2 * nd2],     pah[kf], r0, r2);
                mma16816(oacc[2 * nd2 + 1], pah[kf], r1, r3);
                mma16816(oacc[2 * nd2],     pal[kf], r0, r2);
                mma16816(oacc[2 * nd2 + 1], pal[kf], r1, r3);
                ldmA(KB + 24576 + sw, r0, r1, r2, r3);        // Vl
                mma16816(oacc[2 * nd2],     pah[kf], r0, r2);
                mma16816(oacc[2 * nd2 + 1], pah[kf], r1, r3);
            }
        }
        __syncthreads();
    }

    #pragma unroll
    for (int h = 0; h < 2; h++) {
        lsum[h] += __shfl_xor_sync(0xffffffffu, lsum[h], 1);
        lsum[h] += __shfl_xor_sync(0xffffffffu, lsum[h], 2);
    }
    int b = bh >> 4, hd = bh & 15;
    #pragma unroll
    for (int h = 0; h < 2; h++) {
        int q = q0 + wid * 16 + groupID + 8 * h;
        float inv = 1.f / lsum[h];
        size_t rowbase = ((size_t)(b * Ss + q)) * Dm + hd * 64;
        #pragma unroll
        for (int nd = 0; nd < 8; nd++) {
            float x0 = oacc[nd][2 * h] * inv, x1 = oacc[nd][2 * h + 1] * inv;
            __nv_bfloat16 h0 = __float2bfloat16(x0), h1 = __float2bfloat16(x1);
            __nv_bfloat162 hp; hp.x = h0; hp.y = h1;
            size_t ad = rowbase + nd * 8 + 2 * tg;
            *(uint32_t*)(g_aoh + ad) = *(uint32_t*)&hp;
            *(uint32_t*)(g_aol + ad) = packbf2(x0 - __bfloat162float(h0),
                                               x1 - __bfloat162float(h1));
        }
    }
}

// ============================================================
// launch
// ============================================================
extern "C" void kernel_launch(void* const* d_in, const int* in_sizes, int n_in,
                              void* d_out, int out_size) {
    const float* Q     = (const float*)d_in[0];
    const float* K     = (const float*)d_in[1];
    const float* V     = (const float*)d_in[2];
    const float* Wq    = (const float*)d_in[3];
    const float* bq    = (const float*)d_in[4];
    const float* Wk    = (const float*)d_in[5];
    const float* bk    = (const float*)d_in[6];
    const float* Wv    = (const float*)d_in[7];
    const float* bv    = (const float*)d_in[8];
    const float* Wo    = (const float*)d_in[9];
    const float* bo    = (const float*)d_in[10];
    const float* gamma = (const float*)d_in[11];
    const float* beta  = (const float*)d_in[12];
    float* out = (float*)d_out;

    float *mu_p, *rs_p, *c1_p, *c2_p;
    __nv_bfloat16 *xhq, *xlq, *xhk, *xlk, *xhv, *xlv, *wh_p, *wl_p;
    __nv_bfloat16 *qh_p, *ql_p, *kh_p, *kl_p, *vh_p, *vl_p, *aoh_p, *aol_p;
    cudaGetSymbolAddress((void**)&mu_p, g_mu);
    cudaGetSymbolAddress((void**)&rs_p, g_rs);
    cudaGetSymbolAddress((void**)&c1_p, g_c1);
    cudaGetSymbolAddress((void**)&c2_p, g_c2);
    cudaGetSymbolAddress((void**)&xhq, g_xh_q);
    cudaGetSymbolAddress((void**)&xlq, g_xl_q);
    cudaGetSymbolAddress((void**)&xhk, g_xh_k);
    cudaGetSymbolAddress((void**)&xlk, g_xl_k);
    cudaGetSymbolAddress((void**)&xhv, g_xh_v);
    cudaGetSymbolAddress((void**)&xlv, g_xl_v);
    cudaGetSymbolAddress((void**)&wh_p, g_wh);
    cudaGetSymbolAddress((void**)&wl_p, g_wl);
    cudaGetSymbolAddress((void**)&qh_p, g_qh);
    cudaGetSymbolAddress((void**)&ql_p, g_ql);
    cudaGetSymbolAddress((void**)&kh_p, g_kh);
    cudaGetSymbolAddress((void**)&kl_p, g_kl);
    cudaGetSymbolAddress((void**)&vh_p, g_vh);
    cudaGetSymbolAddress((void**)&vl_p, g_vl);
    cudaGetSymbolAddress((void**)&aoh_p, g_aoh);
    cudaGetSymbolAddress((void**)&aol_p, g_aol);

    cudaMemsetAsync(c1_p, 0, 3 * Dm * sizeof(float));
    cudaMemsetAsync(c2_p, 0, 3 * Dm * sizeof(float));
    ln_split_kernel<<<3 * NROWS / 8, 256>>>(Q, K, V);
    wprep_kernel<<<dim3(16, 16, 4), 256>>>(Wq, Wk, Wv, Wo, gamma, beta, bq, bk, bv);

    size_t gsmem = NSTG * STG;   // 96K
    cudaFuncSetAttribute(gemm_mma_kernel<0>, cudaFuncAttributeMaxDynamicSharedMemorySize, (int)gsmem);
    cudaFuncSetAttribute(gemm_mma_kernel<1>, cudaFuncAttributeMaxDynamicSharedMemorySize, (int)gsmem);
    cudaFuncSetAttribute(gemm_mma_kernel<2>, cudaFuncAttributeMaxDynamicSharedMemorySize, (int)gsmem);
    cudaFuncSetAttribute(gemm_mma_kernel<3>, cudaFuncAttributeMaxDynamicSharedMemorySize, (int)gsmem);
    dim3 gg(Dm / BN, NROWS / BM);
    size_t WSZ = (size_t)Dm * Dm;

    gemm_mma_kernel<0><<<gg, 256, gsmem>>>(xhq, xlq, wh_p, wl_p,
                                           c1_p, c2_p, rs_p, mu_p, nullptr,
                                           nullptr, qh_p, ql_p);
    gemm_mma_kernel<3><<<gg, 256, gsmem>>>(xhk, xlk, wh_p + WSZ, wl_p + WSZ,
                                           c1_p + Dm, c2_p + Dm, rs_p + NROWS, mu_p + NROWS,
                                           nullptr, nullptr, kh_p, kl_p);
    gemm_mma_kernel<2><<<gg, 256, gsmem>>>(xhv, xlv, wh_p + 2 * WSZ, wl_p + 2 * WSZ,
                                           c1_p + 2 * Dm, c2_p + 2 * Dm,
                                           rs_p + 2 * NROWS, mu_p + 2 * NROWS,
                                           nullptr, nullptr, vh_p, vl_p);

    size_t asmem = 98304;
    cudaFuncSetAttribute(attn_mma_kernel, cudaFuncAttributeMaxDynamicSharedMemorySize, (int)asmem);
    attn_mma_kernel<<<dim3(16, 64), 256, asmem>>>();

    gemm_mma_kernel<1><<<gg, 256, gsmem>>>(aoh_p, aol_p, wh_p + 3 * WSZ, wl_p + 3 * WSZ,
                                           nullptr, bo, nullptr, nullptr, Q,
                                           out, nullptr, nullptr);
}

// round 11
// speedup vs baseline: 1.1565x; 1.1565x over previous
#include <cuda_runtime.h>
#include <cuda_fp16.h>
#include <cstdint>
#include <math.h>

#define Dm 1024
#define Hh 16
#define DHd 64
#define Bb 4
#define Ss 2048
#define NROWS (Bb*Ss)   // 8192
#define LOG2E 1.4426950408889634f

// ---------------- static device scratch ----------------
__device__ float g_mu[3*NROWS];
__device__ float g_rs[3*NROWS];
__device__ __half g_xh_q[NROWS*Dm]; __device__ __half g_xl_q[NROWS*Dm];
__device__ __half g_xh_k[NROWS*Dm]; __device__ __half g_xl_k[NROWS*Dm];
__device__ __half g_xh_v[NROWS*Dm]; __device__ __half g_xl_v[NROWS*Dm];
__device__ __half g_wh[4*Dm*Dm];
__device__ __half g_wl[4*Dm*Dm];
__device__ float g_c1[3*Dm];
__device__ float g_c2[3*Dm];
__device__ __half g_qh[NROWS*Dm], g_ql[NROWS*Dm];  // [bh][s][d], *LOG2E
__device__ __half g_kh[NROWS*Dm], g_kl[NROWS*Dm];  // [bh][s][d]
__device__ __half g_vh[NROWS*Dm];                  // [bh][d][s], single fp16
__device__ __half g_aoh[NROWS*Dm], g_aol[NROWS*Dm]; // [b*s][D]

// ---------------- helpers ----------------
__device__ __forceinline__ uint32_t smem_u32(const void* p) {
    uint32_t a;
    asm("{ .reg .u64 t; cvta.to.shared.u64 t, %1; cvt.u32.u64 %0, t; }" : "=r"(a) : "l"(p));
    return a;
}
__device__ __forceinline__ void cp16(uint32_t s, const void* g) {
    asm volatile("cp.async.cg.shared.global [%0], [%1], 16;\n" :: "r"(s), "l"(g));
}
__device__ __forceinline__ void ldmA(uint32_t addr, uint32_t& r0, uint32_t& r1,
                                     uint32_t& r2, uint32_t& r3) {
    asm volatile("ldmatrix.sync.aligned.m8n8.x4.shared.b16 {%0,%1,%2,%3}, [%4];"
                 : "=r"(r0), "=r"(r1), "=r"(r2), "=r"(r3) : "r"(addr));
}
__device__ __forceinline__ void mma16816(float* c, const uint32_t* a,
                                         uint32_t b0, uint32_t b1) {
    asm volatile("mma.sync.aligned.m16n8k16.row.col.f32.f16.f16.f32 "
                 "{%0,%1,%2,%3}, {%4,%5,%6,%7}, {%8,%9}, {%0,%1,%2,%3};"
                 : "+f"(c[0]), "+f"(c[1]), "+f"(c[2]), "+f"(c[3])
                 : "r"(a[0]), "r"(a[1]), "r"(a[2]), "r"(a[3]), "r"(b0), "r"(b1));
}
__device__ __forceinline__ float ex2f(float x) {
    float r; asm("ex2.approx.f32 %0, %1;" : "=f"(r) : "f"(x)); return r;
}
__device__ __forceinline__ float exp2poly(float z) {
    z = fmaxf(z, -126.f);
    float t = z + 12582912.f;
    int n = __float_as_int(t) - 0x4B400000;
    float f = z - (t - 12582912.f);
    float p = fmaf(0.0096181291f, f, 0.055504109f);
    p = fmaf(p, f, 0.24022651f);
    p = fmaf(p, f, 0.69314718f);
    p = fmaf(p, f, 1.0f);
    return __int_as_float(__float_as_int(p) + (n << 23));
}
__device__ __forceinline__ uint32_t packh2(float a, float b) {
    __half2 t;
    t.x = __float2half_rn(a);
    t.y = __float2half_rn(b);
    return *(uint32_t*)&t;
}

// ============================================================
// 1) LN stats + fp16 hi/lo split — warp per row
// ============================================================
__global__ void ln_split_kernel(const float* __restrict__ Q,
                                const float* __restrict__ K,
                                const float* __restrict__ V) {
    int wid = threadIdx.x >> 5, lane = threadIdx.x & 31;
    int row = blockIdx.x * 8 + wid;
    int which = row >> 13;
    int r = row & (NROWS - 1);
    const float* x; __half* xh; __half* xl;
    if (which == 0)      { x = Q; xh = g_xh_q; xl = g_xl_q; }
    else if (which == 1) { x = K; xh = g_xh_k; xl = g_xl_k; }
    else                 { x = V; xh = g_xh_v; xl = g_xl_v; }
    const float4* xr = (const float4*)(x + (size_t)r * Dm);

    float4 v[8];
    float s = 0.f, s2 = 0.f;
    #pragma unroll
    for (int i = 0; i < 8; i++) {
        v[i] = xr[lane + i * 32];
        s  += v[i].x + v[i].y + v[i].z + v[i].w;
        s2 += v[i].x * v[i].x + v[i].y * v[i].y + v[i].z * v[i].z + v[i].w * v[i].w;
    }
    #pragma unroll
    for (int o = 16; o > 0; o >>= 1) {
        s  += __shfl_xor_sync(0xffffffffu, s,  o);
        s2 += __shfl_xor_sync(0xffffffffu, s2, o);
    }
    float muv = s / (float)Dm;
    float var = s2 / (float)Dm - muv * muv;
    if (lane == 0) {
        g_mu[row] = muv;
        g_rs[row] = rsqrtf(var + 1e-6f);
    }
    uint2* xhp = (uint2*)(xh + (size_t)r * Dm);
    uint2* xlp = (uint2*)(xl + (size_t)r * Dm);
    #pragma unroll
    for (int i = 0; i < 8; i++) {
        __half h0 = __float2half_rn(v[i].x), h1 = __float2half_rn(v[i].y);
        __half h2 = __float2half_rn(v[i].z), h3 = __float2half_rn(v[i].w);
        uint2 hv, lv;
        __half2 p01, p23;
        p01.x = h0; p01.y = h1; p23.x = h2; p23.y = h3;
        hv.x = *(uint32_t*)&p01; hv.y = *(uint32_t*)&p23;
        lv.x = packh2(v[i].x - __half2float(h0), v[i].y - __half2float(h1));
        lv.y = packh2(v[i].z - __half2float(h2), v[i].w - __half2float(h3));
        xhp[lane + i * 32] = hv;
        xlp[lane + i * 32] = lv;
    }
}

// ============================================================
// 2) weight prep + fused column constants (c1/c2 pre-zeroed)
// ============================================================
__global__ void wprep_kernel(const float* __restrict__ Wq, const float* __restrict__ Wk,
                             const float* __restrict__ Wv, const float* __restrict__ Wo,
                             const float* __restrict__ gamma, const float* __restrict__ beta,
                             const float* __restrict__ bq, const float* __restrict__ bk,
                             const float* __restrict__ bv) {
    int w = blockIdx.z;
    const float* W = (w == 0) ? Wq : (w == 1) ? Wk : (w == 2) ? Wv : Wo;
    const float* b = (w == 0) ? bq : (w == 1) ? bk : bv;
    __shared__ float ts[64][65];
    int n0 = blockIdx.x * 64, k0 = blockIdx.y * 64;
    int tx = threadIdx.x & 63, ty = threadIdx.x >> 6;

    float s1 = 0.f, s2 = 0.f;
    #pragma unroll
    for (int l = 0; l < 16; l++) {
        int k = ty + l * 4;
        float wv = W[(size_t)(k0 + k) * Dm + n0 + tx];
        float g = (w < 3) ? gamma[k0 + k] : 1.f;
        float gw = g * wv;
        ts[k][tx] = gw;
        if (w < 3) { s1 += gw; s2 += beta[k0 + k] * wv; }
    }
    if (w < 3) {
        if (k0 == 0 && ty == 0) s2 += b[n0 + tx];
        atomicAdd(&g_c1[w * Dm + n0 + tx], s1);
        atomicAdd(&g_c2[w * Dm + n0 + tx], s2);
    }
    __syncthreads();
    __half* whp = g_wh + (size_t)w * Dm * Dm;
    __half* wlp = g_wl + (size_t)w * Dm * Dm;
    #pragma unroll
    for (int l = 0; l < 16; l++) {
        int n = ty + l * 4;
        float val = ts[tx][n];
        __half h = __float2half_rn(val);
        size_t o = (size_t)(n0 + n) * Dm + k0 + tx;
        whp[o] = h;
        wlp[o] = __float2half_rn(val - __half2float(h));
    }
}

// ============================================================
// 3) fp16 mma GEMM. NPROD=3: AhBh+AlBh+AhBl (Q,K). NPROD=2:
//    AhBh+AlBh, Bl never loaded (V,O). Tile 128x128x32, 8 warps,
//    conflict-free swizzle, 3-stage cp.async, 2 CTAs/SM.
//    MODE 0: Q epi (LN, *LOG2E, fp16 split [bh][s][d])
//    MODE 3: K epi (LN, fp16 split [bh][s][d])
//    MODE 2: V epi (LN, single fp16 transposed [bh][d][s])
//    MODE 1: O epi (fp32 +bias +residual row-major)
// ============================================================
#define BM 128
#define BN 128
#define BK 32
#define KBYTES 64
#define STG   32768
#define NSTG  3
#define NT    32

#define SW(r, kc) ((uint32_t)((r) * KBYTES + ((((kc) ^ (((r) >> 1) & 3))) << 4)))

template<int MODE, int NPROD>
__global__ void __launch_bounds__(256, 2) gemm_mma_kernel(
    const __half* __restrict__ Ah, const __half* __restrict__ Al,
    const __half* __restrict__ Bh, const __half* __restrict__ Bl,
    const float* __restrict__ c1, const float* __restrict__ c2,
    const float* __restrict__ rs, const float* __restrict__ mu,
    const float* __restrict__ resid,
    float* __restrict__ outF,
    __half* __restrict__ outH, __half* __restrict__ outL)
{
    extern __shared__ char smem[];
    uint32_t sbase = smem_u32(smem);
    int tid = threadIdx.x, lane = tid & 31, wid = tid >> 5;
    int warpM = wid & 1, warpN = wid >> 1;
    int m0 = blockIdx.y * BM, n0 = blockIdx.x * BN;

    float acc[4][4][4] = {};

    auto prefetch = [&](int t) {
        int s = t % NSTG;
        int kb = t * BK;
        uint32_t st = sbase + s * STG;
        #pragma unroll
        for (int l = 0; l < (NPROD == 3 ? 8 : 6); l++) {
            int e = tid + l * 256;
            int tile = e >> 9;              // 0:Ah 1:Al 2:Bh 3:Bl
            int idx = e & 511;
            int r = idx >> 2, kc = idx & 3;
            const __half* p = (tile == 0) ? Ah : (tile == 1) ? Al
                            : (tile == 2) ? Bh : Bl;
            int rb = (tile < 2) ? m0 : n0;
            cp16(st + tile * 8192 + SW(r, kc), p + (size_t)(rb + r) * Dm + kb + kc * 8);
        }
    };

    prefetch(0); asm volatile("cp.async.commit_group;\n" ::: "memory");
    prefetch(1); asm volatile("cp.async.commit_group;\n" ::: "memory");

    for (int t = 0; t < NT; t++) {
        asm volatile("cp.async.wait_group 1;\n" ::: "memory");
        __syncthreads();
        if (t + 2 < NT) prefetch(t + 2);
        asm volatile("cp.async.commit_group;\n" ::: "memory");

        uint32_t st = sbase + (t % NSTG) * STG;
        uint32_t sAh = st, sAl = st + 8192, sBh = st + 16384, sBl = st + 24576;
        #pragma unroll
        for (int ks = 0; ks < 2; ks++) {
            uint32_t ah[4][4], al[4][4];
            #pragma unroll
            for (int mf = 0; mf < 4; mf++) {
                int row = warpM * 64 + mf * 16 + (lane & 15);
                int ch = ks * 2 + (lane >> 4);
                uint32_t sw = SW(row, ch);
                ldmA(sAh + sw, ah[mf][0], ah[mf][1], ah[mf][2], ah[mf][3]);
                ldmA(sAl + sw, al[mf][0], al[mf][1], al[mf][2], al[mf][3]);
            }
            #pragma unroll
            for (int nf2 = 0; nf2 < 2; nf2++) {
                int nrow = warpN * 32 + nf2 * 16 + (lane & 7) + ((lane >> 4) << 3);
                int ch = ks * 2 + ((lane >> 3) & 1);
                uint32_t swb = SW(nrow, ch);
                uint32_t r0, r1, r2, r3;
                ldmA(sBh + swb, r0, r1, r2, r3);
                #pragma unroll
                for (int mf = 0; mf < 4; mf++) {
                    mma16816(acc[mf][2*nf2],   ah[mf], r0, r1);
                    mma16816(acc[mf][2*nf2+1], ah[mf], r2, r3);
                    mma16816(acc[mf][2*nf2],   al[mf], r0, r1);
                    mma16816(acc[mf][2*nf2+1], al[mf], r2, r3);
                }
                if (NPROD == 3) {
                    ldmA(sBl + swb, r0, r1, r2, r3);
                    #pragma unroll
                    for (int mf = 0; mf < 4; mf++) {
                        mma16816(acc[mf][2*nf2],   ah[mf], r0, r1);
                        mma16816(acc[mf][2*nf2+1], ah[mf], r2, r3);
                    }
                }
            }
        }
    }

    int groupID = lane >> 2, tg = lane & 3;
    #pragma unroll
    for (int mf = 0; mf < 4; mf++) {
        #pragma unroll
        for (int half = 0; half < 2; half++) {
            int r = m0 + warpM * 64 + mf * 16 + groupID + half * 8;
            float rsv = 1.f, muv = 0.f;
            if (MODE != 1) { rsv = rs[r]; muv = mu[r]; }
            int b = r >> 11, srow = r & 2047;
            #pragma unroll
            for (int nf = 0; nf < 4; nf++) {
                int c = n0 + warpN * 32 + nf * 8 + 2 * tg;
                float x0 = acc[mf][nf][2 * half + 0];
                float x1 = acc[mf][nf][2 * half + 1];
                if (MODE == 1) {
                    float2 bo2 = *(const float2*)(c2 + c);
                    float2 q2  = *(const float2*)(resid + (size_t)r * Dm + c);
                    float2 o;
                    o.x = x0 + bo2.x + q2.x;
                    o.y = x1 + bo2.y + q2.y;
                    *(float2*)(outF + (size_t)r * Dm + c) = o;
                } else {
                    float2 c1v = *(const float2*)(c1 + c);
                    float2 c2v = *(const float2*)(c2 + c);
                    float o0 = rsv * (x0 - muv * c1v.x) + c2v.x;
                    float o1 = rsv * (x1 - muv * c1v.y) + c2v.y;
                    if (MODE == 0) { o0 *= LOG2E; o1 *= LOG2E; }
                    __half h0 = __float2half_rn(o0);
                    __half h1 = __float2half_rn(o1);
                    int hd = c >> 6, dd = c & 63;
                    int bh = b * Hh + hd;
                    if (MODE == 2) {
                        size_t a0 = ((size_t)(bh * DHd + dd)) * Ss + srow;
                        size_t a1 = ((size_t)(bh * DHd + dd + 1)) * Ss + srow;
                        outH[a0] = h0; outH[a1] = h1;   // single fp16 V
                    } else {
                        float l0 = o0 - __half2float(h0);
                        float l1 = o1 - __half2float(h1);
                        size_t ad = ((size_t)(bh * Ss + srow)) * DHd + dd;
                        __half2 hp; hp.x = h0; hp.y = h1;
                        *(uint32_t*)(outH + ad) = *(uint32_t*)&hp;
                        *(uint32_t*)(outL + ad) = packh2(l0, l1);
                    }
                }
            }
        }
    }
}

// ============================================================
// 4) tensor-core causal attention, fp16.
//    S: 3 products (qh*Kh + ql*Kh + qh*Kl).
//    PV: 2 products ((ph+pl)*Vh), V single fp16 — no Vl tile.
// ============================================================
__device__ __forceinline__ void loadKV(int bh, int t, uint32_t base, int tid) {
    int kt = t * 64;
    const __half* khp = g_kh + ((size_t)bh * Ss + kt) * DHd;
    const __half* klp = g_kl + ((size_t)bh * Ss + kt) * DHd;
    const __half* vhp = g_vh + (size_t)bh * DHd * Ss + kt;
    #pragma unroll
    for (int l = 0; l < 2; l++) {
        int e = tid + l * 256;
        int row = e >> 3, c = e & 7;
        uint32_t d = row * 128 + ((c ^ (row & 7)) << 4);
        cp16(base + d,         khp + (size_t)row * DHd + c * 8);
        cp16(base + 8192 + d,  klp + (size_t)row * DHd + c * 8);
        cp16(base + 16384 + d, vhp + (size_t)row * Ss + c * 8);
    }
}

#define KVB 24576   // kh + kl + vh per buffer

__global__ void __launch_bounds__(256, 2) attn_mma_kernel() {
    extern __shared__ char smraw[];
    uint32_t sb = smem_u32(smraw);
    const uint32_t QHs = sb;
    const uint32_t KVs = sb + 32768;
    int tid = threadIdx.x, lane = tid & 31, wid = tid >> 5;
    int groupID = lane >> 2, tg = lane & 3;
    int bh = blockIdx.y;
    int mt = (int)(gridDim.x - 1) - (int)blockIdx.x;
    int q0 = mt * 128;
    int numt = 2 * mt + 2;

    const __half* qhp = g_qh + ((size_t)bh * Ss + q0) * DHd;
    const __half* qlp = g_ql + ((size_t)bh * Ss + q0) * DHd;

    #pragma unroll
    for (int l = 0; l < 4; l++) {
        int e = tid + l * 256;
        int row = e >> 3, c = e & 7;
        uint32_t d = row * 128 + ((c ^ (row & 7)) << 4);
        cp16(QHs + d,         qhp + (size_t)row * DHd + c * 8);
        cp16(QHs + 16384 + d, qlp + (size_t)row * DHd + c * 8);
    }
    asm volatile("cp.async.commit_group;\n" ::: "memory");
    loadKV(bh, 0, KVs, tid);
    asm volatile("cp.async.commit_group;\n" ::: "memory");
    asm volatile("cp.async.wait_group 1;\n" ::: "memory");
    __syncthreads();

    uint32_t qh[4][4];
    #pragma unroll
    for (int kf = 0; kf < 4; kf++) {
        int row = wid * 16 + (lane & 15);
        int ch = 2 * kf + (lane >> 4);
        uint32_t ad = QHs + row * 128 + ((ch ^ (row & 7)) << 4);
        ldmA(ad, qh[kf][0], qh[kf][1], qh[kf][2], qh[kf][3]);
    }

    float m[2] = {-1e30f, -1e30f}, lsum[2] = {0.f, 0.f};
    float oacc[8][4] = {};

    for (int t = 0; t < numt; t++) {
        if (t + 1 < numt) loadKV(bh, t + 1, KVs + ((t + 1) & 1) * KVB, tid);
        asm volatile("cp.async.commit_group;\n" ::: "memory");
        asm volatile("cp.async.wait_group 1;\n" ::: "memory");
        __syncthreads();
        uint32_t KB = KVs + (t & 1) * KVB;

        // ---- S = Q K^T (qh*Kh + ql*Kh + qh*Kl) ----
        float sacc[8][4] = {};
        #pragma unroll
        for (int kf = 0; kf < 4; kf++) {
            uint32_t qlf[4];
            {
                int row = wid * 16 + (lane & 15);
                int ch = 2 * kf + (lane >> 4);
                uint32_t ad = QHs + 16384 + row * 128 + ((ch ^ (row & 7)) << 4);
                ldmA(ad, qlf[0], qlf[1], qlf[2], qlf[3]);
            }
            #pragma unroll
            for (int nf2 = 0; nf2 < 4; nf2++) {
                int row = nf2 * 16 + (lane & 15);
                int ch = 2 * kf + (lane >> 4);
                uint32_t sw = row * 128 + ((ch ^ (row & 7)) << 4);
                uint32_t r0, r1, r2, r3;
                ldmA(KB + sw, r0, r1, r2, r3);               // Kh
                mma16816(sacc[2 * nf2],     qh[kf], r0, r2);
                mma16816(sacc[2 * nf2 + 1], qh[kf], r1, r3);
                mma16816(sacc[2 * nf2],     qlf,    r0, r2);
                mma16816(sacc[2 * nf2 + 1], qlf,    r1, r3);
                ldmA(KB + 8192 + sw, r0, r1, r2, r3);        // Kl
                mma16816(sacc[2 * nf2],     qh[kf], r0, r2);
                mma16816(sacc[2 * nf2 + 1], qh[kf], r1, r3);
            }
        }

        if (t >= numt - 2) {
            int kt = t * 64;
            int qrow = q0 + wid * 16 + groupID;
            #pragma unroll
            for (int nf = 0; nf < 8; nf++) {
                int k0 = kt + nf * 8 + 2 * tg;
                if (k0     > qrow)     sacc[nf][0] = -1e30f;
                if (k0 + 1 > qrow)     sacc[nf][1] = -1e30f;
                if (k0     > qrow + 8) sacc[nf][2] = -1e30f;
                if (k0 + 1 > qrow + 8) sacc[nf][3] = -1e30f;
            }
        }

        float alpha[2];
        #pragma unroll
        for (int h = 0; h < 2; h++) {
            float rm = -1e30f;
            #pragma unroll
            for (int nf = 0; nf < 8; nf++)
                rm = fmaxf(rm, fmaxf(sacc[nf][2 * h], sacc[nf][2 * h + 1]));
            rm = fmaxf(rm, __shfl_xor_sync(0xffffffffu, rm, 1));
            rm = fmaxf(rm, __shfl_xor_sync(0xffffffffu, rm, 2));
            float mn = fmaxf(m[h], rm);
            alpha[h] = ex2f(m[h] - mn);
            m[h] = mn;
            float ls = 0.f;
            #pragma unroll
            for (int nf = 0; nf < 8; nf++) {
                float p0 = exp2poly(sacc[nf][2 * h]     - mn);
                float p1 = exp2poly(sacc[nf][2 * h + 1] - mn);
                sacc[nf][2 * h] = p0; sacc[nf][2 * h + 1] = p1;
                ls += p0 + p1;
            }
            lsum[h] = lsum[h] * alpha[h] + ls;
        }
        #pragma unroll
        for (int nd = 0; nd < 8; nd++) {
            oacc[nd][0] *= alpha[0]; oacc[nd][1] *= alpha[0];
            oacc[nd][2] *= alpha[1]; oacc[nd][3] *= alpha[1];
        }

        uint32_t pah[4][4], pal[4][4];
        #pragma unroll
        for (int kf = 0; kf < 4; kf++) {
            #pragma unroll
            for (int q = 0; q < 4; q++) {
                int nf = 2 * kf + (q >> 1);
                float x0 = sacc[nf][(q & 1) * 2], x1 = sacc[nf][(q & 1) * 2 + 1];
                __half h0 = __float2half_rn(x0), h1 = __float2half_rn(x1);
                __half2 hp; hp.x = h0; hp.y = h1;
                pah[kf][q] = *(uint32_t*)&hp;
                pal[kf][q] = packh2(x0 - __half2float(h0), x1 - __half2float(h1));
            }
        }

        // ---- O += P V (2 products: (ph+pl)*Vh) ----
        #pragma unroll
        for (int kf = 0; kf < 4; kf++) {
            #pragma unroll
            for (int nd2 = 0; nd2 < 4; nd2++) {
                int row = nd2 * 16 + (lane & 15);
                int ch = 2 * kf + (lane >> 4);
                uint32_t sw = row * 128 + ((ch ^ (row & 7)) << 4);
                uint32_t r0, r1, r2, r3;
                ldmA(KB + 16384 + sw, r0, r1, r2, r3);        // Vh
                mma16816(oacc[2 * nd2],     pah[kf], r0, r2);
                mma16816(oacc[2 * nd2 + 1], pah[kf], r1, r3);
                mma16816(oacc[2 * nd2],     pal[kf], r0, r2);
                mma16816(oacc[2 * nd2 + 1], pal[kf], r1, r3);
            }
        }
        __syncthreads();
    }

    #pragma unroll
    for (int h = 0; h < 2; h++) {
        lsum[h] += __shfl_xor_sync(0xffffffffu, lsum[h], 1);
        lsum[h] += __shfl_xor_sync(0xffffffffu, lsum[h], 2);
    }
    int b = bh >> 4, hd = bh & 15;
    #pragma unroll
    for (int h = 0; h < 2; h++) {
        int q = q0 + wid * 16 + groupID + 8 * h;
        float inv = 1.f / lsum[h];
        size_t rowbase = ((size_t)(b * Ss + q)) * Dm + hd * 64;
        #pragma unroll
        for (int nd = 0; nd < 8; nd++) {
            float x0 = oacc[nd][2 * h] * inv, x1 = oacc[nd][2 * h + 1] * inv;
            __half h0 = __float2half_rn(x0), h1 = __float2half_rn(x1);
            __half2 hp; hp.x = h0; hp.y = h1;
            size_t ad = rowbase + nd * 8 + 2 * tg;
            *(uint32_t*)(g_aoh + ad) = *(uint32_t*)&hp;
            *(uint32_t*)(g_aol + ad) = packh2(x0 - __half2float(h0),
                                              x1 - __half2float(h1));
        }
    }
}

// ============================================================
// launch
// ============================================================
extern "C" void kernel_launch(void* const* d_in, const int* in_sizes, int n_in,
                              void* d_out, int out_size) {
    const float* Q     = (const float*)d_in[0];
    const float* K     = (const float*)d_in[1];
    const float* V     = (const float*)d_in[2];
    const float* Wq    = (const float*)d_in[3];
    const float* bq    = (const float*)d_in[4];
    const float* Wk    = (const float*)d_in[5];
    const float* bk    = (const float*)d_in[6];
    const float* Wv    = (const float*)d_in[7];
    const float* bv    = (const float*)d_in[8];
    const float* Wo    = (const float*)d_in[9];
    const float* bo    = (const float*)d_in[10];
    const float* gamma = (const float*)d_in[11];
    const float* beta  = (const float*)d_in[12];
    float* out = (float*)d_out;

    float *mu_p, *rs_p, *c1_p, *c2_p;
    __half *xhq, *xlq, *xhk, *xlk, *xhv, *xlv, *wh_p, *wl_p;
    __half *qh_p, *ql_p, *kh_p, *kl_p, *vh_p, *aoh_p, *aol_p;
    cudaGetSymbolAddress((void**)&mu_p, g_mu);
    cudaGetSymbolAddress((void**)&rs_p, g_rs);
    cudaGetSymbolAddress((void**)&c1_p, g_c1);
    cudaGetSymbolAddress((void**)&c2_p, g_c2);
    cudaGetSymbolAddress((void**)&xhq, g_xh_q);
    cudaGetSymbolAddress((void**)&xlq, g_xl_q);
    cudaGetSymbolAddress((void**)&xhk, g_xh_k);
    cudaGetSymbolAddress((void**)&xlk, g_xl_k);
    cudaGetSymbolAddress((void**)&xhv, g_xh_v);
    cudaGetSymbolAddress((void**)&xlv, g_xl_v);
    cudaGetSymbolAddress((void**)&wh_p, g_wh);
    cudaGetSymbolAddress((void**)&wl_p, g_wl);
    cudaGetSymbolAddress((void**)&qh_p, g_qh);
    cudaGetSymbolAddress((void**)&ql_p, g_ql);
    cudaGetSymbolAddress((void**)&kh_p, g_kh);
    cudaGetSymbolAddress((void**)&kl_p, g_kl);
    cudaGetSymbolAddress((void**)&vh_p, g_vh);
    cudaGetSymbolAddress((void**)&aoh_p, g_aoh);
    cudaGetSymbolAddress((void**)&aol_p, g_aol);

    cudaMemsetAsync(c1_p, 0, 3 * Dm * sizeof(float));
    cudaMemsetAsync(c2_p, 0, 3 * Dm * sizeof(float));
    ln_split_kernel<<<3 * NROWS / 8, 256>>>(Q, K, V);
    wprep_kernel<<<dim3(16, 16, 4), 256>>>(Wq, Wk, Wv, Wo, gamma, beta, bq, bk, bv);

    size_t gsmem = NSTG * STG;   // 96K
    cudaFuncSetAttribute((const void*)gemm_mma_kernel<0,3>, cudaFuncAttributeMaxDynamicSharedMemorySize, (int)gsmem);
    cudaFuncSetAttribute((const void*)gemm_mma_kernel<3,3>, cudaFuncAttributeMaxDynamicSharedMemorySize, (int)gsmem);
    cudaFuncSetAttribute((const void*)gemm_mma_kernel<2,2>, cudaFuncAttributeMaxDynamicSharedMemorySize, (int)gsmem);
    cudaFuncSetAttribute((const void*)gemm_mma_kernel<1,2>, cudaFuncAttributeMaxDynamicSharedMemorySize, (int)gsmem);
    dim3 gg(Dm / BN, NROWS / BM);
    size_t WSZ = (size_t)Dm * Dm;

    gemm_mma_kernel<0,3><<<gg, 256, gsmem>>>(xhq, xlq, wh_p, wl_p,
                                             c1_p, c2_p, rs_p, mu_p, nullptr,
                                             nullptr, qh_p, ql_p);
    gemm_mma_kernel<3,3><<<gg, 256, gsmem>>>(xhk, xlk, wh_p + WSZ, wl_p + WSZ,
                                             c1_p + Dm, c2_p + Dm, rs_p + NROWS, mu_p + NROWS,
                                             nullptr, nullptr, kh_p, kl_p);
    gemm_mma_kernel<2,2><<<gg, 256, gsmem>>>(xhv, xlv, wh_p + 2 * WSZ, nullptr,
                                             c1_p + 2 * Dm, c2_p + 2 * Dm,
                                             rs_p + 2 * NROWS, mu_p + 2 * NROWS,
                                             nullptr, nullptr, vh_p, nullptr);

    size_t asmem = 32768 + 2 * KVB;   // 81920
    cudaFuncSetAttribute(attn_mma_kernel, cudaFuncAttributeMaxDynamicSharedMemorySize, (int)asmem);
    attn_mma_kernel<<<dim3(16, 64), 256, asmem>>>();

    gemm_mma_kernel<1,2><<<gg, 256, gsmem>>>(aoh_p, aol_p, wh_p + 3 * WSZ, nullptr,
                                             nullptr, bo, nullptr, nullptr, Q,
                                             out, nullptr, nullptr);
}

// round 12
// speedup vs baseline: 1.2731x; 1.1008x over previous
#include <cuda_runtime.h>
#include <cuda_fp16.h>
#include <cstdint>
#include <math.h>

#define Dm 1024
#define Hh 16
#define DHd 64
#define Bb 4
#define Ss 2048
#define NROWS (Bb*Ss)   // 8192
#define LOG2E 1.4426950408889634f

// ---------------- static device scratch ----------------
__device__ float g_mu[3*NROWS];
__device__ float g_rs[3*NROWS];
__device__ __half g_xh_q[NROWS*Dm]; __device__ __half g_xl_q[NROWS*Dm];
__device__ __half g_xh_k[NROWS*Dm]; __device__ __half g_xl_k[NROWS*Dm];
__device__ __half g_xh_v[NROWS*Dm]; __device__ __half g_xl_v[NROWS*Dm];
__device__ __half g_wh[4*Dm*Dm];
__device__ float g_c1[3*Dm];
__device__ float g_c2[3*Dm];
__device__ __half g_qh[NROWS*Dm], g_ql[NROWS*Dm];  // [bh][s][d], *LOG2E
__device__ __half g_kh[NROWS*Dm], g_kl[NROWS*Dm];  // [bh][s][d]
__device__ __half g_vh[NROWS*Dm];                  // [bh][d][s], single fp16
__device__ __half g_aoh[NROWS*Dm], g_aol[NROWS*Dm]; // [b*s][D]

// ---------------- helpers ----------------
__device__ __forceinline__ uint32_t smem_u32(const void* p) {
    uint32_t a;
    asm("{ .reg .u64 t; cvta.to.shared.u64 t, %1; cvt.u32.u64 %0, t; }" : "=r"(a) : "l"(p));
    return a;
}
__device__ __forceinline__ void cp16(uint32_t s, const void* g) {
    asm volatile("cp.async.cg.shared.global [%0], [%1], 16;\n" :: "r"(s), "l"(g));
}
__device__ __forceinline__ void ldmA(uint32_t addr, uint32_t& r0, uint32_t& r1,
                                     uint32_t& r2, uint32_t& r3) {
    asm volatile("ldmatrix.sync.aligned.m8n8.x4.shared.b16 {%0,%1,%2,%3}, [%4];"
                 : "=r"(r0), "=r"(r1), "=r"(r2), "=r"(r3) : "r"(addr));
}
__device__ __forceinline__ void mma16816(float* c, const uint32_t* a,
                                         uint32_t b0, uint32_t b1) {
    asm volatile("mma.sync.aligned.m16n8k16.row.col.f32.f16.f16.f32 "
                 "{%0,%1,%2,%3}, {%4,%5,%6,%7}, {%8,%9}, {%0,%1,%2,%3};"
                 : "+f"(c[0]), "+f"(c[1]), "+f"(c[2]), "+f"(c[3])
                 : "r"(a[0]), "r"(a[1]), "r"(a[2]), "r"(a[3]), "r"(b0), "r"(b1));
}
__device__ __forceinline__ float ex2f(float x) {
    float r; asm("ex2.approx.f32 %0, %1;" : "=f"(r) : "f"(x)); return r;
}
__device__ __forceinline__ float exp2poly(float z) {
    z = fmaxf(z, -126.f);
    float t = z + 12582912.f;
    int n = __float_as_int(t) - 0x4B400000;
    float f = z - (t - 12582912.f);
    float p = fmaf(0.0096181291f, f, 0.055504109f);
    p = fmaf(p, f, 0.24022651f);
    p = fmaf(p, f, 0.69314718f);
    p = fmaf(p, f, 1.0f);
    return __int_as_float(__float_as_int(p) + (n << 23));
}
__device__ __forceinline__ uint32_t packh2(float a, float b) {
    __half2 t;
    t.x = __float2half_rn(a);
    t.y = __float2half_rn(b);
    return *(uint32_t*)&t;
}

// ============================================================
// 1) LN stats + fp16 hi/lo split — warp per row
// ============================================================
__global__ void ln_split_kernel(const float* __restrict__ Q,
                                const float* __restrict__ K,
                                const float* __restrict__ V) {
    int wid = threadIdx.x >> 5, lane = threadIdx.x & 31;
    int row = blockIdx.x * 8 + wid;
    int which = row >> 13;
    int r = row & (NROWS - 1);
    const float* x; __half* xh; __half* xl;
    if (which == 0)      { x = Q; xh = g_xh_q; xl = g_xl_q; }
    else if (which == 1) { x = K; xh = g_xh_k; xl = g_xl_k; }
    else                 { x = V; xh = g_xh_v; xl = g_xl_v; }
    const float4* xr = (const float4*)(x + (size_t)r * Dm);

    float4 v[8];
    float s = 0.f, s2 = 0.f;
    #pragma unroll
    for (int i = 0; i < 8; i++) {
        v[i] = xr[lane + i * 32];
        s  += v[i].x + v[i].y + v[i].z + v[i].w;
        s2 += v[i].x * v[i].x + v[i].y * v[i].y + v[i].z * v[i].z + v[i].w * v[i].w;
    }
    #pragma unroll
    for (int o = 16; o > 0; o >>= 1) {
        s  += __shfl_xor_sync(0xffffffffu, s,  o);
        s2 += __shfl_xor_sync(0xffffffffu, s2, o);
    }
    float muv = s / (float)Dm;
    float var = s2 / (float)Dm - muv * muv;
    if (lane == 0) {
        g_mu[row] = muv;
        g_rs[row] = rsqrtf(var + 1e-6f);
    }
    uint2* xhp = (uint2*)(xh + (size_t)r * Dm);
    uint2* xlp = (uint2*)(xl + (size_t)r * Dm);
    #pragma unroll
    for (int i = 0; i < 8; i++) {
        __half h0 = __float2half_rn(v[i].x), h1 = __float2half_rn(v[i].y);
        __half h2 = __float2half_rn(v[i].z), h3 = __float2half_rn(v[i].w);
        uint2 hv, lv;
        __half2 p01, p23;
        p01.x = h0; p01.y = h1; p23.x = h2; p23.y = h3;
        hv.x = *(uint32_t*)&p01; hv.y = *(uint32_t*)&p23;
        lv.x = packh2(v[i].x - __half2float(h0), v[i].y - __half2float(h1));
        lv.y = packh2(v[i].z - __half2float(h2), v[i].w - __half2float(h3));
        xhp[lane + i * 32] = hv;
        xlp[lane + i * 32] = lv;
    }
}

// ============================================================
// 2) weight prep (fp16 single, no low part needed anymore)
//    + fused column constants (c1/c2 pre-zeroed)
// ============================================================
__global__ void wprep_kernel(const float* __restrict__ Wq, const float* __restrict__ Wk,
                             const float* __restrict__ Wv, const float* __restrict__ Wo,
                             const float* __restrict__ gamma, const float* __restrict__ beta,
                             const float* __restrict__ bq, const float* __restrict__ bk,
                             const float* __restrict__ bv) {
    int w = blockIdx.z;
    const float* W = (w == 0) ? Wq : (w == 1) ? Wk : (w == 2) ? Wv : Wo;
    const float* b = (w == 0) ? bq : (w == 1) ? bk : bv;
    __shared__ float ts[64][65];
    int n0 = blockIdx.x * 64, k0 = blockIdx.y * 64;
    int tx = threadIdx.x & 63, ty = threadIdx.x >> 6;

    float s1 = 0.f, s2 = 0.f;
    #pragma unroll
    for (int l = 0; l < 16; l++) {
        int k = ty + l * 4;
        float wv = W[(size_t)(k0 + k) * Dm + n0 + tx];
        float g = (w < 3) ? gamma[k0 + k] : 1.f;
        float gw = g * wv;
        ts[k][tx] = gw;
        if (w < 3) { s1 += gw; s2 += beta[k0 + k] * wv; }
    }
    if (w < 3) {
        if (k0 == 0 && ty == 0) s2 += b[n0 + tx];
        atomicAdd(&g_c1[w * Dm + n0 + tx], s1);
        atomicAdd(&g_c2[w * Dm + n0 + tx], s2);
    }
    __syncthreads();
    __half* whp = g_wh + (size_t)w * Dm * Dm;
    #pragma unroll
    for (int l = 0; l < 16; l++) {
        int n = ty + l * 4;
        size_t o = (size_t)(n0 + n) * Dm + k0 + tx;
        whp[o] = __float2half_rn(ts[tx][n]);
    }
}

// ============================================================
// 3) fp16 mma GEMM — 2-product (AhBh + AlBh), weight single fp16.
//    Tile 128x128x32, 8 warps, conflict-free swizzle, 3-stage
//    cp.async, 2 CTAs/SM.
//    MODE 0: Q epi (LN, *LOG2E, fp16 split [bh][s][d])
//    MODE 3: K epi (LN, fp16 split [bh][s][d])
//    MODE 2: V epi (LN, single fp16 transposed [bh][d][s])
//    MODE 1: O epi (fp32 +bias +residual row-major)
// ============================================================
#define BM 128
#define BN 128
#define BK 32
#define KBYTES 64
#define STG   24576          // Ah + Al + Bh per stage
#define NSTG  3
#define NT    32

#define SW(r, kc) ((uint32_t)((r) * KBYTES + ((((kc) ^ (((r) >> 1) & 3))) << 4)))

template<int MODE>
__global__ void __launch_bounds__(256, 2) gemm_mma_kernel(
    const __half* __restrict__ Ah, const __half* __restrict__ Al,
    const __half* __restrict__ Bh,
    const float* __restrict__ c1, const float* __restrict__ c2,
    const float* __restrict__ rs, const float* __restrict__ mu,
    const float* __restrict__ resid,
    float* __restrict__ outF,
    __half* __restrict__ outH, __half* __restrict__ outL)
{
    extern __shared__ char smem[];
    uint32_t sbase = smem_u32(smem);
    int tid = threadIdx.x, lane = tid & 31, wid = tid >> 5;
    int warpM = wid & 1, warpN = wid >> 1;
    int m0 = blockIdx.y * BM, n0 = blockIdx.x * BN;

    float acc[4][4][4] = {};

    auto prefetch = [&](int t) {
        int s = t % NSTG;
        int kb = t * BK;
        uint32_t st = sbase + s * STG;
        #pragma unroll
        for (int l = 0; l < 6; l++) {
            int e = tid + l * 256;
            int tile = e >> 9;              // 0:Ah 1:Al 2:Bh
            int idx = e & 511;
            int r = idx >> 2, kc = idx & 3;
            const __half* p = (tile == 0) ? Ah : (tile == 1) ? Al : Bh;
            int rb = (tile < 2) ? m0 : n0;
            cp16(st + tile * 8192 + SW(r, kc), p + (size_t)(rb + r) * Dm + kb + kc * 8);
        }
    };

    prefetch(0); asm volatile("cp.async.commit_group;\n" ::: "memory");
    prefetch(1); asm volatile("cp.async.commit_group;\n" ::: "memory");

    for (int t = 0; t < NT; t++) {
        asm volatile("cp.async.wait_group 1;\n" ::: "memory");
        __syncthreads();
        if (t + 2 < NT) prefetch(t + 2);
        asm volatile("cp.async.commit_group;\n" ::: "memory");

        uint32_t st = sbase + (t % NSTG) * STG;
        uint32_t sAh = st, sAl = st + 8192, sBh = st + 16384;
        #pragma unroll
        for (int ks = 0; ks < 2; ks++) {
            uint32_t ah[4][4], al[4][4];
            #pragma unroll
            for (int mf = 0; mf < 4; mf++) {
                int row = warpM * 64 + mf * 16 + (lane & 15);
                int ch = ks * 2 + (lane >> 4);
                uint32_t sw = SW(row, ch);
                ldmA(sAh + sw, ah[mf][0], ah[mf][1], ah[mf][2], ah[mf][3]);
                ldmA(sAl + sw, al[mf][0], al[mf][1], al[mf][2], al[mf][3]);
            }
            #pragma unroll
            for (int nf2 = 0; nf2 < 2; nf2++) {
                int nrow = warpN * 32 + nf2 * 16 + (lane & 7) + ((lane >> 4) << 3);
                int ch = ks * 2 + ((lane >> 3) & 1);
                uint32_t swb = SW(nrow, ch);
                uint32_t r0, r1, r2, r3;
                ldmA(sBh + swb, r0, r1, r2, r3);
                #pragma unroll
                for (int mf = 0; mf < 4; mf++) {
                    mma16816(acc[mf][2*nf2],   ah[mf], r0, r1);
                    mma16816(acc[mf][2*nf2+1], ah[mf], r2, r3);
                    mma16816(acc[mf][2*nf2],   al[mf], r0, r1);
                    mma16816(acc[mf][2*nf2+1], al[mf], r2, r3);
                }
            }
        }
    }

    int groupID = lane >> 2, tg = lane & 3;
    #pragma unroll
    for (int mf = 0; mf < 4; mf++) {
        #pragma unroll
        for (int half = 0; half < 2; half++) {
            int r = m0 + warpM * 64 + mf * 16 + groupID + half * 8;
            float rsv = 1.f, muv = 0.f;
            if (MODE != 1) { rsv = rs[r]; muv = mu[r]; }
            int b = r >> 11, srow = r & 2047;
            #pragma unroll
            for (int nf = 0; nf < 4; nf++) {
                int c = n0 + warpN * 32 + nf * 8 + 2 * tg;
                float x0 = acc[mf][nf][2 * half + 0];
                float x1 = acc[mf][nf][2 * half + 1];
                if (MODE == 1) {
                    float2 bo2 = *(const float2*)(c2 + c);
                    float2 q2  = *(const float2*)(resid + (size_t)r * Dm + c);
                    float2 o;
                    o.x = x0 + bo2.x + q2.x;
                    o.y = x1 + bo2.y + q2.y;
                    *(float2*)(outF + (size_t)r * Dm + c) = o;
                } else {
                    float2 c1v = *(const float2*)(c1 + c);
                    float2 c2v = *(const float2*)(c2 + c);
                    float o0 = rsv * (x0 - muv * c1v.x) + c2v.x;
                    float o1 = rsv * (x1 - muv * c1v.y) + c2v.y;
                    if (MODE == 0) { o0 *= LOG2E; o1 *= LOG2E; }
                    __half h0 = __float2half_rn(o0);
                    __half h1 = __float2half_rn(o1);
                    int hd = c >> 6, dd = c & 63;
                    int bh = b * Hh + hd;
                    if (MODE == 2) {
                        size_t a0 = ((size_t)(bh * DHd + dd)) * Ss + srow;
                        size_t a1 = ((size_t)(bh * DHd + dd + 1)) * Ss + srow;
                        outH[a0] = h0; outH[a1] = h1;   // single fp16 V
                    } else {
                        float l0 = o0 - __half2float(h0);
                        float l1 = o1 - __half2float(h1);
                        size_t ad = ((size_t)(bh * Ss + srow)) * DHd + dd;
                        __half2 hp; hp.x = h0; hp.y = h1;
                        *(uint32_t*)(outH + ad) = *(uint32_t*)&hp;
                        *(uint32_t*)(outL + ad) = packh2(l0, l1);
                    }
                }
            }
        }
    }
}

// ============================================================
// 4) tensor-core causal attention, fp16 (unchanged from R11).
//    S: 3 products (qh*Kh + ql*Kh + qh*Kl).
//    PV: 2 products ((ph+pl)*Vh), V single fp16.
// ============================================================
__device__ __forceinline__ void loadKV(int bh, int t, uint32_t base, int tid) {
    int kt = t * 64;
    const __half* khp = g_kh + ((size_t)bh * Ss + kt) * DHd;
    const __half* klp = g_kl + ((size_t)bh * Ss + kt) * DHd;
    const __half* vhp = g_vh + (size_t)bh * DHd * Ss + kt;
    #pragma unroll
    for (int l = 0; l < 2; l++) {
        int e = tid + l * 256;
        int row = e >> 3, c = e & 7;
        uint32_t d = row * 128 + ((c ^ (row & 7)) << 4);
        cp16(base + d,         khp + (size_t)row * DHd + c * 8);
        cp16(base + 8192 + d,  klp + (size_t)row * DHd + c * 8);
        cp16(base + 16384 + d, vhp + (size_t)row * Ss + c * 8);
    }
}

#define KVB 24576   // kh + kl + vh per buffer

__global__ void __launch_bounds__(256, 2) attn_mma_kernel() {
    extern __shared__ char smraw[];
    uint32_t sb = smem_u32(smraw);
    const uint32_t QHs = sb;
    const uint32_t KVs = sb + 32768;
    int tid = threadIdx.x, lane = tid & 31, wid = tid >> 5;
    int groupID = lane >> 2, tg = lane & 3;
    int bh = blockIdx.y;
    int mt = (int)(gridDim.x - 1) - (int)blockIdx.x;
    int q0 = mt * 128;
    int numt = 2 * mt + 2;

    const __half* qhp = g_qh + ((size_t)bh * Ss + q0) * DHd;
    const __half* qlp = g_ql + ((size_t)bh * Ss + q0) * DHd;

    #pragma unroll
    for (int l = 0; l < 4; l++) {
        int e = tid + l * 256;
        int row = e >> 3, c = e & 7;
        uint32_t d = row * 128 + ((c ^ (row & 7)) << 4);
        cp16(QHs + d,         qhp + (size_t)row * DHd + c * 8);
        cp16(QHs + 16384 + d, qlp + (size_t)row * DHd + c * 8);
    }
    asm volatile("cp.async.commit_group;\n" ::: "memory");
    loadKV(bh, 0, KVs, tid);
    asm volatile("cp.async.commit_group;\n" ::: "memory");
    asm volatile("cp.async.wait_group 1;\n" ::: "memory");
    __syncthreads();

    uint32_t qh[4][4];
    #pragma unroll
    for (int kf = 0; kf < 4; kf++) {
        int row = wid * 16 + (lane & 15);
        int ch = 2 * kf + (lane >> 4);
        uint32_t ad = QHs + row * 128 + ((ch ^ (row & 7)) << 4);
        ldmA(ad, qh[kf][0], qh[kf][1], qh[kf][2], qh[kf][3]);
    }

    float m[2] = {-1e30f, -1e30f}, lsum[2] = {0.f, 0.f};
    float oacc[8][4] = {};

    for (int t = 0; t < numt; t++) {
        if (t + 1 < numt) loadKV(bh, t + 1, KVs + ((t + 1) & 1) * KVB, tid);
        asm volatile("cp.async.commit_group;\n" ::: "memory");
        asm volatile("cp.async.wait_group 1;\n" ::: "memory");
        __syncthreads();
        uint32_t KB = KVs + (t & 1) * KVB;

        // ---- S = Q K^T (qh*Kh + ql*Kh + qh*Kl) ----
        float sacc[8][4] = {};
        #pragma unroll
        for (int kf = 0; kf < 4; kf++) {
            uint32_t qlf[4];
            {
                int row = wid * 16 + (lane & 15);
                int ch = 2 * kf + (lane >> 4);
                uint32_t ad = QHs + 16384 + row * 128 + ((ch ^ (row & 7)) << 4);
                ldmA(ad, qlf[0], qlf[1], qlf[2], qlf[3]);
            }
            #pragma unroll
            for (int nf2 = 0; nf2 < 4; nf2++) {
                int row = nf2 * 16 + (lane & 15);
                int ch = 2 * kf + (lane >> 4);
                uint32_t sw = row * 128 + ((ch ^ (row & 7)) << 4);
                uint32_t r0, r1, r2, r3;
                ldmA(KB + sw, r0, r1, r2, r3);               // Kh
                mma16816(sacc[2 * nf2],     qh[kf], r0, r2);
                mma16816(sacc[2 * nf2 + 1], qh[kf], r1, r3);
                mma16816(sacc[2 * nf2],     qlf,    r0, r2);
                mma16816(sacc[2 * nf2 + 1], qlf,    r1, r3);
                ldmA(KB + 8192 + sw, r0, r1, r2, r3);        // Kl
                mma16816(sacc[2 * nf2],     qh[kf], r0, r2);
                mma16816(sacc[2 * nf2 + 1], qh[kf], r1, r3);
            }
        }

        if (t >= numt - 2) {
            int kt = t * 64;
            int qrow = q0 + wid * 16 + groupID;
            #pragma unroll
            for (int nf = 0; nf < 8; nf++) {
                int k0 = kt + nf * 8 + 2 * tg;
                if (k0     > qrow)     sacc[nf][0] = -1e30f;
                if (k0 + 1 > qrow)     sacc[nf][1] = -1e30f;
                if (k0     > qrow + 8) sacc[nf][2] = -1e30f;
                if (k0 + 1 > qrow + 8) sacc[nf][3] = -1e30f;
            }
        }

        float alpha[2];
        #pragma unroll
        for (int h = 0; h < 2; h++) {
            float rm = -1e30f;
            #pragma unroll
            for (int nf = 0; nf < 8; nf++)
                rm = fmaxf(rm, fmaxf(sacc[nf][2 * h], sacc[nf][2 * h + 1]));
            rm = fmaxf(rm, __shfl_xor_sync(0xffffffffu, rm, 1));
            rm = fmaxf(rm, __shfl_xor_sync(0xffffffffu, rm, 2));
            float mn = fmaxf(m[h], rm);
            alpha[h] = ex2f(m[h] - mn);
            m[h] = mn;
            float ls = 0.f;
            #pragma unroll
            for (int nf = 0; nf < 8; nf++) {
                float p0 = exp2poly(sacc[nf][2 * h]     - mn);
                float p1 = exp2poly(sacc[nf][2 * h + 1] - mn);
                sacc[nf][2 * h] = p0; sacc[nf][2 * h + 1] = p1;
                ls += p0 + p1;
            }
            lsum[h] = lsum[h] * alpha[h] + ls;
        }
        #pragma unroll
        for (int nd = 0; nd < 8; nd++) {
            oacc[nd][0] *= alpha[0]; oacc[nd][1] *= alpha[0];
            oacc[nd][2] *= alpha[1]; oacc[nd][3] *= alpha[1];
        }

        uint32_t pah[4][4], pal[4][4];
        #pragma unroll
        for (int kf = 0; kf < 4; kf++) {
            #pragma unroll
            for (int q = 0; q < 4; q++) {
                int nf = 2 * kf + (q >> 1);
                float x0 = sacc[nf][(q & 1) * 2], x1 = sacc[nf][(q & 1) * 2 + 1];
                __half h0 = __float2half_rn(x0), h1 = __float2half_rn(x1);
                __half2 hp; hp.x = h0; hp.y = h1;
                pah[kf][q] = *(uint32_t*)&hp;
                pal[kf][q] = packh2(x0 - __half2float(h0), x1 - __half2float(h1));
            }
        }

        // ---- O += P V (2 products: (ph+pl)*Vh) ----
        #pragma unroll
        for (int kf = 0; kf < 4; kf++) {
            #pragma unroll
            for (int nd2 = 0; nd2 < 4; nd2++) {
                int row = nd2 * 16 + (lane & 15);
                int ch = 2 * kf + (lane >> 4);
                uint32_t sw = row * 128 + ((ch ^ (row & 7)) << 4);
                uint32_t r0, r1, r2, r3;
                ldmA(KB + 16384 + sw, r0, r1, r2, r3);        // Vh
                mma16816(oacc[2 * nd2],     pah[kf], r0, r2);
                mma16816(oacc[2 * nd2 + 1], pah[kf], r1, r3);
                mma16816(oacc[2 * nd2],     pal[kf], r0, r2);
                mma16816(oacc[2 * nd2 + 1], pal[kf], r1, r3);
            }
        }
        __syncthreads();
    }

    #pragma unroll
    for (int h = 0; h < 2; h++) {
        lsum[h] += __shfl_xor_sync(0xffffffffu, lsum[h], 1);
        lsum[h] += __shfl_xor_sync(0xffffffffu, lsum[h], 2);
    }
    int b = bh >> 4, hd = bh & 15;
    #pragma unroll
    for (int h = 0; h < 2; h++) {
        int q = q0 + wid * 16 + groupID + 8 * h;
        float inv = 1.f / lsum[h];
        size_t rowbase = ((size_t)(b * Ss + q)) * Dm + hd * 64;
        #pragma unroll
        for (int nd = 0; nd < 8; nd++) {
            float x0 = oacc[nd][2 * h] * inv, x1 = oacc[nd][2 * h + 1] * inv;
            __half h0 = __float2half_rn(x0), h1 = __float2half_rn(x1);
            __half2 hp; hp.x = h0; hp.y = h1;
            size_t ad = rowbase + nd * 8 + 2 * tg;
            *(uint32_t*)(g_aoh + ad) = *(uint32_t*)&hp;
            *(uint32_t*)(g_aol + ad) = packh2(x0 - __half2float(h0),
                                              x1 - __half2float(h1));
        }
    }
}

// ============================================================
// launch
// ============================================================
extern "C" void kernel_launch(void* const* d_in, const int* in_sizes, int n_in,
                              void* d_out, int out_size) {
    const float* Q     = (const float*)d_in[0];
    const float* K     = (const float*)d_in[1];
    const float* V     = (const float*)d_in[2];
    const float* Wq    = (const float*)d_in[3];
    const float* bq    = (const float*)d_in[4];
    const float* Wk    = (const float*)d_in[5];
    const float* bk    = (const float*)d_in[6];
    const float* Wv    = (const float*)d_in[7];
    const float* bv    = (const float*)d_in[8];
    const float* Wo    = (const float*)d_in[9];
    const float* bo    = (const float*)d_in[10];
    const float* gamma = (const float*)d_in[11];
    const float* beta  = (const float*)d_in[12];
    float* out = (float*)d_out;

    float *mu_p, *rs_p, *c1_p, *c2_p;
    __half *xhq, *xlq, *xhk, *xlk, *xhv, *xlv, *wh_p;
    __half *qh_p, *ql_p, *kh_p, *kl_p, *vh_p, *aoh_p, *aol_p;
    cudaGetSymbolAddress((void**)&mu_p, g_mu);
    cudaGetSymbolAddress((void**)&rs_p, g_rs);
    cudaGetSymbolAddress((void**)&c1_p, g_c1);
    cudaGetSymbolAddress((void**)&c2_p, g_c2);
    cudaGetSymbolAddress((void**)&xhq, g_xh_q);
    cudaGetSymbolAddress((void**)&xlq, g_xl_q);
    cudaGetSymbolAddress((void**)&xhk, g_xh_k);
    cudaGetSymbolAddress((void**)&xlk, g_xl_k);
    cudaGetSymbolAddress((void**)&xhv, g_xh_v);
    cudaGetSymbolAddress((void**)&xlv, g_xl_v);
    cudaGetSymbolAddress((void**)&wh_p, g_wh);
    cudaGetSymbolAddress((void**)&qh_p, g_qh);
    cudaGetSymbolAddress((void**)&ql_p, g_ql);
    cudaGetSymbolAddress((void**)&kh_p, g_kh);
    cudaGetSymbolAddress((void**)&kl_p, g_kl);
    cudaGetSymbolAddress((void**)&vh_p, g_vh);
    cudaGetSymbolAddress((void**)&aoh_p, g_aoh);
    cudaGetSymbolAddress((void**)&aol_p, g_aol);

    cudaMemsetAsync(c1_p, 0, 3 * Dm * sizeof(float));
    cudaMemsetAsync(c2_p, 0, 3 * Dm * sizeof(float));
    ln_split_kernel<<<3 * NROWS / 8, 256>>>(Q, K, V);
    wprep_kernel<<<dim3(16, 16, 4), 256>>>(Wq, Wk, Wv, Wo, gamma, beta, bq, bk, bv);

    size_t gsmem = NSTG * STG;   // 72K
    cudaFuncSetAttribute((const void*)gemm_mma_kernel<0>, cudaFuncAttributeMaxDynamicSharedMemorySize, (int)gsmem);
    cudaFuncSetAttribute((const void*)gemm_mma_kernel<3>, cudaFuncAttributeMaxDynamicSharedMemorySize, (int)gsmem);
    cudaFuncSetAttribute((const void*)gemm_mma_kernel<2>, cudaFuncAttributeMaxDynamicSharedMemorySize, (int)gsmem);
    cudaFuncSetAttribute((const void*)gemm_mma_kernel<1>, cudaFuncAttributeMaxDynamicSharedMemorySize, (int)gsmem);
    dim3 gg(Dm / BN, NROWS / BM);
    size_t WSZ = (size_t)Dm * Dm;

    gemm_mma_kernel<0><<<gg, 256, gsmem>>>(xhq, xlq, wh_p,
                                           c1_p, c2_p, rs_p, mu_p, nullptr,
                                           nullptr, qh_p, ql_p);
    gemm_mma_kernel<3><<<gg, 256, gsmem>>>(xhk, xlk, wh_p + WSZ,
                                           c1_p + Dm, c2_p + Dm, rs_p + NROWS, mu_p + NROWS,
                                           nullptr, nullptr, kh_p, kl_p);
    gemm_mma_kernel<2><<<gg, 256, gsmem>>>(xhv, xlv, wh_p + 2 * WSZ,
                                           c1_p + 2 * Dm, c2_p + 2 * Dm,
                                           rs_p + 2 * NROWS, mu_p + 2 * NROWS,
                                           nullptr, nullptr, vh_p, nullptr);

    size_t asmem = 32768 + 2 * KVB;   // 81920
    cudaFuncSetAttribute(attn_mma_kernel, cudaFuncAttributeMaxDynamicSharedMemorySize, (int)asmem);
    attn_mma_kernel<<<dim3(16, 64), 256, asmem>>>();

    gemm_mma_kernel<1><<<gg, 256, gsmem>>>(aoh_p, aol_p, wh_p + 3 * WSZ,
                                           nullptr, bo, nullptr, nullptr, Q,
                                           out, nullptr, nullptr);
}

// round 13
// speedup vs baseline: 1.3360x; 1.0494x over previous
#include <cuda_runtime.h>
#include <cuda_fp16.h>
#include <cstdint>
#include <math.h>

#define Dm 1024
#define Hh 16
#define DHd 64
#define Bb 4
#define Ss 2048
#define NROWS (Bb*Ss)   // 8192
#define LOG2E 1.4426950408889634f

// ---------------- static device scratch ----------------
__device__ float g_mu[3*NROWS];
__device__ float g_rs[3*NROWS];
__device__ __half g_xh_q[NROWS*Dm]; __device__ __half g_xl_q[NROWS*Dm];
__device__ __half g_xh_k[NROWS*Dm]; __device__ __half g_xl_k[NROWS*Dm];
__device__ __half g_xh_v[NROWS*Dm]; __device__ __half g_xl_v[NROWS*Dm];
__device__ __half g_wh[4*Dm*Dm];
__device__ float g_c1[3*Dm];
__device__ float g_c2[3*Dm];
__device__ __half g_qh[NROWS*Dm], g_ql[NROWS*Dm];  // [bh][s][d], *LOG2E
__device__ __half g_kh[NROWS*Dm], g_kl[NROWS*Dm];  // [bh][s][d]
__device__ __half g_vh[NROWS*Dm];                  // [bh][d][s], single fp16
__device__ __half g_aoh[NROWS*Dm], g_aol[NROWS*Dm]; // [b*s][D]

// ---------------- helpers ----------------
__device__ __forceinline__ uint32_t smem_u32(const void* p) {
    uint32_t a;
    asm("{ .reg .u64 t; cvta.to.shared.u64 t, %1; cvt.u32.u64 %0, t; }" : "=r"(a) : "l"(p));
    return a;
}
__device__ __forceinline__ void cp16(uint32_t s, const void* g) {
    asm volatile("cp.async.cg.shared.global [%0], [%1], 16;\n" :: "r"(s), "l"(g));
}
__device__ __forceinline__ void ldmA(uint32_t addr, uint32_t& r0, uint32_t& r1,
                                     uint32_t& r2, uint32_t& r3) {
    asm volatile("ldmatrix.sync.aligned.m8n8.x4.shared.b16 {%0,%1,%2,%3}, [%4];"
                 : "=r"(r0), "=r"(r1), "=r"(r2), "=r"(r3) : "r"(addr));
}
__device__ __forceinline__ void mma16816(float* c, const uint32_t* a,
                                         uint32_t b0, uint32_t b1) {
    asm volatile("mma.sync.aligned.m16n8k16.row.col.f32.f16.f16.f32 "
                 "{%0,%1,%2,%3}, {%4,%5,%6,%7}, {%8,%9}, {%0,%1,%2,%3};"
                 : "+f"(c[0]), "+f"(c[1]), "+f"(c[2]), "+f"(c[3])
                 : "r"(a[0]), "r"(a[1]), "r"(a[2]), "r"(a[3]), "r"(b0), "r"(b1));
}
__device__ __forceinline__ float ex2f(float x) {
    float r; asm("ex2.approx.f32 %0, %1;" : "=f"(r) : "f"(x)); return r;
}
__device__ __forceinline__ float exp2poly(float z) {
    z = fmaxf(z, -126.f);
    float t = z + 12582912.f;
    int n = __float_as_int(t) - 0x4B400000;
    float f = z - (t - 12582912.f);
    float p = fmaf(0.0096181291f, f, 0.055504109f);
    p = fmaf(p, f, 0.24022651f);
    p = fmaf(p, f, 0.69314718f);
    p = fmaf(p, f, 1.0f);
    return __int_as_float(__float_as_int(p) + (n << 23));
}
__device__ __forceinline__ uint32_t packh2(float a, float b) {
    __half2 t;
    t.x = __float2half_rn(a);
    t.y = __float2half_rn(b);
    return *(uint32_t*)&t;
}

// ============================================================
// 1) LN stats + fp16 hi/lo split — warp per row
// ============================================================
__global__ void ln_split_kernel(const float* __restrict__ Q,
                                const float* __restrict__ K,
                                const float* __restrict__ V) {
    int wid = threadIdx.x >> 5, lane = threadIdx.x & 31;
    int row = blockIdx.x * 8 + wid;
    int which = row >> 13;
    int r = row & (NROWS - 1);
    const float* x; __half* xh; __half* xl;
    if (which == 0)      { x = Q; xh = g_xh_q; xl = g_xl_q; }
    else if (which == 1) { x = K; xh = g_xh_k; xl = g_xl_k; }
    else                 { x = V; xh = g_xh_v; xl = g_xl_v; }
    const float4* xr = (const float4*)(x + (size_t)r * Dm);

    float4 v[8];
    float s = 0.f, s2 = 0.f;
    #pragma unroll
    for (int i = 0; i < 8; i++) {
        v[i] = xr[lane + i * 32];
        s  += v[i].x + v[i].y + v[i].z + v[i].w;
        s2 += v[i].x * v[i].x + v[i].y * v[i].y + v[i].z * v[i].z + v[i].w * v[i].w;
    }
    #pragma unroll
    for (int o = 16; o > 0; o >>= 1) {
        s  += __shfl_xor_sync(0xffffffffu, s,  o);
        s2 += __shfl_xor_sync(0xffffffffu, s2, o);
    }
    float muv = s / (float)Dm;
    float var = s2 / (float)Dm - muv * muv;
    if (lane == 0) {
        g_mu[row] = muv;
        g_rs[row] = rsqrtf(var + 1e-6f);
    }
    uint2* xhp = (uint2*)(xh + (size_t)r * Dm);
    uint2* xlp = (uint2*)(xl + (size_t)r * Dm);
    #pragma unroll
    for (int i = 0; i < 8; i++) {
        __half h0 = __float2half_rn(v[i].x), h1 = __float2half_rn(v[i].y);
        __half h2 = __float2half_rn(v[i].z), h3 = __float2half_rn(v[i].w);
        uint2 hv, lv;
        __half2 p01, p23;
        p01.x = h0; p01.y = h1; p23.x = h2; p23.y = h3;
        hv.x = *(uint32_t*)&p01; hv.y = *(uint32_t*)&p23;
        lv.x = packh2(v[i].x - __half2float(h0), v[i].y - __half2float(h1));
        lv.y = packh2(v[i].z - __half2float(h2), v[i].w - __half2float(h3));
        xhp[lane + i * 32] = hv;
        xlp[lane + i * 32] = lv;
    }
}

// ============================================================
// 2) weight prep (fp16 single) + fused column constants
// ============================================================
__global__ void wprep_kernel(const float* __restrict__ Wq, const float* __restrict__ Wk,
                             const float* __restrict__ Wv, const float* __restrict__ Wo,
                             const float* __restrict__ gamma, const float* __restrict__ beta,
                             const float* __restrict__ bq, const float* __restrict__ bk,
                             const float* __restrict__ bv) {
    int w = blockIdx.z;
    const float* W = (w == 0) ? Wq : (w == 1) ? Wk : (w == 2) ? Wv : Wo;
    const float* b = (w == 0) ? bq : (w == 1) ? bk : bv;
    __shared__ float ts[64][65];
    int n0 = blockIdx.x * 64, k0 = blockIdx.y * 64;
    int tx = threadIdx.x & 63, ty = threadIdx.x >> 6;

    float s1 = 0.f, s2 = 0.f;
    #pragma unroll
    for (int l = 0; l < 16; l++) {
        int k = ty + l * 4;
        float wv = W[(size_t)(k0 + k) * Dm + n0 + tx];
        float g = (w < 3) ? gamma[k0 + k] : 1.f;
        float gw = g * wv;
        ts[k][tx] = gw;
        if (w < 3) { s1 += gw; s2 += beta[k0 + k] * wv; }
    }
    if (w < 3) {
        if (k0 == 0 && ty == 0) s2 += b[n0 + tx];
        atomicAdd(&g_c1[w * Dm + n0 + tx], s1);
        atomicAdd(&g_c2[w * Dm + n0 + tx], s2);
    }
    __syncthreads();
    __half* whp = g_wh + (size_t)w * Dm * Dm;
    #pragma unroll
    for (int l = 0; l < 16; l++) {
        int n = ty + l * 4;
        size_t o = (size_t)(n0 + n) * Dm + k0 + tx;
        whp[o] = __float2half_rn(ts[tx][n]);
    }
}

// ============================================================
// 3) GEMM common pieces
// ============================================================
#define BM 128
#define BN 128
#define BK 32
#define KBYTES 64
#define STG   24576          // Ah + Al + Bh per stage
#define NSTG  3
#define NT    32

#define SW(r, kc) ((uint32_t)((r) * KBYTES + ((((kc) ^ (((r) >> 1) & 3))) << 4)))

// main-loop body shared by both GEMM kernels
__device__ __forceinline__ void gemm_mainloop(
    uint32_t sbase, int tid, int lane, int warpM, int warpN,
    const __half* Ah, const __half* Al, const __half* Bh,
    int m0, int n0, float acc[4][4][4])
{
    auto prefetch = [&](int t) {
        int s = t % NSTG;
        int kb = t * BK;
        uint32_t st = sbase + s * STG;
        #pragma unroll
        for (int l = 0; l < 6; l++) {
            int e = tid + l * 256;
            int tile = e >> 9;              // 0:Ah 1:Al 2:Bh
            int idx = e & 511;
            int r = idx >> 2, kc = idx & 3;
            const __half* p = (tile == 0) ? Ah : (tile == 1) ? Al : Bh;
            int rb = (tile < 2) ? m0 : n0;
            cp16(st + tile * 8192 + SW(r, kc), p + (size_t)(rb + r) * Dm + kb + kc * 8);
        }
    };

    prefetch(0); asm volatile("cp.async.commit_group;\n" ::: "memory");
    prefetch(1); asm volatile("cp.async.commit_group;\n" ::: "memory");

    for (int t = 0; t < NT; t++) {
        asm volatile("cp.async.wait_group 1;\n" ::: "memory");
        __syncthreads();
        if (t + 2 < NT) prefetch(t + 2);
        asm volatile("cp.async.commit_group;\n" ::: "memory");

        uint32_t st = sbase + (t % NSTG) * STG;
        uint32_t sAh = st, sAl = st + 8192, sBh = st + 16384;
        #pragma unroll
        for (int ks = 0; ks < 2; ks++) {
            uint32_t ah[4][4], al[4][4];
            #pragma unroll
            for (int mf = 0; mf < 4; mf++) {
                int row = warpM * 64 + mf * 16 + (lane & 15);
                int ch = ks * 2 + (lane >> 4);
                uint32_t sw = SW(row, ch);
                ldmA(sAh + sw, ah[mf][0], ah[mf][1], ah[mf][2], ah[mf][3]);
                ldmA(sAl + sw, al[mf][0], al[mf][1], al[mf][2], al[mf][3]);
            }
            #pragma unroll
            for (int nf2 = 0; nf2 < 2; nf2++) {
                int nrow = warpN * 32 + nf2 * 16 + (lane & 7) + ((lane >> 4) << 3);
                int ch = ks * 2 + ((lane >> 3) & 1);
                uint32_t swb = SW(nrow, ch);
                uint32_t r0, r1, r2, r3;
                ldmA(sBh + swb, r0, r1, r2, r3);
                #pragma unroll
                for (int mf = 0; mf < 4; mf++) {
                    mma16816(acc[mf][2*nf2],   ah[mf], r0, r1);
                    mma16816(acc[mf][2*nf2+1], ah[mf], r2, r3);
                    mma16816(acc[mf][2*nf2],   al[mf], r0, r1);
                    mma16816(acc[mf][2*nf2+1], al[mf], r2, r3);
                }
            }
        }
    }
}

// ---- merged Q/K/V projection GEMM: blockIdx.z selects operands+epilogue ----
__global__ void __launch_bounds__(256, 2) gemm_qkv_kernel() {
    extern __shared__ char smem[];
    uint32_t sbase = smem_u32(smem);
    int tid = threadIdx.x, lane = tid & 31, wid = tid >> 5;
    int warpM = wid & 1, warpN = wid >> 1;
    int m0 = blockIdx.y * BM, n0 = blockIdx.x * BN;
    int z = blockIdx.z;                   // 0:Q 1:K 2:V

    const __half* Ah = (z == 0) ? g_xh_q : (z == 1) ? g_xh_k : g_xh_v;
    const __half* Al = (z == 0) ? g_xl_q : (z == 1) ? g_xl_k : g_xl_v;
    const __half* Bh = g_wh + (size_t)z * Dm * Dm;

    float acc[4][4][4] = {};
    gemm_mainloop(sbase, tid, lane, warpM, warpN, Ah, Al, Bh, m0, n0, acc);

    const float* c1 = g_c1 + z * Dm;
    const float* c2 = g_c2 + z * Dm;
    const float* rs = g_rs + z * NROWS;
    const float* mu = g_mu + z * NROWS;

    int groupID = lane >> 2, tg = lane & 3;
    #pragma unroll
    for (int mf = 0; mf < 4; mf++) {
        #pragma unroll
        for (int half = 0; half < 2; half++) {
            int r = m0 + warpM * 64 + mf * 16 + groupID + half * 8;
            float rsv = rs[r], muv = mu[r];
            int b = r >> 11, srow = r & 2047;
            #pragma unroll
            for (int nf = 0; nf < 4; nf++) {
                int c = n0 + warpN * 32 + nf * 8 + 2 * tg;
                float x0 = acc[mf][nf][2 * half + 0];
                float x1 = acc[mf][nf][2 * half + 1];
                float2 c1v = *(const float2*)(c1 + c);
                float2 c2v = *(const float2*)(c2 + c);
                float o0 = rsv * (x0 - muv * c1v.x) + c2v.x;
                float o1 = rsv * (x1 - muv * c1v.y) + c2v.y;
                if (z == 0) { o0 *= LOG2E; o1 *= LOG2E; }
                __half h0 = __float2half_rn(o0);
                __half h1 = __float2half_rn(o1);
                int hd = c >> 6, dd = c & 63;
                int bh = b * Hh + hd;
                if (z == 2) {
                    size_t a0 = ((size_t)(bh * DHd + dd)) * Ss + srow;
                    size_t a1 = ((size_t)(bh * DHd + dd + 1)) * Ss + srow;
                    g_vh[a0] = h0; g_vh[a1] = h1;
                } else {
                    float l0 = o0 - __half2float(h0);
                    float l1 = o1 - __half2float(h1);
                    size_t ad = ((size_t)(bh * Ss + srow)) * DHd + dd;
                    __half2 hp; hp.x = h0; hp.y = h1;
                    __half* oH = (z == 0) ? g_qh : g_kh;
                    __half* oL = (z == 0) ? g_ql : g_kl;
                    *(uint32_t*)(oH + ad) = *(uint32_t*)&hp;
                    *(uint32_t*)(oL + ad) = packh2(l0, l1);
                }
            }
        }
    }
}

// ---- O projection GEMM: +bias +residual, fp32 out ----
__global__ void __launch_bounds__(256, 2) gemm_o_kernel(
    const float* __restrict__ bo, const float* __restrict__ resid,
    float* __restrict__ outF)
{
    extern __shared__ char smem[];
    uint32_t sbase = smem_u32(smem);
    int tid = threadIdx.x, lane = tid & 31, wid = tid >> 5;
    int warpM = wid & 1, warpN = wid >> 1;
    int m0 = blockIdx.y * BM, n0 = blockIdx.x * BN;

    float acc[4][4][4] = {};
    gemm_mainloop(sbase, tid, lane, warpM, warpN, g_aoh, g_aol,
                  g_wh + 3 * (size_t)Dm * Dm, m0, n0, acc);

    int groupID = lane >> 2, tg = lane & 3;
    #pragma unroll
    for (int mf = 0; mf < 4; mf++) {
        #pragma unroll
        for (int half = 0; half < 2; half++) {
            int r = m0 + warpM * 64 + mf * 16 + groupID + half * 8;
            #pragma unroll
            for (int nf = 0; nf < 4; nf++) {
                int c = n0 + warpN * 32 + nf * 8 + 2 * tg;
                float x0 = acc[mf][nf][2 * half + 0];
                float x1 = acc[mf][nf][2 * half + 1];
                float2 bo2 = *(const float2*)(bo + c);
                float2 q2  = *(const float2*)(resid + (size_t)r * Dm + c);
                float2 o;
                o.x = x0 + bo2.x + q2.x;
                o.y = x1 + bo2.y + q2.y;
                *(float2*)(outF + (size_t)r * Dm + c) = o;
            }
        }
    }
}

// ============================================================
// 4) tensor-core causal attention, fp16 (unchanged from R12).
// ============================================================
__device__ __forceinline__ void loadKV(int bh, int t, uint32_t base, int tid) {
    int kt = t * 64;
    const __half* khp = g_kh + ((size_t)bh * Ss + kt) * DHd;
    const __half* klp = g_kl + ((size_t)bh * Ss + kt) * DHd;
    const __half* vhp = g_vh + (size_t)bh * DHd * Ss + kt;
    #pragma unroll
    for (int l = 0; l < 2; l++) {
        int e = tid + l * 256;
        int row = e >> 3, c = e & 7;
        uint32_t d = row * 128 + ((c ^ (row & 7)) << 4);
        cp16(base + d,         khp + (size_t)row * DHd + c * 8);
        cp16(base + 8192 + d,  klp + (size_t)row * DHd + c * 8);
        cp16(base + 16384 + d, vhp + (size_t)row * Ss + c * 8);
    }
}

#define KVB 24576

__global__ void __launch_bounds__(256, 2) attn_mma_kernel() {
    extern __shared__ char smraw[];
    uint32_t sb = smem_u32(smraw);
    const uint32_t QHs = sb;
    const uint32_t KVs = sb + 32768;
    int tid = threadIdx.x, lane = tid & 31, wid = tid >> 5;
    int groupID = lane >> 2, tg = lane & 3;
    int bh = blockIdx.y;
    int mt = (int)(gridDim.x - 1) - (int)blockIdx.x;
    int q0 = mt * 128;
    int numt = 2 * mt + 2;

    const __half* qhp = g_qh + ((size_t)bh * Ss + q0) * DHd;
    const __half* qlp = g_ql + ((size_t)bh * Ss + q0) * DHd;

    #pragma unroll
    for (int l = 0; l < 4; l++) {
        int e = tid + l * 256;
        int row = e >> 3, c = e & 7;
        uint32_t d = row * 128 + ((c ^ (row & 7)) << 4);
        cp16(QHs + d,         qhp + (size_t)row * DHd + c * 8);
        cp16(QHs + 16384 + d, qlp + (size_t)row * DHd + c * 8);
    }
    asm volatile("cp.async.commit_group;\n" ::: "memory");
    loadKV(bh, 0, KVs, tid);
    asm volatile("cp.async.commit_group;\n" ::: "memory");
    asm volatile("cp.async.wait_group 1;\n" ::: "memory");
    __syncthreads();

    uint32_t qh[4][4];
    #pragma unroll
    for (int kf = 0; kf < 4; kf++) {
        int row = wid * 16 + (lane & 15);
        int ch = 2 * kf + (lane >> 4);
        uint32_t ad = QHs + row * 128 + ((ch ^ (row & 7)) << 4);
        ldmA(ad, qh[kf][0], qh[kf][1], qh[kf][2], qh[kf][3]);
    }

    float m[2] = {-1e30f, -1e30f}, lsum[2] = {0.f, 0.f};
    float oacc[8][4] = {};

    for (int t = 0; t < numt; t++) {
        if (t + 1 < numt) loadKV(bh, t + 1, KVs + ((t + 1) & 1) * KVB, tid);
        asm volatile("cp.async.commit_group;\n" ::: "memory");
        asm volatile("cp.async.wait_group 1;\n" ::: "memory");
        __syncthreads();
        uint32_t KB = KVs + (t & 1) * KVB;

        float sacc[8][4] = {};
        #pragma unroll
        for (int kf = 0; kf < 4; kf++) {
            uint32_t qlf[4];
            {
                int row = wid * 16 + (lane & 15);
                int ch = 2 * kf + (lane >> 4);
                uint32_t ad = QHs + 16384 + row * 128 + ((ch ^ (row & 7)) << 4);
                ldmA(ad, qlf[0], qlf[1], qlf[2], qlf[3]);
            }
            #pragma unroll
            for (int nf2 = 0; nf2 < 4; nf2++) {
                int row = nf2 * 16 + (lane & 15);
                int ch = 2 * kf + (lane >> 4);
                uint32_t sw = row * 128 + ((ch ^ (row & 7)) << 4);
                uint32_t r0, r1, r2, r3;
                ldmA(KB + sw, r0, r1, r2, r3);               // Kh
                mma16816(sacc[2 * nf2],     qh[kf], r0, r2);
                mma16816(sacc[2 * nf2 + 1], qh[kf], r1, r3);
                mma16816(sacc[2 * nf2],     qlf,    r0, r2);
                mma16816(sacc[2 * nf2 + 1], qlf,    r1, r3);
                ldmA(KB + 8192 + sw, r0, r1, r2, r3);        // Kl
                mma16816(sacc[2 * nf2],     qh[kf], r0, r2);
                mma16816(sacc[2 * nf2 + 1], qh[kf], r1, r3);
            }
        }

        if (t >= numt - 2) {
            int kt = t * 64;
            int qrow = q0 + wid * 16 + groupID;
            #pragma unroll
            for (int nf = 0; nf < 8; nf++) {
                int k0 = kt + nf * 8 + 2 * tg;
                if (k0     > qrow)     sacc[nf][0] = -1e30f;
                if (k0 + 1 > qrow)     sacc[nf][1] = -1e30f;
                if (k0     > qrow + 8) sacc[nf][2] = -1e30f;
                if (k0 + 1 > qrow + 8) sacc[nf][3] = -1e30f;
            }
        }

        float alpha[2];
        #pragma unroll
        for (int h = 0; h < 2; h++) {
            float rm = -1e30f;
            #pragma unroll
            for (int nf = 0; nf < 8; nf++)
                rm = fmaxf(rm, fmaxf(sacc[nf][2 * h], sacc[nf][2 * h + 1]));
            rm = fmaxf(rm, __shfl_xor_sync(0xffffffffu, rm, 1));
            rm = fmaxf(rm, __shfl_xor_sync(0xffffffffu, rm, 2));
            float mn = fmaxf(m[h], rm);
            alpha[h] = ex2f(m[h] - mn);
            m[h] = mn;
            float ls = 0.f;
            #pragma unroll
            for (int nf = 0; nf < 8; nf++) {
                float p0 = exp2poly(sacc[nf][2 * h]     - mn);
                float p1 = exp2poly(sacc[nf][2 * h + 1] - mn);
                sacc[nf][2 * h] = p0; sacc[nf][2 * h + 1] = p1;
                ls += p0 + p1;
            }
            lsum[h] = lsum[h] * alpha[h] + ls;
        }
        #pragma unroll
        for (int nd = 0; nd < 8; nd++) {
            oacc[nd][0] *= alpha[0]; oacc[nd][1] *= alpha[0];
            oacc[nd][2] *= alpha[1]; oacc[nd][3] *= alpha[1];
        }

        uint32_t pah[4][4], pal[4][4];
        #pragma unroll
        for (int kf = 0; kf < 4; kf++) {
            #pragma unroll
            for (int q = 0; q < 4; q++) {
                int nf = 2 * kf + (q >> 1);
                float x0 = sacc[nf][(q & 1) * 2], x1 = sacc[nf][(q & 1) * 2 + 1];
                __half h0 = __float2half_rn(x0), h1 = __float2half_rn(x1);
                __half2 hp; hp.x = h0; hp.y = h1;
                pah[kf][q] = *(uint32_t*)&hp;
                pal[kf][q] = packh2(x0 - __half2float(h0), x1 - __half2float(h1));
            }
        }

        #pragma unroll
        for (int kf = 0; kf < 4; kf++) {
            #pragma unroll
            for (int nd2 = 0; nd2 < 4; nd2++) {
                int row = nd2 * 16 + (lane & 15);
                int ch = 2 * kf + (lane >> 4);
                uint32_t sw = row * 128 + ((ch ^ (row & 7)) << 4);
                uint32_t r0, r1, r2, r3;
                ldmA(KB + 16384 + sw, r0, r1, r2, r3);        // Vh
                mma16816(oacc[2 * nd2],     pah[kf], r0, r2);
                mma16816(oacc[2 * nd2 + 1], pah[kf], r1, r3);
                mma16816(oacc[2 * nd2],     pal[kf], r0, r2);
                mma16816(oacc[2 * nd2 + 1], pal[kf], r1, r3);
            }
        }
        __syncthreads();
    }

    #pragma unroll
    for (int h = 0; h < 2; h++) {
        lsum[h] += __shfl_xor_sync(0xffffffffu, lsum[h], 1);
        lsum[h] += __shfl_xor_sync(0xffffffffu, lsum[h], 2);
    }
    int b = bh >> 4, hd = bh & 15;
    #pragma unroll
    for (int h = 0; h < 2; h++) {
        int q = q0 + wid * 16 + groupID + 8 * h;
        float inv = 1.f / lsum[h];
        size_t rowbase = ((size_t)(b * Ss + q)) * Dm + hd * 64;
        #pragma unroll
        for (int nd = 0; nd < 8; nd++) {
            float x0 = oacc[nd][2 * h] * inv, x1 = oacc[nd][2 * h + 1] * inv;
            __half h0 = __float2half_rn(x0), h1 = __float2half_rn(x1);
            __half2 hp; hp.x = h0; hp.y = h1;
            size_t ad = rowbase + nd * 8 + 2 * tg;
            *(uint32_t*)(g_aoh + ad) = *(uint32_t*)&hp;
            *(uint32_t*)(g_aol + ad) = packh2(x0 - __half2float(h0),
                                              x1 - __half2float(h1));
        }
    }
}

// ============================================================
// launch
// ============================================================
extern "C" void kernel_launch(void* const* d_in, const int* in_sizes, int n_in,
                              void* d_out, int out_size) {
    const float* Q     = (const float*)d_in[0];
    const float* K     = (const float*)d_in[1];
    const float* V     = (const float*)d_in[2];
    const float* Wq    = (const float*)d_in[3];
    const float* bq    = (const float*)d_in[4];
    const float* Wk    = (const float*)d_in[5];
    const float* bk    = (const float*)d_in[6];
    const float* Wv    = (const float*)d_in[7];
    const float* bv    = (const float*)d_in[8];
    const float* Wo    = (const float*)d_in[9];
    const float* bo    = (const float*)d_in[10];
    const float* gamma = (const float*)d_in[11];
    const float* beta  = (const float*)d_in[12];
    float* out = (float*)d_out;

    float *c1_p, *c2_p;
    cudaGetSymbolAddress((void**)&c1_p, g_c1);
    cudaGetSymbolAddress((void**)&c2_p, g_c2);

    cudaMemsetAsync(c1_p, 0, 3 * Dm * sizeof(float));
    cudaMemsetAsync(c2_p, 0, 3 * Dm * sizeof(float));
    ln_split_kernel<<<3 * NROWS / 8, 256>>>(Q, K, V);
    wprep_kernel<<<dim3(16, 16, 4), 256>>>(Wq, Wk, Wv, Wo, gamma, beta, bq, bk, bv);

    size_t gsmem = NSTG * STG;   // 72K
    cudaFuncSetAttribute(gemm_qkv_kernel, cudaFuncAttributeMaxDynamicSharedMemorySize, (int)gsmem);
    cudaFuncSetAttribute(gemm_o_kernel,   cudaFuncAttributeMaxDynamicSharedMemorySize, (int)gsmem);

    // merged Q/K/V projections: one launch, z selects operands/epilogue
    gemm_qkv_kernel<<<dim3(Dm / BN, NROWS / BM, 3), 256, gsmem>>>();

    size_t asmem = 32768 + 2 * KVB;   // 81920
    cudaFuncSetAttribute(attn_mma_kernel, cudaFuncAttributeMaxDynamicSharedMemorySize, (int)asmem);
    attn_mma_kernel<<<dim3(16, 64), 256, asmem>>>();

    gemm_o_kernel<<<dim3(Dm / BN, NROWS / BM), 256, gsmem>>>(bo, Q, out);
}

// round 14
// speedup vs baseline: 1.4040x; 1.0509x over previous
#include <cuda_runtime.h>
#include <cuda_fp16.h>
#include <cstdint>
#include <math.h>

#define Dm 1024
#define Hh 16
#define DHd 64
#define Bb 4
#define Ss 2048
#define NROWS (Bb*Ss)   // 8192
#define LOG2E 1.4426950408889634f

// ---------------- static device scratch ----------------
__device__ float g_mu[3*NROWS];
__device__ float g_rs[3*NROWS];
__device__ __half g_xh_q[NROWS*Dm]; __device__ __half g_xl_q[NROWS*Dm];
__device__ __half g_xh_k[NROWS*Dm]; __device__ __half g_xl_k[NROWS*Dm];
__device__ __half g_xh_v[NROWS*Dm]; __device__ __half g_xl_v[NROWS*Dm];
__device__ __half g_wh[4*Dm*Dm];
__device__ float g_c1[3*Dm];
__device__ float g_c2[3*Dm];
__device__ __half g_qh[NROWS*Dm], g_ql[NROWS*Dm];  // [bh][s][d], *LOG2E
__device__ __half g_kh[NROWS*Dm];                  // [bh][s][d], single fp16
__device__ __half g_vh[NROWS*Dm];                  // [bh][d][s], single fp16
__device__ __half g_aoh[NROWS*Dm], g_aol[NROWS*Dm]; // [b*s][D]

// ---------------- helpers ----------------
__device__ __forceinline__ uint32_t smem_u32(const void* p) {
    uint32_t a;
    asm("{ .reg .u64 t; cvta.to.shared.u64 t, %1; cvt.u32.u64 %0, t; }" : "=r"(a) : "l"(p));
    return a;
}
__device__ __forceinline__ void cp16(uint32_t s, const void* g) {
    asm volatile("cp.async.cg.shared.global [%0], [%1], 16;\n" :: "r"(s), "l"(g));
}
__device__ __forceinline__ void ldmA(uint32_t addr, uint32_t& r0, uint32_t& r1,
                                     uint32_t& r2, uint32_t& r3) {
    asm volatile("ldmatrix.sync.aligned.m8n8.x4.shared.b16 {%0,%1,%2,%3}, [%4];"
                 : "=r"(r0), "=r"(r1), "=r"(r2), "=r"(r3) : "r"(addr));
}
__device__ __forceinline__ void mma16816(float* c, const uint32_t* a,
                                         uint32_t b0, uint32_t b1) {
    asm volatile("mma.sync.aligned.m16n8k16.row.col.f32.f16.f16.f32 "
                 "{%0,%1,%2,%3}, {%4,%5,%6,%7}, {%8,%9}, {%0,%1,%2,%3};"
                 : "+f"(c[0]), "+f"(c[1]), "+f"(c[2]), "+f"(c[3])
                 : "r"(a[0]), "r"(a[1]), "r"(a[2]), "r"(a[3]), "r"(b0), "r"(b1));
}
__device__ __forceinline__ float ex2f(float x) {
    float r; asm("ex2.approx.f32 %0, %1;" : "=f"(r) : "f"(x)); return r;
}
__device__ __forceinline__ float exp2poly(float z) {
    z = fmaxf(z, -126.f);
    float t = z + 12582912.f;
    int n = __float_as_int(t) - 0x4B400000;
    float f = z - (t - 12582912.f);
    float p = fmaf(0.0096181291f, f, 0.055504109f);
    p = fmaf(p, f, 0.24022651f);
    p = fmaf(p, f, 0.69314718f);
    p = fmaf(p, f, 1.0f);
    return __int_as_float(__float_as_int(p) + (n << 23));
}
__device__ __forceinline__ uint32_t packh2(float a, float b) {
    __half2 t;
    t.x = __float2half_rn(a);
    t.y = __float2half_rn(b);
    return *(uint32_t*)&t;
}

// ============================================================
// 1) LN stats + fp16 hi/lo split — warp per row
// ============================================================
__global__ void ln_split_kernel(const float* __restrict__ Q,
                                const float* __restrict__ K,
                                const float* __restrict__ V) {
    int wid = threadIdx.x >> 5, lane = threadIdx.x & 31;
    int row = blockIdx.x * 8 + wid;
    int which = row >> 13;
    int r = row & (NROWS - 1);
    const float* x; __half* xh; __half* xl;
    if (which == 0)      { x = Q; xh = g_xh_q; xl = g_xl_q; }
    else if (which == 1) { x = K; xh = g_xh_k; xl = g_xl_k; }
    else                 { x = V; xh = g_xh_v; xl = g_xl_v; }
    const float4* xr = (const float4*)(x + (size_t)r * Dm);

    float4 v[8];
    float s = 0.f, s2 = 0.f;
    #pragma unroll
    for (int i = 0; i < 8; i++) {
        v[i] = xr[lane + i * 32];
        s  += v[i].x + v[i].y + v[i].z + v[i].w;
        s2 += v[i].x * v[i].x + v[i].y * v[i].y + v[i].z * v[i].z + v[i].w * v[i].w;
    }
    #pragma unroll
    for (int o = 16; o > 0; o >>= 1) {
        s  += __shfl_xor_sync(0xffffffffu, s,  o);
        s2 += __shfl_xor_sync(0xffffffffu, s2, o);
    }
    float muv = s / (float)Dm;
    float var = s2 / (float)Dm - muv * muv;
    if (lane == 0) {
        g_mu[row] = muv;
        g_rs[row] = rsqrtf(var + 1e-6f);
    }
    uint2* xhp = (uint2*)(xh + (size_t)r * Dm);
    uint2* xlp = (uint2*)(xl + (size_t)r * Dm);
    #pragma unroll
    for (int i = 0; i < 8; i++) {
        __half h0 = __float2half_rn(v[i].x), h1 = __float2half_rn(v[i].y);
        __half h2 = __float2half_rn(v[i].z), h3 = __float2half_rn(v[i].w);
        uint2 hv, lv;
        __half2 p01, p23;
        p01.x = h0; p01.y = h1; p23.x = h2; p23.y = h3;
        hv.x = *(uint32_t*)&p01; hv.y = *(uint32_t*)&p23;
        lv.x = packh2(v[i].x - __half2float(h0), v[i].y - __half2float(h1));
        lv.y = packh2(v[i].z - __half2float(h2), v[i].w - __half2float(h3));
        xhp[lane + i * 32] = hv;
        xlp[lane + i * 32] = lv;
    }
}

// ============================================================
// 2) weight prep (fp16 single) + fused column constants
// ============================================================
__global__ void wprep_kernel(const float* __restrict__ Wq, const float* __restrict__ Wk,
                             const float* __restrict__ Wv, const float* __restrict__ Wo,
                             const float* __restrict__ gamma, const float* __restrict__ beta,
                             const float* __restrict__ bq, const float* __restrict__ bk,
                             const float* __restrict__ bv) {
    int w = blockIdx.z;
    const float* W = (w == 0) ? Wq : (w == 1) ? Wk : (w == 2) ? Wv : Wo;
    const float* b = (w == 0) ? bq : (w == 1) ? bk : bv;
    __shared__ float ts[64][65];
    int n0 = blockIdx.x * 64, k0 = blockIdx.y * 64;
    int tx = threadIdx.x & 63, ty = threadIdx.x >> 6;

    float s1 = 0.f, s2 = 0.f;
    #pragma unroll
    for (int l = 0; l < 16; l++) {
        int k = ty + l * 4;
        float wv = W[(size_t)(k0 + k) * Dm + n0 + tx];
        float g = (w < 3) ? gamma[k0 + k] : 1.f;
        float gw = g * wv;
        ts[k][tx] = gw;
        if (w < 3) { s1 += gw; s2 += beta[k0 + k] * wv; }
    }
    if (w < 3) {
        if (k0 == 0 && ty == 0) s2 += b[n0 + tx];
        atomicAdd(&g_c1[w * Dm + n0 + tx], s1);
        atomicAdd(&g_c2[w * Dm + n0 + tx], s2);
    }
    __syncthreads();
    __half* whp = g_wh + (size_t)w * Dm * Dm;
    #pragma unroll
    for (int l = 0; l < 16; l++) {
        int n = ty + l * 4;
        size_t o = (size_t)(n0 + n) * Dm + k0 + tx;
        whp[o] = __float2half_rn(ts[tx][n]);
    }
}

// ============================================================
// 3) GEMM common pieces (2-product: AhBh + AlBh)
// ============================================================
#define BM 128
#define BN 128
#define BK 32
#define KBYTES 64
#define STG   24576
#define NSTG  3
#define NT    32

#define SW(r, kc) ((uint32_t)((r) * KBYTES + ((((kc) ^ (((r) >> 1) & 3))) << 4)))

__device__ __forceinline__ void gemm_mainloop(
    uint32_t sbase, int tid, int lane, int warpM, int warpN,
    const __half* Ah, const __half* Al, const __half* Bh,
    int m0, int n0, float acc[4][4][4])
{
    auto prefetch = [&](int t) {
        int s = t % NSTG;
        int kb = t * BK;
        uint32_t st = sbase + s * STG;
        #pragma unroll
        for (int l = 0; l < 6; l++) {
            int e = tid + l * 256;
            int tile = e >> 9;
            int idx = e & 511;
            int r = idx >> 2, kc = idx & 3;
            const __half* p = (tile == 0) ? Ah : (tile == 1) ? Al : Bh;
            int rb = (tile < 2) ? m0 : n0;
            cp16(st + tile * 8192 + SW(r, kc), p + (size_t)(rb + r) * Dm + kb + kc * 8);
        }
    };

    prefetch(0); asm volatile("cp.async.commit_group;\n" ::: "memory");
    prefetch(1); asm volatile("cp.async.commit_group;\n" ::: "memory");

    for (int t = 0; t < NT; t++) {
        asm volatile("cp.async.wait_group 1;\n" ::: "memory");
        __syncthreads();
        if (t + 2 < NT) prefetch(t + 2);
        asm volatile("cp.async.commit_group;\n" ::: "memory");

        uint32_t st = sbase + (t % NSTG) * STG;
        uint32_t sAh = st, sAl = st + 8192, sBh = st + 16384;
        #pragma unroll
        for (int ks = 0; ks < 2; ks++) {
            uint32_t ah[4][4], al[4][4];
            #pragma unroll
            for (int mf = 0; mf < 4; mf++) {
                int row = warpM * 64 + mf * 16 + (lane & 15);
                int ch = ks * 2 + (lane >> 4);
                uint32_t sw = SW(row, ch);
                ldmA(sAh + sw, ah[mf][0], ah[mf][1], ah[mf][2], ah[mf][3]);
                ldmA(sAl + sw, al[mf][0], al[mf][1], al[mf][2], al[mf][3]);
            }
            #pragma unroll
            for (int nf2 = 0; nf2 < 2; nf2++) {
                int nrow = warpN * 32 + nf2 * 16 + (lane & 7) + ((lane >> 4) << 3);
                int ch = ks * 2 + ((lane >> 3) & 1);
                uint32_t swb = SW(nrow, ch);
                uint32_t r0, r1, r2, r3;
                ldmA(sBh + swb, r0, r1, r2, r3);
                #pragma unroll
                for (int mf = 0; mf < 4; mf++) {
                    mma16816(acc[mf][2*nf2],   ah[mf], r0, r1);
                    mma16816(acc[mf][2*nf2+1], ah[mf], r2, r3);
                    mma16816(acc[mf][2*nf2],   al[mf], r0, r1);
                    mma16816(acc[mf][2*nf2+1], al[mf], r2, r3);
                }
            }
        }
    }
}

// ---- merged Q/K/V projection GEMM ----
__global__ void __launch_bounds__(256, 2) gemm_qkv_kernel() {
    extern __shared__ char smem[];
    uint32_t sbase = smem_u32(smem);
    int tid = threadIdx.x, lane = tid & 31, wid = tid >> 5;
    int warpM = wid & 1, warpN = wid >> 1;
    int m0 = blockIdx.y * BM, n0 = blockIdx.x * BN;
    int z = blockIdx.z;                   // 0:Q 1:K 2:V

    const __half* Ah = (z == 0) ? g_xh_q : (z == 1) ? g_xh_k : g_xh_v;
    const __half* Al = (z == 0) ? g_xl_q : (z == 1) ? g_xl_k : g_xl_v;
    const __half* Bh = g_wh + (size_t)z * Dm * Dm;

    float acc[4][4][4] = {};
    gemm_mainloop(sbase, tid, lane, warpM, warpN, Ah, Al, Bh, m0, n0, acc);

    const float* c1 = g_c1 + z * Dm;
    const float* c2 = g_c2 + z * Dm;
    const float* rs = g_rs + z * NROWS;
    const float* mu = g_mu + z * NROWS;

    int groupID = lane >> 2, tg = lane & 3;
    #pragma unroll
    for (int mf = 0; mf < 4; mf++) {
        #pragma unroll
        for (int half = 0; half < 2; half++) {
            int r = m0 + warpM * 64 + mf * 16 + groupID + half * 8;
            float rsv = rs[r], muv = mu[r];
            int b = r >> 11, srow = r & 2047;
            #pragma unroll
            for (int nf = 0; nf < 4; nf++) {
                int c = n0 + warpN * 32 + nf * 8 + 2 * tg;
                float x0 = acc[mf][nf][2 * half + 0];
                float x1 = acc[mf][nf][2 * half + 1];
                float2 c1v = *(const float2*)(c1 + c);
                float2 c2v = *(const float2*)(c2 + c);
                float o0 = rsv * (x0 - muv * c1v.x) + c2v.x;
                float o1 = rsv * (x1 - muv * c1v.y) + c2v.y;
                if (z == 0) { o0 *= LOG2E; o1 *= LOG2E; }
                __half h0 = __float2half_rn(o0);
                __half h1 = __float2half_rn(o1);
                int hd = c >> 6, dd = c & 63;
                int bh = b * Hh + hd;
                if (z == 2) {
                    // V: single fp16, transposed [bh][d][s]
                    size_t a0 = ((size_t)(bh * DHd + dd)) * Ss + srow;
                    size_t a1 = ((size_t)(bh * DHd + dd + 1)) * Ss + srow;
                    g_vh[a0] = h0; g_vh[a1] = h1;
                } else if (z == 1) {
                    // K: single fp16, [bh][s][d]
                    size_t ad = ((size_t)(bh * Ss + srow)) * DHd + dd;
                    __half2 hp; hp.x = h0; hp.y = h1;
                    *(uint32_t*)(g_kh + ad) = *(uint32_t*)&hp;
                } else {
                    // Q: fp16 split
                    float l0 = o0 - __half2float(h0);
                    float l1 = o1 - __half2float(h1);
                    size_t ad = ((size_t)(bh * Ss + srow)) * DHd + dd;
                    __half2 hp; hp.x = h0; hp.y = h1;
                    *(uint32_t*)(g_qh + ad) = *(uint32_t*)&hp;
                    *(uint32_t*)(g_ql + ad) = packh2(l0, l1);
                }
            }
        }
    }
}

// ---- O projection GEMM: +bias +residual, fp32 out ----
__global__ void __launch_bounds__(256, 2) gemm_o_kernel(
    const float* __restrict__ bo, const float* __restrict__ resid,
    float* __restrict__ outF)
{
    extern __shared__ char smem[];
    uint32_t sbase = smem_u32(smem);
    int tid = threadIdx.x, lane = tid & 31, wid = tid >> 5;
    int warpM = wid & 1, warpN = wid >> 1;
    int m0 = blockIdx.y * BM, n0 = blockIdx.x * BN;

    float acc[4][4][4] = {};
    gemm_mainloop(sbase, tid, lane, warpM, warpN, g_aoh, g_aol,
                  g_wh + 3 * (size_t)Dm * Dm, m0, n0, acc);

    int groupID = lane >> 2, tg = lane & 3;
    #pragma unroll
    for (int mf = 0; mf < 4; mf++) {
        #pragma unroll
        for (int half = 0; half < 2; half++) {
            int r = m0 + warpM * 64 + mf * 16 + groupID + half * 8;
            #pragma unroll
            for (int nf = 0; nf < 4; nf++) {
                int c = n0 + warpN * 32 + nf * 8 + 2 * tg;
                float x0 = acc[mf][nf][2 * half + 0];
                float x1 = acc[mf][nf][2 * half + 1];
                float2 bo2 = *(const float2*)(bo + c);
                float2 q2  = *(const float2*)(resid + (size_t)r * Dm + c);
                float2 o;
                o.x = x0 + bo2.x + q2.x;
                o.y = x1 + bo2.y + q2.y;
                *(float2*)(outF + (size_t)r * Dm + c) = o;
            }
        }
    }
}

// ============================================================
// 4) tensor-core causal attention, fp16.
//    S: 2 products ((qh+ql)*Kh), K single fp16.
//    PV: 2 products ((ph+pl)*Vh), V single fp16.
// ============================================================
__device__ __forceinline__ void loadKV(int bh, int t, uint32_t base, int tid) {
    int kt = t * 64;
    const __half* khp = g_kh + ((size_t)bh * Ss + kt) * DHd;
    const __half* vhp = g_vh + (size_t)bh * DHd * Ss + kt;
    #pragma unroll
    for (int l = 0; l < 2; l++) {
        int e = tid + l * 256;
        int row = e >> 3, c = e & 7;
        uint32_t d = row * 128 + ((c ^ (row & 7)) << 4);
        cp16(base + d,        khp + (size_t)row * DHd + c * 8);
        cp16(base + 8192 + d, vhp + (size_t)row * Ss + c * 8);
    }
}

#define KVB 16384   // kh + vh per buffer

__global__ void __launch_bounds__(256, 2) attn_mma_kernel() {
    extern __shared__ char smraw[];
    uint32_t sb = smem_u32(smraw);
    const uint32_t QHs = sb;                 // qh 16K + ql 16K
    const uint32_t KVs = sb + 32768;         // 2 x 16K
    int tid = threadIdx.x, lane = tid & 31, wid = tid >> 5;
    int groupID = lane >> 2, tg = lane & 3;
    int bh = blockIdx.y;
    int mt = (int)(gridDim.x - 1) - (int)blockIdx.x;
    int q0 = mt * 128;
    int numt = 2 * mt + 2;

    const __half* qhp = g_qh + ((size_t)bh * Ss + q0) * DHd;
    const __half* qlp = g_ql + ((size_t)bh * Ss + q0) * DHd;

    #pragma unroll
    for (int l = 0; l < 4; l++) {
        int e = tid + l * 256;
        int row = e >> 3, c = e & 7;
        uint32_t d = row * 128 + ((c ^ (row & 7)) << 4);
        cp16(QHs + d,         qhp + (size_t)row * DHd + c * 8);
        cp16(QHs + 16384 + d, qlp + (size_t)row * DHd + c * 8);
    }
    asm volatile("cp.async.commit_group;\n" ::: "memory");
    loadKV(bh, 0, KVs, tid);
    asm volatile("cp.async.commit_group;\n" ::: "memory");
    asm volatile("cp.async.wait_group 1;\n" ::: "memory");
    __syncthreads();

    uint32_t qh[4][4];
    #pragma unroll
    for (int kf = 0; kf < 4; kf++) {
        int row = wid * 16 + (lane & 15);
        int ch = 2 * kf + (lane >> 4);
        uint32_t ad = QHs + row * 128 + ((ch ^ (row & 7)) << 4);
        ldmA(ad, qh[kf][0], qh[kf][1], qh[kf][2], qh[kf][3]);
    }

    float m[2] = {-1e30f, -1e30f}, lsum[2] = {0.f, 0.f};
    float oacc[8][4] = {};

    for (int t = 0; t < numt; t++) {
        if (t + 1 < numt) loadKV(bh, t + 1, KVs + ((t + 1) & 1) * KVB, tid);
        asm volatile("cp.async.commit_group;\n" ::: "memory");
        asm volatile("cp.async.wait_group 1;\n" ::: "memory");
        __syncthreads();
        uint32_t KB = KVs + (t & 1) * KVB;

        // ---- S = Q K^T (2 products: (qh+ql)*Kh) ----
        float sacc[8][4] = {};
        #pragma unroll
        for (int kf = 0; kf < 4; kf++) {
            uint32_t qlf[4];
            {
                int row = wid * 16 + (lane & 15);
                int ch = 2 * kf + (lane >> 4);
                uint32_t ad = QHs + 16384 + row * 128 + ((ch ^ (row & 7)) << 4);
                ldmA(ad, qlf[0], qlf[1], qlf[2], qlf[3]);
            }
            #pragma unroll
            for (int nf2 = 0; nf2 < 4; nf2++) {
                int row = nf2 * 16 + (lane & 15);
                int ch = 2 * kf + (lane >> 4);
                uint32_t sw = row * 128 + ((ch ^ (row & 7)) << 4);
                uint32_t r0, r1, r2, r3;
                ldmA(KB + sw, r0, r1, r2, r3);               // Kh
                mma16816(sacc[2 * nf2],     qh[kf], r0, r2);
                mma16816(sacc[2 * nf2 + 1], qh[kf], r1, r3);
                mma16816(sacc[2 * nf2],     qlf,    r0, r2);
                mma16816(sacc[2 * nf2 + 1], qlf,    r1, r3);
            }
        }

        if (t >= numt - 2) {
            int kt = t * 64;
            int qrow = q0 + wid * 16 + groupID;
            #pragma unroll
            for (int nf = 0; nf < 8; nf++) {
                int k0 = kt + nf * 8 + 2 * tg;
                if (k0     > qrow)     sacc[nf][0] = -1e30f;
                if (k0 + 1 > qrow)     sacc[nf][1] = -1e30f;
                if (k0     > qrow + 8) sacc[nf][2] = -1e30f;
                if (k0 + 1 > qrow + 8) sacc[nf][3] = -1e30f;
            }
        }

        float alpha[2];
        #pragma unroll
        for (int h = 0; h < 2; h++) {
            float rm = -1e30f;
            #pragma unroll
            for (int nf = 0; nf < 8; nf++)
                rm = fmaxf(rm, fmaxf(sacc[nf][2 * h], sacc[nf][2 * h + 1]));
            rm = fmaxf(rm, __shfl_xor_sync(0xffffffffu, rm, 1));
            rm = fmaxf(rm, __shfl_xor_sync(0xffffffffu, rm, 2));
            float mn = fmaxf(m[h], rm);
            alpha[h] = ex2f(m[h] - mn);
            m[h] = mn;
            float ls = 0.f;
            #pragma unroll
            for (int nf = 0; nf < 8; nf++) {
                float p0 = exp2poly(sacc[nf][2 * h]     - mn);
                float p1 = exp2poly(sacc[nf][2 * h + 1] - mn);
                sacc[nf][2 * h] = p0; sacc[nf][2 * h + 1] = p1;
                ls += p0 + p1;
            }
            lsum[h] = lsum[h] * alpha[h] + ls;
        }
        #pragma unroll
        for (int nd = 0; nd < 8; nd++) {
            oacc[nd][0] *= alpha[0]; oacc[nd][1] *= alpha[0];
            oacc[nd][2] *= alpha[1]; oacc[nd][3] *= alpha[1];
        }

        uint32_t pah[4][4], pal[4][4];
        #pragma unroll
        for (int kf = 0; kf < 4; kf++) {
            #pragma unroll
            for (int q = 0; q < 4; q++) {
                int nf = 2 * kf + (q >> 1);
                float x0 = sacc[nf][(q & 1) * 2], x1 = sacc[nf][(q & 1) * 2 + 1];
                __half h0 = __float2half_rn(x0), h1 = __float2half_rn(x1);
                __half2 hp; hp.x = h0; hp.y = h1;
                pah[kf][q] = *(uint32_t*)&hp;
                pal[kf][q] = packh2(x0 - __half2float(h0), x1 - __half2float(h1));
            }
        }

        // ---- O += P V (2 products: (ph+pl)*Vh) ----
        #pragma unroll
        for (int kf = 0; kf < 4; kf++) {
            #pragma unroll
            for (int nd2 = 0; nd2 < 4; nd2++) {
                int row = nd2 * 16 + (lane & 15);
                int ch = 2 * kf + (lane >> 4);
                uint32_t sw = row * 128 + ((ch ^ (row & 7)) << 4);
                uint32_t r0, r1, r2, r3;
                ldmA(KB + 8192 + sw, r0, r1, r2, r3);         // Vh
                mma16816(oacc[2 * nd2],     pah[kf], r0, r2);
                mma16816(oacc[2 * nd2 + 1], pah[kf], r1, r3);
                mma16816(oacc[2 * nd2],     pal[kf], r0, r2);
                mma16816(oacc[2 * nd2 + 1], pal[kf], r1, r3);
            }
        }
        __syncthreads();
    }

    #pragma unroll
    for (int h = 0; h < 2; h++) {
        lsum[h] += __shfl_xor_sync(0xffffffffu, lsum[h], 1);
        lsum[h] += __shfl_xor_sync(0xffffffffu, lsum[h], 2);
    }
    int b = bh >> 4, hd = bh & 15;
    #pragma unroll
    for (int h = 0; h < 2; h++) {
        int q = q0 + wid * 16 + groupID + 8 * h;
        float inv = 1.f / lsum[h];
        size_t rowbase = ((size_t)(b * Ss + q)) * Dm + hd * 64;
        #pragma unroll
        for (int nd = 0; nd < 8; nd++) {
            float x0 = oacc[nd][2 * h] * inv, x1 = oacc[nd][2 * h + 1] * inv;
            __half h0 = __float2half_rn(x0), h1 = __float2half_rn(x1);
            __half2 hp; hp.x = h0; hp.y = h1;
            size_t ad = rowbase + nd * 8 + 2 * tg;
            *(uint32_t*)(g_aoh + ad) = *(uint32_t*)&hp;
            *(uint32_t*)(g_aol + ad) = packh2(x0 - __half2float(h0),
                                              x1 - __half2float(h1));
        }
    }
}

// ============================================================
// launch
// ============================================================
extern "C" void kernel_launch(void* const* d_in, const int* in_sizes, int n_in,
                              void* d_out, int out_size) {
    const float* Q     = (const float*)d_in[0];
    const float* K     = (const float*)d_in[1];
    const float* V     = (const float*)d_in[2];
    const float* Wq    = (const float*)d_in[3];
    const float* bq    = (const float*)d_in[4];
    const float* Wk    = (const float*)d_in[5];
    const float* bk    = (const float*)d_in[6];
    const float* Wv    = (const float*)d_in[7];
    const float* bv    = (const float*)d_in[8];
    const float* Wo    = (const float*)d_in[9];
    const float* bo    = (const float*)d_in[10];
    const float* gamma = (const float*)d_in[11];
    const float* beta  = (const float*)d_in[12];
    float* out = (float*)d_out;

    float *c1_p, *c2_p;
    cudaGetSymbolAddress((void**)&c1_p, g_c1);
    cudaGetSymbolAddress((void**)&c2_p, g_c2);

    cudaMemsetAsync(c1_p, 0, 3 * Dm * sizeof(float));
    cudaMemsetAsync(c2_p, 0, 3 * Dm * sizeof(float));
    ln_split_kernel<<<3 * NROWS / 8, 256>>>(Q, K, V);
    wprep_kernel<<<dim3(16, 16, 4), 256>>>(Wq, Wk, Wv, Wo, gamma, beta, bq, bk, bv);

    size_t gsmem = NSTG * STG;   // 72K
    cudaFuncSetAttribute(gemm_qkv_kernel, cudaFuncAttributeMaxDynamicSharedMemorySize, (int)gsmem);
    cudaFuncSetAttribute(gemm_o_kernel,   cudaFuncAttributeMaxDynamicSharedMemorySize, (int)gsmem);

    gemm_qkv_kernel<<<dim3(Dm / BN, NROWS / BM, 3), 256, gsmem>>>();

    size_t asmem = 32768 + 2 * KVB;   // 65536
    cudaFuncSetAttribute(attn_mma_kernel, cudaFuncAttributeMaxDynamicSharedMemorySize, (int)asmem);
    attn_mma_kernel<<<dim3(16, 64), 256, asmem>>>();

    gemm_o_kernel<<<dim3(Dm / BN, NROWS / BM), 256, gsmem>>>(bo, Q, out);
}

// round 15
// speedup vs baseline: 1.6168x; 1.1516x over previous
#include <cuda_runtime.h>
#include <cuda_fp16.h>
#include <cstdint>
#include <math.h>

#define Dm 1024
#define Hh 16
#define DHd 64
#define Bb 4
#define Ss 2048
#define NROWS (Bb*Ss)   // 8192
#define LOG2E 1.4426950408889634f

// ---------------- static device scratch ----------------
__device__ float g_mu[3*NROWS];
__device__ float g_rs[3*NROWS];
__device__ __half g_xh_q[NROWS*Dm]; __device__ __half g_xl_q[NROWS*Dm];
__device__ __half g_xh_k[NROWS*Dm]; __device__ __half g_xl_k[NROWS*Dm];
__device__ __half g_xh_v[NROWS*Dm]; __device__ __half g_xl_v[NROWS*Dm];
__device__ __half g_wh[4*Dm*Dm];
__device__ float g_c1[3*Dm];
__device__ float g_c2[3*Dm];
__device__ __half g_qh[NROWS*Dm], g_ql[NROWS*Dm];  // [bh][s][d], *LOG2E
__device__ __half g_kh[NROWS*Dm];                  // [bh][s][d], single fp16
__device__ __half g_vh[NROWS*Dm];                  // [bh][d][s], single fp16
__device__ __half g_aoh[NROWS*Dm];                 // [b*s][D], single fp16

// ---------------- helpers ----------------
__device__ __forceinline__ uint32_t smem_u32(const void* p) {
    uint32_t a;
    asm("{ .reg .u64 t; cvta.to.shared.u64 t, %1; cvt.u32.u64 %0, t; }" : "=r"(a) : "l"(p));
    return a;
}
__device__ __forceinline__ void cp16(uint32_t s, const void* g) {
    asm volatile("cp.async.cg.shared.global [%0], [%1], 16;\n" :: "r"(s), "l"(g));
}
__device__ __forceinline__ void ldmA(uint32_t addr, uint32_t& r0, uint32_t& r1,
                                     uint32_t& r2, uint32_t& r3) {
    asm volatile("ldmatrix.sync.aligned.m8n8.x4.shared.b16 {%0,%1,%2,%3}, [%4];"
                 : "=r"(r0), "=r"(r1), "=r"(r2), "=r"(r3) : "r"(addr));
}
__device__ __forceinline__ void mma16816(float* c, const uint32_t* a,
                                         uint32_t b0, uint32_t b1) {
    asm volatile("mma.sync.aligned.m16n8k16.row.col.f32.f16.f16.f32 "
                 "{%0,%1,%2,%3}, {%4,%5,%6,%7}, {%8,%9}, {%0,%1,%2,%3};"
                 : "+f"(c[0]), "+f"(c[1]), "+f"(c[2]), "+f"(c[3])
                 : "r"(a[0]), "r"(a[1]), "r"(a[2]), "r"(a[3]), "r"(b0), "r"(b1));
}
__device__ __forceinline__ float ex2f(float x) {
    float r; asm("ex2.approx.f32 %0, %1;" : "=f"(r) : "f"(x)); return r;
}
__device__ __forceinline__ float exp2poly(float z) {
    z = fmaxf(z, -126.f);
    float t = z + 12582912.f;
    int n = __float_as_int(t) - 0x4B400000;
    float f = z - (t - 12582912.f);
    float p = fmaf(0.0096181291f, f, 0.055504109f);
    p = fmaf(p, f, 0.24022651f);
    p = fmaf(p, f, 0.69314718f);
    p = fmaf(p, f, 1.0f);
    return __int_as_float(__float_as_int(p) + (n << 23));
}
__device__ __forceinline__ uint32_t packh2(float a, float b) {
    __half2 t;
    t.x = __float2half_rn(a);
    t.y = __float2half_rn(b);
    return *(uint32_t*)&t;
}

// ============================================================
// 1) LN stats + fp16 hi/lo split — warp per row
// ============================================================
__global__ void ln_split_kernel(const float* __restrict__ Q,
                                const float* __restrict__ K,
                                const float* __restrict__ V) {
    int wid = threadIdx.x >> 5, lane = threadIdx.x & 31;
    int row = blockIdx.x * 8 + wid;
    int which = row >> 13;
    int r = row & (NROWS - 1);
    const float* x; __half* xh; __half* xl;
    if (which == 0)      { x = Q; xh = g_xh_q; xl = g_xl_q; }
    else if (which == 1) { x = K; xh = g_xh_k; xl = g_xl_k; }
    else                 { x = V; xh = g_xh_v; xl = g_xl_v; }
    const float4* xr = (const float4*)(x + (size_t)r * Dm);

    float4 v[8];
    float s = 0.f, s2 = 0.f;
    #pragma unroll
    for (int i = 0; i < 8; i++) {
        v[i] = xr[lane + i * 32];
        s  += v[i].x + v[i].y + v[i].z + v[i].w;
        s2 += v[i].x * v[i].x + v[i].y * v[i].y + v[i].z * v[i].z + v[i].w * v[i].w;
    }
    #pragma unroll
    for (int o = 16; o > 0; o >>= 1) {
        s  += __shfl_xor_sync(0xffffffffu, s,  o);
        s2 += __shfl_xor_sync(0xffffffffu, s2, o);
    }
    float muv = s / (float)Dm;
    float var = s2 / (float)Dm - muv * muv;
    if (lane == 0) {
        g_mu[row] = muv;
        g_rs[row] = rsqrtf(var + 1e-6f);
    }
    uint2* xhp = (uint2*)(xh + (size_t)r * Dm);
    uint2* xlp = (uint2*)(xl + (size_t)r * Dm);
    #pragma unroll
    for (int i = 0; i < 8; i++) {
        __half h0 = __float2half_rn(v[i].x), h1 = __float2half_rn(v[i].y);
        __half h2 = __float2half_rn(v[i].z), h3 = __float2half_rn(v[i].w);
        uint2 hv, lv;
        __half2 p01, p23;
        p01.x = h0; p01.y = h1; p23.x = h2; p23.y = h3;
        hv.x = *(uint32_t*)&p01; hv.y = *(uint32_t*)&p23;
        lv.x = packh2(v[i].x - __half2float(h0), v[i].y - __half2float(h1));
        lv.y = packh2(v[i].z - __half2float(h2), v[i].w - __half2float(h3));
        xhp[lane + i * 32] = hv;
        xlp[lane + i * 32] = lv;
    }
}

// ============================================================
// 2) weight prep (fp16 single) + fused column constants
// ============================================================
__global__ void wprep_kernel(const float* __restrict__ Wq, const float* __restrict__ Wk,
                             const float* __restrict__ Wv, const float* __restrict__ Wo,
                             const float* __restrict__ gamma, const float* __restrict__ beta,
                             const float* __restrict__ bq, const float* __restrict__ bk,
                             const float* __restrict__ bv) {
    int w = blockIdx.z;
    const float* W = (w == 0) ? Wq : (w == 1) ? Wk : (w == 2) ? Wv : Wo;
    const float* b = (w == 0) ? bq : (w == 1) ? bk : bv;
    __shared__ float ts[64][65];
    int n0 = blockIdx.x * 64, k0 = blockIdx.y * 64;
    int tx = threadIdx.x & 63, ty = threadIdx.x >> 6;

    float s1 = 0.f, s2 = 0.f;
    #pragma unroll
    for (int l = 0; l < 16; l++) {
        int k = ty + l * 4;
        float wv = W[(size_t)(k0 + k) * Dm + n0 + tx];
        float g = (w < 3) ? gamma[k0 + k] : 1.f;
        float gw = g * wv;
        ts[k][tx] = gw;
        if (w < 3) { s1 += gw; s2 += beta[k0 + k] * wv; }
    }
    if (w < 3) {
        if (k0 == 0 && ty == 0) s2 += b[n0 + tx];
        atomicAdd(&g_c1[w * Dm + n0 + tx], s1);
        atomicAdd(&g_c2[w * Dm + n0 + tx], s2);
    }
    __syncthreads();
    __half* whp = g_wh + (size_t)w * Dm * Dm;
    #pragma unroll
    for (int l = 0; l < 16; l++) {
        int n = ty + l * 4;
        size_t o = (size_t)(n0 + n) * Dm + k0 + tx;
        whp[o] = __float2half_rn(ts[tx][n]);
    }
}

// ============================================================
// 3) GEMM common pieces. NPROD=2: AhBh+AlBh. NPROD=1: AhBh only.
// ============================================================
#define BM 128
#define BN 128
#define BK 32
#define KBYTES 64
#define NSTG  3
#define NT    32

#define SW(r, kc) ((uint32_t)((r) * KBYTES + ((((kc) ^ (((r) >> 1) & 3))) << 4)))

template<int NPROD>
__device__ __forceinline__ void gemm_mainloop(
    uint32_t sbase, int tid, int lane, int warpM, int warpN,
    const __half* Ah, const __half* Al, const __half* Bh,
    int m0, int n0, float acc[4][4][4])
{
    const int STG_T = (NPROD + 1) * 8192;
    auto prefetch = [&](int t) {
        int s = t % NSTG;
        int kb = t * BK;
        uint32_t st = sbase + s * STG_T;
        #pragma unroll
        for (int l = 0; l < (NPROD + 1) * 2; l++) {
            int e = tid + l * 256;
            int tile = e >> 9;              // 0:Ah [1:Al] last:Bh
            int idx = e & 511;
            int r = idx >> 2, kc = idx & 3;
            const __half* p = (tile == 0) ? Ah : (NPROD == 2 && tile == 1) ? Al : Bh;
            int rb = (tile < NPROD) ? m0 : n0;
            cp16(st + tile * 8192 + SW(r, kc), p + (size_t)(rb + r) * Dm + kb + kc * 8);
        }
    };

    prefetch(0); asm volatile("cp.async.commit_group;\n" ::: "memory");
    prefetch(1); asm volatile("cp.async.commit_group;\n" ::: "memory");

    for (int t = 0; t < NT; t++) {
        asm volatile("cp.async.wait_group 1;\n" ::: "memory");
        __syncthreads();
        if (t + 2 < NT) prefetch(t + 2);
        asm volatile("cp.async.commit_group;\n" ::: "memory");

        uint32_t st = sbase + (t % NSTG) * STG_T;
        uint32_t sAh = st, sAl = st + 8192, sBh = st + NPROD * 8192;
        #pragma unroll
        for (int ks = 0; ks < 2; ks++) {
            uint32_t ah[4][4], al[4][4];
            #pragma unroll
            for (int mf = 0; mf < 4; mf++) {
                int row = warpM * 64 + mf * 16 + (lane & 15);
                int ch = ks * 2 + (lane >> 4);
                uint32_t sw = SW(row, ch);
                ldmA(sAh + sw, ah[mf][0], ah[mf][1], ah[mf][2], ah[mf][3]);
                if (NPROD == 2)
                    ldmA(sAl + sw, al[mf][0], al[mf][1], al[mf][2], al[mf][3]);
            }
            #pragma unroll
            for (int nf2 = 0; nf2 < 2; nf2++) {
                int nrow = warpN * 32 + nf2 * 16 + (lane & 7) + ((lane >> 4) << 3);
                int ch = ks * 2 + ((lane >> 3) & 1);
                uint32_t swb = SW(nrow, ch);
                uint32_t r0, r1, r2, r3;
                ldmA(sBh + swb, r0, r1, r2, r3);
                #pragma unroll
                for (int mf = 0; mf < 4; mf++) {
                    mma16816(acc[mf][2*nf2],   ah[mf], r0, r1);
                    mma16816(acc[mf][2*nf2+1], ah[mf], r2, r3);
                    if (NPROD == 2) {
                        mma16816(acc[mf][2*nf2],   al[mf], r0, r1);
                        mma16816(acc[mf][2*nf2+1], al[mf], r2, r3);
                    }
                }
            }
        }
    }
}

// ---- merged Q/K/V projection GEMM (2-product) ----
__global__ void __launch_bounds__(256, 2) gemm_qkv_kernel() {
    extern __shared__ char smem[];
    uint32_t sbase = smem_u32(smem);
    int tid = threadIdx.x, lane = tid & 31, wid = tid >> 5;
    int warpM = wid & 1, warpN = wid >> 1;
    int m0 = blockIdx.y * BM, n0 = blockIdx.x * BN;
    int z = blockIdx.z;                   // 0:Q 1:K 2:V

    const __half* Ah = (z == 0) ? g_xh_q : (z == 1) ? g_xh_k : g_xh_v;
    const __half* Al = (z == 0) ? g_xl_q : (z == 1) ? g_xl_k : g_xl_v;
    const __half* Bh = g_wh + (size_t)z * Dm * Dm;

    float acc[4][4][4] = {};
    gemm_mainloop<2>(sbase, tid, lane, warpM, warpN, Ah, Al, Bh, m0, n0, acc);

    const float* c1 = g_c1 + z * Dm;
    const float* c2 = g_c2 + z * Dm;
    const float* rs = g_rs + z * NROWS;
    const float* mu = g_mu + z * NROWS;

    int groupID = lane >> 2, tg = lane & 3;
    #pragma unroll
    for (int mf = 0; mf < 4; mf++) {
        #pragma unroll
        for (int half = 0; half < 2; half++) {
            int r = m0 + warpM * 64 + mf * 16 + groupID + half * 8;
            float rsv = rs[r], muv = mu[r];
            int b = r >> 11, srow = r & 2047;
            #pragma unroll
            for (int nf = 0; nf < 4; nf++) {
                int c = n0 + warpN * 32 + nf * 8 + 2 * tg;
                float x0 = acc[mf][nf][2 * half + 0];
                float x1 = acc[mf][nf][2 * half + 1];
                float2 c1v = *(const float2*)(c1 + c);
                float2 c2v = *(const float2*)(c2 + c);
                float o0 = rsv * (x0 - muv * c1v.x) + c2v.x;
                float o1 = rsv * (x1 - muv * c1v.y) + c2v.y;
                if (z == 0) { o0 *= LOG2E; o1 *= LOG2E; }
                __half h0 = __float2half_rn(o0);
                __half h1 = __float2half_rn(o1);
                int hd = c >> 6, dd = c & 63;
                int bh = b * Hh + hd;
                if (z == 2) {
                    size_t a0 = ((size_t)(bh * DHd + dd)) * Ss + srow;
                    size_t a1 = ((size_t)(bh * DHd + dd + 1)) * Ss + srow;
                    g_vh[a0] = h0; g_vh[a1] = h1;
                } else if (z == 1) {
                    size_t ad = ((size_t)(bh * Ss + srow)) * DHd + dd;
                    __half2 hp; hp.x = h0; hp.y = h1;
                    *(uint32_t*)(g_kh + ad) = *(uint32_t*)&hp;
                } else {
                    float l0 = o0 - __half2float(h0);
                    float l1 = o1 - __half2float(h1);
                    size_t ad = ((size_t)(bh * Ss + srow)) * DHd + dd;
                    __half2 hp; hp.x = h0; hp.y = h1;
                    *(uint32_t*)(g_qh + ad) = *(uint32_t*)&hp;
                    *(uint32_t*)(g_ql + ad) = packh2(l0, l1);
                }
            }
        }
    }
}

// ---- O projection GEMM (1-product): +bias +residual, fp32 out ----
__global__ void __launch_bounds__(256, 2) gemm_o_kernel(
    const float* __restrict__ bo, const float* __restrict__ resid,
    float* __restrict__ outF)
{
    extern __shared__ char smem[];
    uint32_t sbase = smem_u32(smem);
    int tid = threadIdx.x, lane = tid & 31, wid = tid >> 5;
    int warpM = wid & 1, warpN = wid >> 1;
    int m0 = blockIdx.y * BM, n0 = blockIdx.x * BN;

    float acc[4][4][4] = {};
    gemm_mainloop<1>(sbase, tid, lane, warpM, warpN, g_aoh, nullptr,
                     g_wh + 3 * (size_t)Dm * Dm, m0, n0, acc);

    int groupID = lane >> 2, tg = lane & 3;
    #pragma unroll
    for (int mf = 0; mf < 4; mf++) {
        #pragma unroll
        for (int half = 0; half < 2; half++) {
            int r = m0 + warpM * 64 + mf * 16 + groupID + half * 8;
            #pragma unroll
            for (int nf = 0; nf < 4; nf++) {
                int c = n0 + warpN * 32 + nf * 8 + 2 * tg;
                float x0 = acc[mf][nf][2 * half + 0];
                float x1 = acc[mf][nf][2 * half + 1];
                float2 bo2 = *(const float2*)(bo + c);
                float2 q2  = *(const float2*)(resid + (size_t)r * Dm + c);
                float2 o;
                o.x = x0 + bo2.x + q2.x;
                o.y = x1 + bo2.y + q2.y;
                *(float2*)(outF + (size_t)r * Dm + c) = o;
            }
        }
    }
}

// ============================================================
// 4) tensor-core causal attention, fp16.
//    S: 2 products ((qh+ql)*Kh).  PV: 1 product (p_fp16 * Vh).
// ============================================================
__device__ __forceinline__ void loadKV(int bh, int t, uint32_t base, int tid) {
    int kt = t * 64;
    const __half* khp = g_kh + ((size_t)bh * Ss + kt) * DHd;
    const __half* vhp = g_vh + (size_t)bh * DHd * Ss + kt;
    #pragma unroll
    for (int l = 0; l < 2; l++) {
        int e = tid + l * 256;
        int row = e >> 3, c = e & 7;
        uint32_t d = row * 128 + ((c ^ (row & 7)) << 4);
        cp16(base + d,        khp + (size_t)row * DHd + c * 8);
        cp16(base + 8192 + d, vhp + (size_t)row * Ss + c * 8);
    }
}

#define KVB 16384   // kh + vh per buffer

__global__ void __launch_bounds__(256, 2) attn_mma_kernel() {
    extern __shared__ char smraw[];
    uint32_t sb = smem_u32(smraw);
    const uint32_t QHs = sb;                 // qh 16K + ql 16K
    const uint32_t KVs = sb + 32768;         // 2 x 16K
    int tid = threadIdx.x, lane = tid & 31, wid = tid >> 5;
    int groupID = lane >> 2, tg = lane & 3;
    int bh = blockIdx.y;
    int mt = (int)(gridDim.x - 1) - (int)blockIdx.x;
    int q0 = mt * 128;
    int numt = 2 * mt + 2;

    const __half* qhp = g_qh + ((size_t)bh * Ss + q0) * DHd;
    const __half* qlp = g_ql + ((size_t)bh * Ss + q0) * DHd;

    #pragma unroll
    for (int l = 0; l < 4; l++) {
        int e = tid + l * 256;
        int row = e >> 3, c = e & 7;
        uint32_t d = row * 128 + ((c ^ (row & 7)) << 4);
        cp16(QHs + d,         qhp + (size_t)row * DHd + c * 8);
        cp16(QHs + 16384 + d, qlp + (size_t)row * DHd + c * 8);
    }
    asm volatile("cp.async.commit_group;\n" ::: "memory");
    loadKV(bh, 0, KVs, tid);
    asm volatile("cp.async.commit_group;\n" ::: "memory");
    asm volatile("cp.async.wait_group 1;\n" ::: "memory");
    __syncthreads();

    uint32_t qh[4][4];
    #pragma unroll
    for (int kf = 0; kf < 4; kf++) {
        int row = wid * 16 + (lane & 15);
        int ch = 2 * kf + (lane >> 4);
        uint32_t ad = QHs + row * 128 + ((ch ^ (row & 7)) << 4);
        ldmA(ad, qh[kf][0], qh[kf][1], qh[kf][2], qh[kf][3]);
    }

    float m[2] = {-1e30f, -1e30f}, lsum[2] = {0.f, 0.f};
    float oacc[8][4] = {};

    for (int t = 0; t < numt; t++) {
        if (t + 1 < numt) loadKV(bh, t + 1, KVs + ((t + 1) & 1) * KVB, tid);
        asm volatile("cp.async.commit_group;\n" ::: "memory");
        asm volatile("cp.async.wait_group 1;\n" ::: "memory");
        __syncthreads();
        uint32_t KB = KVs + (t & 1) * KVB;

        // ---- S = Q K^T (2 products: (qh+ql)*Kh) ----
        float sacc[8][4] = {};
        #pragma unroll
        for (int kf = 0; kf < 4; kf++) {
            uint32_t qlf[4];
            {
                int row = wid * 16 + (lane & 15);
                int ch = 2 * kf + (lane >> 4);
                uint32_t ad = QHs + 16384 + row * 128 + ((ch ^ (row & 7)) << 4);
                ldmA(ad, qlf[0], qlf[1], qlf[2], qlf[3]);
            }
            #pragma unroll
            for (int nf2 = 0; nf2 < 4; nf2++) {
                int row = nf2 * 16 + (lane & 15);
                int ch = 2 * kf + (lane >> 4);
                uint32_t sw = row * 128 + ((ch ^ (row & 7)) << 4);
                uint32_t r0, r1, r2, r3;
                ldmA(KB + sw, r0, r1, r2, r3);               // Kh
                mma16816(sacc[2 * nf2],     qh[kf], r0, r2);
                mma16816(sacc[2 * nf2 + 1], qh[kf], r1, r3);
                mma16816(sacc[2 * nf2],     qlf,    r0, r2);
                mma16816(sacc[2 * nf2 + 1], qlf,    r1, r3);
            }
        }

        if (t >= numt - 2) {
            int kt = t * 64;
            int qrow = q0 + wid * 16 + groupID;
            #pragma unroll
            for (int nf = 0; nf < 8; nf++) {
                int k0 = kt + nf * 8 + 2 * tg;
                if (k0     > qrow)     sacc[nf][0] = -1e30f;
                if (k0 + 1 > qrow)     sacc[nf][1] = -1e30f;
                if (k0     > qrow + 8) sacc[nf][2] = -1e30f;
                if (k0 + 1 > qrow + 8) sacc[nf][3] = -1e30f;
            }
        }

        float alpha[2];
        #pragma unroll
        for (int h = 0; h < 2; h++) {
            float rm = -1e30f;
            #pragma unroll
            for (int nf = 0; nf < 8; nf++)
                rm = fmaxf(rm, fmaxf(sacc[nf][2 * h], sacc[nf][2 * h + 1]));
            rm = fmaxf(rm, __shfl_xor_sync(0xffffffffu, rm, 1));
            rm = fmaxf(rm, __shfl_xor_sync(0xffffffffu, rm, 2));
            float mn = fmaxf(m[h], rm);
            alpha[h] = ex2f(m[h] - mn);
            m[h] = mn;
            float ls = 0.f;
            #pragma unroll
            for (int nf = 0; nf < 8; nf++) {
                float p0 = exp2poly(sacc[nf][2 * h]     - mn);
                float p1 = exp2poly(sacc[nf][2 * h + 1] - mn);
                sacc[nf][2 * h] = p0; sacc[nf][2 * h + 1] = p1;
                ls += p0 + p1;
            }
            lsum[h] = lsum[h] * alpha[h] + ls;
        }
        #pragma unroll
        for (int nd = 0; nd < 8; nd++) {
            oacc[nd][0] *= alpha[0]; oacc[nd][1] *= alpha[0];
            oacc[nd][2] *= alpha[1]; oacc[nd][3] *= alpha[1];
        }

        uint32_t pah[4][4];
        #pragma unroll
        for (int kf = 0; kf < 4; kf++) {
            #pragma unroll
            for (int q = 0; q < 4; q++) {
                int nf = 2 * kf + (q >> 1);
                pah[kf][q] = packh2(sacc[nf][(q & 1) * 2], sacc[nf][(q & 1) * 2 + 1]);
            }
        }

        // ---- O += P V (1 product: p_fp16 * Vh) ----
        #pragma unroll
        for (int kf = 0; kf < 4; kf++) {
            #pragma unroll
            for (int nd2 = 0; nd2 < 4; nd2++) {
                int row = nd2 * 16 + (lane & 15);
                int ch = 2 * kf + (lane >> 4);
                uint32_t sw = row * 128 + ((ch ^ (row & 7)) << 4);
                uint32_t r0, r1, r2, r3;
                ldmA(KB + 8192 + sw, r0, r1, r2, r3);         // Vh
                mma16816(oacc[2 * nd2],     pah[kf], r0, r2);
                mma16816(oacc[2 * nd2 + 1], pah[kf], r1, r3);
            }
        }
        __syncthreads();
    }

    #pragma unroll
    for (int h = 0; h < 2; h++) {
        lsum[h] += __shfl_xor_sync(0xffffffffu, lsum[h], 1);
        lsum[h] += __shfl_xor_sync(0xffffffffu, lsum[h], 2);
    }
    int b = bh >> 4, hd = bh & 15;
    #pragma unroll
    for (int h = 0; h < 2; h++) {
        int q = q0 + wid * 16 + groupID + 8 * h;
        float inv = 1.f / lsum[h];
        size_t rowbase = ((size_t)(b * Ss + q)) * Dm + hd * 64;
        #pragma unroll
        for (int nd = 0; nd < 8; nd++) {
            float x0 = oacc[nd][2 * h] * inv, x1 = oacc[nd][2 * h + 1] * inv;
            size_t ad = rowbase + nd * 8 + 2 * tg;
            *(uint32_t*)(g_aoh + ad) = packh2(x0, x1);
        }
    }
}

// ============================================================
// launch
// ============================================================
extern "C" void kernel_launch(void* const* d_in, const int* in_sizes, int n_in,
                              void* d_out, int out_size) {
    const float* Q     = (const float*)d_in[0];
    const float* K     = (const float*)d_in[1];
    const float* V     = (const float*)d_in[2];
    const float* Wq    = (const float*)d_in[3];
    const float* bq    = (const float*)d_in[4];
    const float* Wk    = (const float*)d_in[5];
    const float* bk    = (const float*)d_in[6];
    const float* Wv    = (const float*)d_in[7];
    const float* bv    = (const float*)d_in[8];
    const float* Wo    = (const float*)d_in[9];
    const float* bo    = (const float*)d_in[10];
    const float* gamma = (const float*)d_in[11];
    const float* beta  = (const float*)d_in[12];
    float* out = (float*)d_out;

    float *c1_p, *c2_p;
    cudaGetSymbolAddress((void**)&c1_p, g_c1);
    cudaGetSymbolAddress((void**)&c2_p, g_c2);

    cudaMemsetAsync(c1_p, 0, 3 * Dm * sizeof(float));
    cudaMemsetAsync(c2_p, 0, 3 * Dm * sizeof(float));
    ln_split_kernel<<<3 * NROWS / 8, 256>>>(Q, K, V);
    wprep_kernel<<<dim3(16, 16, 4), 256>>>(Wq, Wk, Wv, Wo, gamma, beta, bq, bk, bv);

    size_t qkv_smem = NSTG * 3 * 8192;   // 72K
    size_t o_smem   = NSTG * 2 * 8192;   // 48K
    cudaFuncSetAttribute(gemm_qkv_kernel, cudaFuncAttributeMaxDynamicSharedMemorySize, (int)qkv_smem);
    cudaFuncSetAttribute(gemm_o_kernel,   cudaFuncAttributeMaxDynamicSharedMemorySize, (int)o_smem);

    gemm_qkv_kernel<<<dim3(Dm / BN, NROWS / BM, 3), 256, qkv_smem>>>();

    size_t asmem = 32768 + 2 * KVB;   // 65536
    cudaFuncSetAttribute(attn_mma_kernel, cudaFuncAttributeMaxDynamicSharedMemorySize, (int)asmem);
    attn_mma_kernel<<<dim3(16, 64), 256, asmem>>>();

    gemm_o_kernel<<<dim3(Dm / BN, NROWS / BM), 256, o_smem>>>(bo, Q, out);
}

// round 16
// speedup vs baseline: 1.7654x; 1.0919x over previous
#include <cuda_runtime.h>
#include <cuda_fp16.h>
#include <cstdint>
#include <math.h>

#define Dm 1024
#define Hh 16
#define DHd 64
#define Bb 4
#define Ss 2048
#define NROWS (Bb*Ss)   // 8192
#define LOG2E 1.4426950408889634f

// ---------------- static device scratch ----------------
__device__ float g_mu[3*NROWS];
__device__ float g_rs[3*NROWS];
__device__ __half g_xh_q[NROWS*Dm]; __device__ __half g_xl_q[NROWS*Dm];
__device__ __half g_xh_k[NROWS*Dm]; __device__ __half g_xl_k[NROWS*Dm];
__device__ __half g_xh_v[NROWS*Dm];                 // V x-side single fp16
__device__ __half g_wh[4*Dm*Dm];
__device__ float g_c1[3*Dm];
__device__ float g_c2[3*Dm];
__device__ __half g_qh[NROWS*Dm], g_ql[NROWS*Dm];  // [bh][s][d], *LOG2E
__device__ __half g_kh[NROWS*Dm];                  // [bh][s][d], single fp16
__device__ __half g_vh[NROWS*Dm];                  // [bh][d][s], single fp16
__device__ __half g_aoh[NROWS*Dm];                 // [b*s][D], single fp16

// ---------------- helpers ----------------
__device__ __forceinline__ uint32_t smem_u32(const void* p) {
    uint32_t a;
    asm("{ .reg .u64 t; cvta.to.shared.u64 t, %1; cvt.u32.u64 %0, t; }" : "=r"(a) : "l"(p));
    return a;
}
__device__ __forceinline__ void cp16(uint32_t s, const void* g) {
    asm volatile("cp.async.cg.shared.global [%0], [%1], 16;\n" :: "r"(s), "l"(g));
}
__device__ __forceinline__ void ldmA(uint32_t addr, uint32_t& r0, uint32_t& r1,
                                     uint32_t& r2, uint32_t& r3) {
    asm volatile("ldmatrix.sync.aligned.m8n8.x4.shared.b16 {%0,%1,%2,%3}, [%4];"
                 : "=r"(r0), "=r"(r1), "=r"(r2), "=r"(r3) : "r"(addr));
}
__device__ __forceinline__ void mma16816(float* c, const uint32_t* a,
                                         uint32_t b0, uint32_t b1) {
    asm volatile("mma.sync.aligned.m16n8k16.row.col.f32.f16.f16.f32 "
                 "{%0,%1,%2,%3}, {%4,%5,%6,%7}, {%8,%9}, {%0,%1,%2,%3};"
                 : "+f"(c[0]), "+f"(c[1]), "+f"(c[2]), "+f"(c[3])
                 : "r"(a[0]), "r"(a[1]), "r"(a[2]), "r"(a[3]), "r"(b0), "r"(b1));
}
__device__ __forceinline__ float ex2f(float x) {
    float r; asm("ex2.approx.f32 %0, %1;" : "=f"(r) : "f"(x)); return r;
}
__device__ __forceinline__ float exp2poly(float z) {
    z = fmaxf(z, -126.f);
    float t = z + 12582912.f;
    int n = __float_as_int(t) - 0x4B400000;
    float f = z - (t - 12582912.f);
    float p = fmaf(0.0096181291f, f, 0.055504109f);
    p = fmaf(p, f, 0.24022651f);
    p = fmaf(p, f, 0.69314718f);
    p = fmaf(p, f, 1.0f);
    return __int_as_float(__float_as_int(p) + (n << 23));
}
__device__ __forceinline__ uint32_t packh2(float a, float b) {
    __half2 t;
    t.x = __float2half_rn(a);
    t.y = __float2half_rn(b);
    return *(uint32_t*)&t;
}

// ============================================================
// 1) LN stats + fp16 split — warp per row. V gets hi-only.
// ============================================================
__global__ void ln_split_kernel(const float* __restrict__ Q,
                                const float* __restrict__ K,
                                const float* __restrict__ V) {
    int wid = threadIdx.x >> 5, lane = threadIdx.x & 31;
    int row = blockIdx.x * 8 + wid;
    int which = row >> 13;
    int r = row & (NROWS - 1);
    const float* x; __half* xh; __half* xl;
    if (which == 0)      { x = Q; xh = g_xh_q; xl = g_xl_q; }
    else if (which == 1) { x = K; xh = g_xh_k; xl = g_xl_k; }
    else                 { x = V; xh = g_xh_v; xl = nullptr; }
    const float4* xr = (const float4*)(x + (size_t)r * Dm);

    float4 v[8];
    float s = 0.f, s2 = 0.f;
    #pragma unroll
    for (int i = 0; i < 8; i++) {
        v[i] = xr[lane + i * 32];
        s  += v[i].x + v[i].y + v[i].z + v[i].w;
        s2 += v[i].x * v[i].x + v[i].y * v[i].y + v[i].z * v[i].z + v[i].w * v[i].w;
    }
    #pragma unroll
    for (int o = 16; o > 0; o >>= 1) {
        s  += __shfl_xor_sync(0xffffffffu, s,  o);
        s2 += __shfl_xor_sync(0xffffffffu, s2, o);
    }
    float muv = s / (float)Dm;
    float var = s2 / (float)Dm - muv * muv;
    if (lane == 0) {
        g_mu[row] = muv;
        g_rs[row] = rsqrtf(var + 1e-6f);
    }
    uint2* xhp = (uint2*)(xh + (size_t)r * Dm);
    uint2* xlp = xl ? (uint2*)(xl + (size_t)r * Dm) : nullptr;
    #pragma unroll
    for (int i = 0; i < 8; i++) {
        __half h0 = __float2half_rn(v[i].x), h1 = __float2half_rn(v[i].y);
        __half h2 = __float2half_rn(v[i].z), h3 = __float2half_rn(v[i].w);
        uint2 hv;
        __half2 p01, p23;
        p01.x = h0; p01.y = h1; p23.x = h2; p23.y = h3;
        hv.x = *(uint32_t*)&p01; hv.y = *(uint32_t*)&p23;
        xhp[lane + i * 32] = hv;
        if (xlp) {
            uint2 lv;
            lv.x = packh2(v[i].x - __half2float(h0), v[i].y - __half2float(h1));
            lv.y = packh2(v[i].z - __half2float(h2), v[i].w - __half2float(h3));
            xlp[lane + i * 32] = lv;
        }
    }
}

// ============================================================
// 2) weight prep (fp16 single) + fused column constants
// ============================================================
__global__ void wprep_kernel(const float* __restrict__ Wq, const float* __restrict__ Wk,
                             const float* __restrict__ Wv, const float* __restrict__ Wo,
                             const float* __restrict__ gamma, const float* __restrict__ beta,
                             const float* __restrict__ bq, const float* __restrict__ bk,
                             const float* __restrict__ bv) {
    int w = blockIdx.z;
    const float* W = (w == 0) ? Wq : (w == 1) ? Wk : (w == 2) ? Wv : Wo;
    const float* b = (w == 0) ? bq : (w == 1) ? bk : bv;
    __shared__ float ts[64][65];
    int n0 = blockIdx.x * 64, k0 = blockIdx.y * 64;
    int tx = threadIdx.x & 63, ty = threadIdx.x >> 6;

    float s1 = 0.f, s2 = 0.f;
    #pragma unroll
    for (int l = 0; l < 16; l++) {
        int k = ty + l * 4;
        float wv = W[(size_t)(k0 + k) * Dm + n0 + tx];
        float g = (w < 3) ? gamma[k0 + k] : 1.f;
        float gw = g * wv;
        ts[k][tx] = gw;
        if (w < 3) { s1 += gw; s2 += beta[k0 + k] * wv; }
    }
    if (w < 3) {
        if (k0 == 0 && ty == 0) s2 += b[n0 + tx];
        atomicAdd(&g_c1[w * Dm + n0 + tx], s1);
        atomicAdd(&g_c2[w * Dm + n0 + tx], s2);
    }
    __syncthreads();
    __half* whp = g_wh + (size_t)w * Dm * Dm;
    #pragma unroll
    for (int l = 0; l < 16; l++) {
        int n = ty + l * 4;
        size_t o = (size_t)(n0 + n) * Dm + k0 + tx;
        whp[o] = __float2half_rn(ts[tx][n]);
    }
}

// ============================================================
// 3) GEMM common pieces. NPROD=2: AhBh+AlBh. NPROD=1: AhBh only.
// ============================================================
#define BM 128
#define BN 128
#define BK 32
#define KBYTES 64
#define NSTG  3
#define NT    32

#define SW(r, kc) ((uint32_t)((r) * KBYTES + ((((kc) ^ (((r) >> 1) & 3))) << 4)))

template<int NPROD>
__device__ __forceinline__ void gemm_mainloop(
    uint32_t sbase, int tid, int lane, int warpM, int warpN,
    const __half* Ah, const __half* Al, const __half* Bh,
    int m0, int n0, float acc[4][4][4])
{
    const int STG_T = (NPROD + 1) * 8192;
    auto prefetch = [&](int t) {
        int s = t % NSTG;
        int kb = t * BK;
        uint32_t st = sbase + s * STG_T;
        #pragma unroll
        for (int l = 0; l < (NPROD + 1) * 2; l++) {
            int e = tid + l * 256;
            int tile = e >> 9;              // 0:Ah [1:Al] last:Bh
            int idx = e & 511;
            int r = idx >> 2, kc = idx & 3;
            const __half* p = (tile == 0) ? Ah : (NPROD == 2 && tile == 1) ? Al : Bh;
            int rb = (tile < NPROD) ? m0 : n0;
            cp16(st + tile * 8192 + SW(r, kc), p + (size_t)(rb + r) * Dm + kb + kc * 8);
        }
    };

    prefetch(0); asm volatile("cp.async.commit_group;\n" ::: "memory");
    prefetch(1); asm volatile("cp.async.commit_group;\n" ::: "memory");

    for (int t = 0; t < NT; t++) {
        asm volatile("cp.async.wait_group 1;\n" ::: "memory");
        __syncthreads();
        if (t + 2 < NT) prefetch(t + 2);
        asm volatile("cp.async.commit_group;\n" ::: "memory");

        uint32_t st = sbase + (t % NSTG) * STG_T;
        uint32_t sAh = st, sAl = st + 8192, sBh = st + NPROD * 8192;
        #pragma unroll
        for (int ks = 0; ks < 2; ks++) {
            uint32_t ah[4][4], al[4][4];
            #pragma unroll
            for (int mf = 0; mf < 4; mf++) {
                int row = warpM * 64 + mf * 16 + (lane & 15);
                int ch = ks * 2 + (lane >> 4);
                uint32_t sw = SW(row, ch);
                ldmA(sAh + sw, ah[mf][0], ah[mf][1], ah[mf][2], ah[mf][3]);
                if (NPROD == 2)
                    ldmA(sAl + sw, al[mf][0], al[mf][1], al[mf][2], al[mf][3]);
            }
            #pragma unroll
            for (int nf2 = 0; nf2 < 2; nf2++) {
                int nrow = warpN * 32 + nf2 * 16 + (lane & 7) + ((lane >> 4) << 3);
                int ch = ks * 2 + ((lane >> 3) & 1);
                uint32_t swb = SW(nrow, ch);
                uint32_t r0, r1, r2, r3;
                ldmA(sBh + swb, r0, r1, r2, r3);
                #pragma unroll
                for (int mf = 0; mf < 4; mf++) {
                    mma16816(acc[mf][2*nf2],   ah[mf], r0, r1);
                    mma16816(acc[mf][2*nf2+1], ah[mf], r2, r3);
                    if (NPROD == 2) {
                        mma16816(acc[mf][2*nf2],   al[mf], r0, r1);
                        mma16816(acc[mf][2*nf2+1], al[mf], r2, r3);
                    }
                }
            }
        }
    }
}

// ---- merged Q/K/V projection GEMM (Q,K: 2-product; V: 1-product) ----
__global__ void __launch_bounds__(256, 2) gemm_qkv_kernel() {
    extern __shared__ char smem[];
    uint32_t sbase = smem_u32(smem);
    int tid = threadIdx.x, lane = tid & 31, wid = tid >> 5;
    int warpM = wid & 1, warpN = wid >> 1;
    int m0 = blockIdx.y * BM, n0 = blockIdx.x * BN;
    int z = blockIdx.z;                   // 0:Q 1:K 2:V

    float acc[4][4][4] = {};
    if (z == 2) {
        gemm_mainloop<1>(sbase, tid, lane, warpM, warpN,
                         g_xh_v, nullptr, g_wh + 2 * (size_t)Dm * Dm, m0, n0, acc);
    } else {
        const __half* Ah = (z == 0) ? g_xh_q : g_xh_k;
        const __half* Al = (z == 0) ? g_xl_q : g_xl_k;
        gemm_mainloop<2>(sbase, tid, lane, warpM, warpN,
                         Ah, Al, g_wh + (size_t)z * Dm * Dm, m0, n0, acc);
    }

    const float* c1 = g_c1 + z * Dm;
    const float* c2 = g_c2 + z * Dm;
    const float* rs = g_rs + z * NROWS;
    const float* mu = g_mu + z * NROWS;

    int groupID = lane >> 2, tg = lane & 3;
    #pragma unroll
    for (int mf = 0; mf < 4; mf++) {
        #pragma unroll
        for (int half = 0; half < 2; half++) {
            int r = m0 + warpM * 64 + mf * 16 + groupID + half * 8;
            float rsv = rs[r], muv = mu[r];
            int b = r >> 11, srow = r & 2047;
            #pragma unroll
            for (int nf = 0; nf < 4; nf++) {
                int c = n0 + warpN * 32 + nf * 8 + 2 * tg;
                float x0 = acc[mf][nf][2 * half + 0];
                float x1 = acc[mf][nf][2 * half + 1];
                float2 c1v = *(const float2*)(c1 + c);
                float2 c2v = *(const float2*)(c2 + c);
                float o0 = rsv * (x0 - muv * c1v.x) + c2v.x;
                float o1 = rsv * (x1 - muv * c1v.y) + c2v.y;
                if (z == 0) { o0 *= LOG2E; o1 *= LOG2E; }
                __half h0 = __float2half_rn(o0);
                __half h1 = __float2half_rn(o1);
                int hd = c >> 6, dd = c & 63;
                int bh = b * Hh + hd;
                if (z == 2) {
                    size_t a0 = ((size_t)(bh * DHd + dd)) * Ss + srow;
                    size_t a1 = ((size_t)(bh * DHd + dd + 1)) * Ss + srow;
                    g_vh[a0] = h0; g_vh[a1] = h1;
                } else if (z == 1) {
                    size_t ad = ((size_t)(bh * Ss + srow)) * DHd + dd;
                    __half2 hp; hp.x = h0; hp.y = h1;
                    *(uint32_t*)(g_kh + ad) = *(uint32_t*)&hp;
                } else {
                    float l0 = o0 - __half2float(h0);
                    float l1 = o1 - __half2float(h1);
                    size_t ad = ((size_t)(bh * Ss + srow)) * DHd + dd;
                    __half2 hp; hp.x = h0; hp.y = h1;
                    *(uint32_t*)(g_qh + ad) = *(uint32_t*)&hp;
                    *(uint32_t*)(g_ql + ad) = packh2(l0, l1);
                }
            }
        }
    }
}

// ---- O projection GEMM (1-product): +bias +residual, fp32 out ----
__global__ void __launch_bounds__(256, 2) gemm_o_kernel(
    const float* __restrict__ bo, const float* __restrict__ resid,
    float* __restrict__ outF)
{
    extern __shared__ char smem[];
    uint32_t sbase = smem_u32(smem);
    int tid = threadIdx.x, lane = tid & 31, wid = tid >> 5;
    int warpM = wid & 1, warpN = wid >> 1;
    int m0 = blockIdx.y * BM, n0 = blockIdx.x * BN;

    float acc[4][4][4] = {};
    gemm_mainloop<1>(sbase, tid, lane, warpM, warpN, g_aoh, nullptr,
                     g_wh + 3 * (size_t)Dm * Dm, m0, n0, acc);

    int groupID = lane >> 2, tg = lane & 3;
    #pragma unroll
    for (int mf = 0; mf < 4; mf++) {
        #pragma unroll
        for (int half = 0; half < 2; half++) {
            int r = m0 + warpM * 64 + mf * 16 + groupID + half * 8;
            #pragma unroll
            for (int nf = 0; nf < 4; nf++) {
                int c = n0 + warpN * 32 + nf * 8 + 2 * tg;
                float x0 = acc[mf][nf][2 * half + 0];
                float x1 = acc[mf][nf][2 * half + 1];
                float2 bo2 = *(const float2*)(bo + c);
                float2 q2  = *(const float2*)(resid + (size_t)r * Dm + c);
                float2 o;
                o.x = x0 + bo2.x + q2.x;
                o.y = x1 + bo2.y + q2.y;
                *(float2*)(outF + (size_t)r * Dm + c) = o;
            }
        }
    }
}

// ============================================================
// 4) tensor-core causal attention, fp16 (unchanged from R15).
// ============================================================
__device__ __forceinline__ void loadKV(int bh, int t, uint32_t base, int tid) {
    int kt = t * 64;
    const __half* khp = g_kh + ((size_t)bh * Ss + kt) * DHd;
    const __half* vhp = g_vh + (size_t)bh * DHd * Ss + kt;
    #pragma unroll
    for (int l = 0; l < 2; l++) {
        int e = tid + l * 256;
        int row = e >> 3, c = e & 7;
        uint32_t d = row * 128 + ((c ^ (row & 7)) << 4);
        cp16(base + d,        khp + (size_t)row * DHd + c * 8);
        cp16(base + 8192 + d, vhp + (size_t)row * Ss + c * 8);
    }
}

#define KVB 16384

__global__ void __launch_bounds__(256, 2) attn_mma_kernel() {
    extern __shared__ char smraw[];
    uint32_t sb = smem_u32(smraw);
    const uint32_t QHs = sb;
    const uint32_t KVs = sb + 32768;
    int tid = threadIdx.x, lane = tid & 31, wid = tid >> 5;
    int groupID = lane >> 2, tg = lane & 3;
    int bh = blockIdx.y;
    int mt = (int)(gridDim.x - 1) - (int)blockIdx.x;
    int q0 = mt * 128;
    int numt = 2 * mt + 2;

    const __half* qhp = g_qh + ((size_t)bh * Ss + q0) * DHd;
    const __half* qlp = g_ql + ((size_t)bh * Ss + q0) * DHd;

    #pragma unroll
    for (int l = 0; l < 4; l++) {
        int e = tid + l * 256;
        int row = e >> 3, c = e & 7;
        uint32_t d = row * 128 + ((c ^ (row & 7)) << 4);
        cp16(QHs + d,         qhp + (size_t)row * DHd + c * 8);
        cp16(QHs + 16384 + d, qlp + (size_t)row * DHd + c * 8);
    }
    asm volatile("cp.async.commit_group;\n" ::: "memory");
    loadKV(bh, 0, KVs, tid);
    asm volatile("cp.async.commit_group;\n" ::: "memory");
    asm volatile("cp.async.wait_group 1;\n" ::: "memory");
    __syncthreads();

    uint32_t qh[4][4];
    #pragma unroll
    for (int kf = 0; kf < 4; kf++) {
        int row = wid * 16 + (lane & 15);
        int ch = 2 * kf + (lane >> 4);
        uint32_t ad = QHs + row * 128 + ((ch ^ (row & 7)) << 4);
        ldmA(ad, qh[kf][0], qh[kf][1], qh[kf][2], qh[kf][3]);
    }

    float m[2] = {-1e30f, -1e30f}, lsum[2] = {0.f, 0.f};
    float oacc[8][4] = {};

    for (int t = 0; t < numt; t++) {
        if (t + 1 < numt) loadKV(bh, t + 1, KVs + ((t + 1) & 1) * KVB, tid);
        asm volatile("cp.async.commit_group;\n" ::: "memory");
        asm volatile("cp.async.wait_group 1;\n" ::: "memory");
        __syncthreads();
        uint32_t KB = KVs + (t & 1) * KVB;

        // ---- S = Q K^T (2 products: (qh+ql)*Kh) ----
        float sacc[8][4] = {};
        #pragma unroll
        for (int kf = 0; kf < 4; kf++) {
            uint32_t qlf[4];
            {
                int row = wid * 16 + (lane & 15);
                int ch = 2 * kf + (lane >> 4);
                uint32_t ad = QHs + 16384 + row * 128 + ((ch ^ (row & 7)) << 4);
                ldmA(ad, qlf[0], qlf[1], qlf[2], qlf[3]);
            }
            #pragma unroll
            for (int nf2 = 0; nf2 < 4; nf2++) {
                int row = nf2 * 16 + (lane & 15);
                int ch = 2 * kf + (lane >> 4);
                uint32_t sw = row * 128 + ((ch ^ (row & 7)) << 4);
                uint32_t r0, r1, r2, r3;
                ldmA(KB + sw, r0, r1, r2, r3);               // Kh
                mma16816(sacc[2 * nf2],     qh[kf], r0, r2);
                mma16816(sacc[2 * nf2 + 1], qh[kf], r1, r3);
                mma16816(sacc[2 * nf2],     qlf,    r0, r2);
                mma16816(sacc[2 * nf2 + 1], qlf,    r1, r3);
            }
        }

        if (t >= numt - 2) {
            int kt = t * 64;
            int qrow = q0 + wid * 16 + groupID;
            #pragma unroll
            for (int nf = 0; nf < 8; nf++) {
                int k0 = kt + nf * 8 + 2 * tg;
                if (k0     > qrow)     sacc[nf][0] = -1e30f;
                if (k0 + 1 > qrow)     sacc[nf][1] = -1e30f;
                if (k0     > qrow + 8) sacc[nf][2] = -1e30f;
                if (k0 + 1 > qrow + 8) sacc[nf][3] = -1e30f;
            }
        }

        float alpha[2];
        #pragma unroll
        for (int h = 0; h < 2; h++) {
            float rm = -1e30f;
            #pragma unroll
            for (int nf = 0; nf < 8; nf++)
                rm = fmaxf(rm, fmaxf(sacc[nf][2 * h], sacc[nf][2 * h + 1]));
            rm = fmaxf(rm, __shfl_xor_sync(0xffffffffu, rm, 1));
            rm = fmaxf(rm, __shfl_xor_sync(0xffffffffu, rm, 2));
            float mn = fmaxf(m[h], rm);
            alpha[h] = ex2f(m[h] - mn);
            m[h] = mn;
            float ls = 0.f;
            #pragma unroll
            for (int nf = 0; nf < 8; nf++) {
                float p0 = exp2poly(sacc[nf][2 * h]     - mn);
                float p1 = exp2poly(sacc[nf][2 * h + 1] - mn);
                sacc[nf][2 * h] = p0; sacc[nf][2 * h + 1] = p1;
                ls += p0 + p1;
            }
            lsum[h] = lsum[h] * alpha[h] + ls;
        }
        #pragma unroll
        for (int nd = 0; nd < 8; nd++) {
            oacc[nd][0] *= alpha[0]; oacc[nd][1] *= alpha[0];
            oacc[nd][2] *= alpha[1]; oacc[nd][3] *= alpha[1];
        }

        uint32_t pah[4][4];
        #pragma unroll
        for (int kf = 0; kf < 4; kf++) {
            #pragma unroll
            for (int q = 0; q < 4; q++) {
                int nf = 2 * kf + (q >> 1);
                pah[kf][q] = packh2(sacc[nf][(q & 1) * 2], sacc[nf][(q & 1) * 2 + 1]);
            }
        }

        // ---- O += P V (1 product: p_fp16 * Vh) ----
        #pragma unroll
        for (int kf = 0; kf < 4; kf++) {
            #pragma unroll
            for (int nd2 = 0; nd2 < 4; nd2++) {
                int row = nd2 * 16 + (lane & 15);
                int ch = 2 * kf + (lane >> 4);
                uint32_t sw = row * 128 + ((ch ^ (row & 7)) << 4);
                uint32_t r0, r1, r2, r3;
                ldmA(KB + 8192 + sw, r0, r1, r2, r3);         // Vh
                mma16816(oacc[2 * nd2],     pah[kf], r0, r2);
                mma16816(oacc[2 * nd2 + 1], pah[kf], r1, r3);
            }
        }
        __syncthreads();
    }

    #pragma unroll
    for (int h = 0; h < 2; h++) {
        lsum[h] += __shfl_xor_sync(0xffffffffu, lsum[h], 1);
        lsum[h] += __shfl_xor_sync(0xffffffffu, lsum[h], 2);
    }
    int b = bh >> 4, hd = bh & 15;
    #pragma unroll
    for (int h = 0; h < 2; h++) {
        int q = q0 + wid * 16 + groupID + 8 * h;
        float inv = 1.f / lsum[h];
        size_t rowbase = ((size_t)(b * Ss + q)) * Dm + hd * 64;
        #pragma unroll
        for (int nd = 0; nd < 8; nd++) {
            float x0 = oacc[nd][2 * h] * inv, x1 = oacc[nd][2 * h + 1] * inv;
            size_t ad = rowbase + nd * 8 + 2 * tg;
            *(uint32_t*)(g_aoh + ad) = packh2(x0, x1);
        }
    }
}

// ============================================================
// launch — wprep forked onto a side stream (overlaps ln_split)
// ============================================================
extern "C" void kernel_launch(void* const* d_in, const int* in_sizes, int n_in,
                              void* d_out, int out_size) {
    const float* Q     = (const float*)d_in[0];
    const float* K     = (const float*)d_in[1];
    const float* V     = (const float*)d_in[2];
    const float* Wq    = (const float*)d_in[3];
    const float* bq    = (const float*)d_in[4];
    const float* Wk    = (const float*)d_in[5];
    const float* bk    = (const float*)d_in[6];
    const float* Wv    = (const float*)d_in[7];
    const float* bv    = (const float*)d_in[8];
    const float* Wo    = (const float*)d_in[9];
    const float* bo    = (const float*)d_in[10];
    const float* gamma = (const float*)d_in[11];
    const float* beta  = (const float*)d_in[12];
    float* out = (float*)d_out;

    float *c1_p, *c2_p;
    cudaGetSymbolAddress((void**)&c1_p, g_c1);
    cudaGetSymbolAddress((void**)&c2_p, g_c2);

    cudaMemsetAsync(c1_p, 0, 3 * Dm * sizeof(float));
    cudaMemsetAsync(c2_p, 0, 3 * Dm * sizeof(float));

    // fork: wprep on side stream, ln_split on main stream
    cudaStream_t side;
    cudaEvent_t evFork, evJoin;
    cudaStreamCreateWithFlags(&side, cudaStreamNonBlocking);
    cudaEventCreateWithFlags(&evFork, cudaEventDisableTiming);
    cudaEventCreateWithFlags(&evJoin, cudaEventDisableTiming);

    cudaEventRecord(evFork, 0);
    cudaStreamWaitEvent(side, evFork, 0);
    wprep_kernel<<<dim3(16, 16, 4), 256, 0, side>>>(Wq, Wk, Wv, Wo, gamma, beta,
                                                    bq, bk, bv);
    cudaEventRecord(evJoin, side);

    ln_split_kernel<<<3 * NROWS / 8, 256>>>(Q, K, V);
    cudaStreamWaitEvent(0, evJoin, 0);

    size_t qkv_smem = NSTG * 3 * 8192;   // 72K (V CTAs use first 48K)
    size_t o_smem   = NSTG * 2 * 8192;   // 48K
    cudaFuncSetAttribute(gemm_qkv_kernel, cudaFuncAttributeMaxDynamicSharedMemorySize, (int)qkv_smem);
    cudaFuncSetAttribute(gemm_o_kernel,   cudaFuncAttributeMaxDynamicSharedMemorySize, (int)o_smem);

    gemm_qkv_kernel<<<dim3(Dm / BN, NROWS / BM, 3), 256, qkv_smem>>>();

    size_t asmem = 32768 + 2 * KVB;   // 65536
    cudaFuncSetAttribute(attn_mma_kernel, cudaFuncAttributeMaxDynamicSharedMemorySize, (int)asmem);
    attn_mma_kernel<<<dim3(16, 64), 256, asmem>>>();

    gemm_o_kernel<<<dim3(Dm / BN, NROWS / BM), 256, o_smem>>>(bo, Q, out);
}

// round 17
// speedup vs baseline: 1.8588x; 1.0529x over previous
#include <cuda_runtime.h>
#include <cuda_fp16.h>
#include <cstdint>
#include <math.h>

#define Dm 1024
#define Hh 16
#define DHd 64
#define Bb 4
#define Ss 2048
#define NROWS (Bb*Ss)   // 8192
#define LOG2E 1.4426950408889634f

// ---------------- static device scratch ----------------
__device__ float g_mu[3*NROWS];
__device__ float g_rs[3*NROWS];
__device__ __half g_xh_q[NROWS*Dm]; __device__ __half g_xl_q[NROWS*Dm];
__device__ __half g_xh_k[NROWS*Dm]; __device__ __half g_xl_k[NROWS*Dm];
__device__ __half g_xh_v[NROWS*Dm];                 // V x-side single fp16
__device__ __half g_wh[4*Dm*Dm];
__device__ float g_c1[3*Dm];
__device__ float g_c2[3*Dm];
__device__ __half g_qh[NROWS*Dm], g_ql[NROWS*Dm];  // [bh][s][d], *LOG2E
__device__ __half g_kh[NROWS*Dm];                  // [bh][s][d], single fp16
__device__ __half g_vh[NROWS*Dm];                  // [bh][d][s], single fp16
__device__ __half g_aoh[NROWS*Dm];                 // [b*s][D], single fp16

// ---------------- helpers ----------------
__device__ __forceinline__ uint32_t smem_u32(const void* p) {
    uint32_t a;
    asm("{ .reg .u64 t; cvta.to.shared.u64 t, %1; cvt.u32.u64 %0, t; }" : "=r"(a) : "l"(p));
    return a;
}
__device__ __forceinline__ void cp16(uint32_t s, const void* g) {
    asm volatile("cp.async.cg.shared.global [%0], [%1], 16;\n" :: "r"(s), "l"(g));
}
__device__ __forceinline__ void ldmA(uint32_t addr, uint32_t& r0, uint32_t& r1,
                                     uint32_t& r2, uint32_t& r3) {
    asm volatile("ldmatrix.sync.aligned.m8n8.x4.shared.b16 {%0,%1,%2,%3}, [%4];"
                 : "=r"(r0), "=r"(r1), "=r"(r2), "=r"(r3) : "r"(addr));
}
__device__ __forceinline__ void mma16816(float* c, const uint32_t* a,
                                         uint32_t b0, uint32_t b1) {
    asm volatile("mma.sync.aligned.m16n8k16.row.col.f32.f16.f16.f32 "
                 "{%0,%1,%2,%3}, {%4,%5,%6,%7}, {%8,%9}, {%0,%1,%2,%3};"
                 : "+f"(c[0]), "+f"(c[1]), "+f"(c[2]), "+f"(c[3])
                 : "r"(a[0]), "r"(a[1]), "r"(a[2]), "r"(a[3]), "r"(b0), "r"(b1));
}
__device__ __forceinline__ float ex2f(float x) {
    float r; asm("ex2.approx.f32 %0, %1;" : "=f"(r) : "f"(x)); return r;
}
__device__ __forceinline__ uint32_t packh2(float a, float b) {
    __half2 t;
    t.x = __float2half_rn(a);
    t.y = __float2half_rn(b);
    return *(uint32_t*)&t;
}

// packed-fp16 2^z for z<=0; exact 0 below cutoff (-1e30 mask -> 0).
// p' = 2*2^f via doubled poly keeps result normal after exponent insert.
__device__ __forceinline__ uint32_t exp2_h2(float z0, float z1) {
    __half2 z = __floats2half2_rn(z0, z1);
    const __half2 lo = __floats2half2_rn(-13.5f, -13.5f);
    __half2 msk = __hge2(z, lo);              // 1.0 / 0.0 per lane
    z = __hmax2(z, lo);
    const __half2 cBig = __floats2half2_rn(1552.f, 1552.f);
    __half2 t = __hadd2(z, cBig);             // 1536 + (n+16), n = round(z)
    __half2 f = __hsub2(z, __hsub2(t, cBig)); // f in [-0.5, 0.5]
    const __half2 k4 = __floats2half2_rn(0.019236258f, 0.019236258f);
    const __half2 k3 = __floats2half2_rn(0.111008218f, 0.111008218f);
    const __half2 k2 = __floats2half2_rn(0.480453020f, 0.480453020f);
    const __half2 k1 = __floats2half2_rn(1.386294360f, 1.386294360f);
    const __half2 k0 = __floats2half2_rn(2.0f, 2.0f);
    __half2 p = __hfma2(k4, f, k3);
    p = __hfma2(p, f, k2);
    p = __hfma2(p, f, k1);
    p = __hfma2(p, f, k0);                    // p' = 2*2^f in [1.41, 2.84]
    uint32_t n16 = (*(uint32_t*)&t) - 0x66006600u;   // packed n+16 in [2,16]
    uint32_t pb  = (*(uint32_t*)&p) + (n16 << 10) - 0x44004400u;
    __half2 r = __hmul2(*(__half2*)&pb, msk);
    return *(uint32_t*)&r;
}

// ============================================================
// 1) LN stats + fp16 split — warp per row. V gets hi-only.
// ============================================================
__global__ void ln_split_kernel(const float* __restrict__ Q,
                                const float* __restrict__ K,
                                const float* __restrict__ V) {
    int wid = threadIdx.x >> 5, lane = threadIdx.x & 31;
    int row = blockIdx.x * 8 + wid;
    int which = row >> 13;
    int r = row & (NROWS - 1);
    const float* x; __half* xh; __half* xl;
    if (which == 0)      { x = Q; xh = g_xh_q; xl = g_xl_q; }
    else if (which == 1) { x = K; xh = g_xh_k; xl = g_xl_k; }
    else                 { x = V; xh = g_xh_v; xl = nullptr; }
    const float4* xr = (const float4*)(x + (size_t)r * Dm);

    float4 v[8];
    float s = 0.f, s2 = 0.f;
    #pragma unroll
    for (int i = 0; i < 8; i++) {
        v[i] = xr[lane + i * 32];
        s  += v[i].x + v[i].y + v[i].z + v[i].w;
        s2 += v[i].x * v[i].x + v[i].y * v[i].y + v[i].z * v[i].z + v[i].w * v[i].w;
    }
    #pragma unroll
    for (int o = 16; o > 0; o >>= 1) {
        s  += __shfl_xor_sync(0xffffffffu, s,  o);
        s2 += __shfl_xor_sync(0xffffffffu, s2, o);
    }
    float muv = s / (float)Dm;
    float var = s2 / (float)Dm - muv * muv;
    if (lane == 0) {
        g_mu[row] = muv;
        g_rs[row] = rsqrtf(var + 1e-6f);
    }
    uint2* xhp = (uint2*)(xh + (size_t)r * Dm);
    uint2* xlp = xl ? (uint2*)(xl + (size_t)r * Dm) : nullptr;
    #pragma unroll
    for (int i = 0; i < 8; i++) {
        __half h0 = __float2half_rn(v[i].x), h1 = __float2half_rn(v[i].y);
        __half h2 = __float2half_rn(v[i].z), h3 = __float2half_rn(v[i].w);
        uint2 hv;
        __half2 p01, p23;
        p01.x = h0; p01.y = h1; p23.x = h2; p23.y = h3;
        hv.x = *(uint32_t*)&p01; hv.y = *(uint32_t*)&p23;
        xhp[lane + i * 32] = hv;
        if (xlp) {
            uint2 lv;
            lv.x = packh2(v[i].x - __half2float(h0), v[i].y - __half2float(h1));
            lv.y = packh2(v[i].z - __half2float(h2), v[i].w - __half2float(h3));
            xlp[lane + i * 32] = lv;
        }
    }
}

// ============================================================
// 2) weight prep (fp16 single) + fused column constants
// ============================================================
__global__ void wprep_kernel(const float* __restrict__ Wq, const float* __restrict__ Wk,
                             const float* __restrict__ Wv, const float* __restrict__ Wo,
                             const float* __restrict__ gamma, const float* __restrict__ beta,
                             const float* __restrict__ bq, const float* __restrict__ bk,
                             const float* __restrict__ bv) {
    int w = blockIdx.z;
    const float* W = (w == 0) ? Wq : (w == 1) ? Wk : (w == 2) ? Wv : Wo;
    const float* b = (w == 0) ? bq : (w == 1) ? bk : bv;
    __shared__ float ts[64][65];
    int n0 = blockIdx.x * 64, k0 = blockIdx.y * 64;
    int tx = threadIdx.x & 63, ty = threadIdx.x >> 6;

    float s1 = 0.f, s2 = 0.f;
    #pragma unroll
    for (int l = 0; l < 16; l++) {
        int k = ty + l * 4;
        float wv = W[(size_t)(k0 + k) * Dm + n0 + tx];
        float g = (w < 3) ? gamma[k0 + k] : 1.f;
        float gw = g * wv;
        ts[k][tx] = gw;
        if (w < 3) { s1 += gw; s2 += beta[k0 + k] * wv; }
    }
    if (w < 3) {
        if (k0 == 0 && ty == 0) s2 += b[n0 + tx];
        atomicAdd(&g_c1[w * Dm + n0 + tx], s1);
        atomicAdd(&g_c2[w * Dm + n0 + tx], s2);
    }
    __syncthreads();
    __half* whp = g_wh + (size_t)w * Dm * Dm;
    #pragma unroll
    for (int l = 0; l < 16; l++) {
        int n = ty + l * 4;
        size_t o = (size_t)(n0 + n) * Dm + k0 + tx;
        whp[o] = __float2half_rn(ts[tx][n]);
    }
}

// ============================================================
// 3) GEMM common pieces. NPROD=2: AhBh+AlBh. NPROD=1: AhBh only.
// ============================================================
#define BM 128
#define BN 128
#define BK 32
#define KBYTES 64
#define NSTG  3
#define NT    32

#define SW(r, kc) ((uint32_t)((r) * KBYTES + ((((kc) ^ (((r) >> 1) & 3))) << 4)))

template<int NPROD>
__device__ __forceinline__ void gemm_mainloop(
    uint32_t sbase, int tid, int lane, int warpM, int warpN,
    const __half* Ah, const __half* Al, const __half* Bh,
    int m0, int n0, float acc[4][4][4])
{
    const int STG_T = (NPROD + 1) * 8192;
    auto prefetch = [&](int t) {
        int s = t % NSTG;
        int kb = t * BK;
        uint32_t st = sbase + s * STG_T;
        #pragma unroll
        for (int l = 0; l < (NPROD + 1) * 2; l++) {
            int e = tid + l * 256;
            int tile = e >> 9;
            int idx = e & 511;
            int r = idx >> 2, kc = idx & 3;
            const __half* p = (tile == 0) ? Ah : (NPROD == 2 && tile == 1) ? Al : Bh;
            int rb = (tile < NPROD) ? m0 : n0;
            cp16(st + tile * 8192 + SW(r, kc), p + (size_t)(rb + r) * Dm + kb + kc * 8);
        }
    };

    prefetch(0); asm volatile("cp.async.commit_group;\n" ::: "memory");
    prefetch(1); asm volatile("cp.async.commit_group;\n" ::: "memory");

    for (int t = 0; t < NT; t++) {
        asm volatile("cp.async.wait_group 1;\n" ::: "memory");
        __syncthreads();
        if (t + 2 < NT) prefetch(t + 2);
        asm volatile("cp.async.commit_group;\n" ::: "memory");

        uint32_t st = sbase + (t % NSTG) * STG_T;
        uint32_t sAh = st, sAl = st + 8192, sBh = st + NPROD * 8192;
        #pragma unroll
        for (int ks = 0; ks < 2; ks++) {
            uint32_t ah[4][4], al[4][4];
            #pragma unroll
            for (int mf = 0; mf < 4; mf++) {
                int row = warpM * 64 + mf * 16 + (lane & 15);
                int ch = ks * 2 + (lane >> 4);
                uint32_t sw = SW(row, ch);
                ldmA(sAh + sw, ah[mf][0], ah[mf][1], ah[mf][2], ah[mf][3]);
                if (NPROD == 2)
                    ldmA(sAl + sw, al[mf][0], al[mf][1], al[mf][2], al[mf][3]);
            }
            #pragma unroll
            for (int nf2 = 0; nf2 < 2; nf2++) {
                int nrow = warpN * 32 + nf2 * 16 + (lane & 7) + ((lane >> 4) << 3);
                int ch = ks * 2 + ((lane >> 3) & 1);
                uint32_t swb = SW(nrow, ch);
                uint32_t r0, r1, r2, r3;
                ldmA(sBh + swb, r0, r1, r2, r3);
                #pragma unroll
                for (int mf = 0; mf < 4; mf++) {
                    mma16816(acc[mf][2*nf2],   ah[mf], r0, r1);
                    mma16816(acc[mf][2*nf2+1], ah[mf], r2, r3);
                    if (NPROD == 2) {
                        mma16816(acc[mf][2*nf2],   al[mf], r0, r1);
                        mma16816(acc[mf][2*nf2+1], al[mf], r2, r3);
                    }
                }
            }
        }
    }
}

// ---- merged Q/K/V projection GEMM (Q,K: 2-product; V: 1-product) ----
__global__ void __launch_bounds__(256, 2) gemm_qkv_kernel() {
    extern __shared__ char smem[];
    uint32_t sbase = smem_u32(smem);
    int tid = threadIdx.x, lane = tid & 31, wid = tid >> 5;
    int warpM = wid & 1, warpN = wid >> 1;
    int m0 = blockIdx.y * BM, n0 = blockIdx.x * BN;
    int z = blockIdx.z;                   // 0:Q 1:K 2:V

    float acc[4][4][4] = {};
    if (z == 2) {
        gemm_mainloop<1>(sbase, tid, lane, warpM, warpN,
                         g_xh_v, nullptr, g_wh + 2 * (size_t)Dm * Dm, m0, n0, acc);
    } else {
        const __half* Ah = (z == 0) ? g_xh_q : g_xh_k;
        const __half* Al = (z == 0) ? g_xl_q : g_xl_k;
        gemm_mainloop<2>(sbase, tid, lane, warpM, warpN,
                         Ah, Al, g_wh + (size_t)z * Dm * Dm, m0, n0, acc);
    }

    const float* c1 = g_c1 + z * Dm;
    const float* c2 = g_c2 + z * Dm;
    const float* rs = g_rs + z * NROWS;
    const float* mu = g_mu + z * NROWS;

    int groupID = lane >> 2, tg = lane & 3;
    #pragma unroll
    for (int mf = 0; mf < 4; mf++) {
        #pragma unroll
        for (int half = 0; half < 2; half++) {
            int r = m0 + warpM * 64 + mf * 16 + groupID + half * 8;
            float rsv = rs[r], muv = mu[r];
            int b = r >> 11, srow = r & 2047;
            #pragma unroll
            for (int nf = 0; nf < 4; nf++) {
                int c = n0 + warpN * 32 + nf * 8 + 2 * tg;
                float x0 = acc[mf][nf][2 * half + 0];
                float x1 = acc[mf][nf][2 * half + 1];
                float2 c1v = *(const float2*)(c1 + c);
                float2 c2v = *(const float2*)(c2 + c);
                float o0 = rsv * (x0 - muv * c1v.x) + c2v.x;
                float o1 = rsv * (x1 - muv * c1v.y) + c2v.y;
                if (z == 0) { o0 *= LOG2E; o1 *= LOG2E; }
                __half h0 = __float2half_rn(o0);
                __half h1 = __float2half_rn(o1);
                int hd = c >> 6, dd = c & 63;
                int bh = b * Hh + hd;
                if (z == 2) {
                    size_t a0 = ((size_t)(bh * DHd + dd)) * Ss + srow;
                    size_t a1 = ((size_t)(bh * DHd + dd + 1)) * Ss + srow;
                    g_vh[a0] = h0; g_vh[a1] = h1;
                } else if (z == 1) {
                    size_t ad = ((size_t)(bh * Ss + srow)) * DHd + dd;
                    __half2 hp; hp.x = h0; hp.y = h1;
                    *(uint32_t*)(g_kh + ad) = *(uint32_t*)&hp;
                } else {
                    float l0 = o0 - __half2float(h0);
                    float l1 = o1 - __half2float(h1);
                    size_t ad = ((size_t)(bh * Ss + srow)) * DHd + dd;
                    __half2 hp; hp.x = h0; hp.y = h1;
                    *(uint32_t*)(g_qh + ad) = *(uint32_t*)&hp;
                    *(uint32_t*)(g_ql + ad) = packh2(l0, l1);
                }
            }
        }
    }
}

// ---- O projection GEMM (1-product): +bias +residual, fp32 out ----
__global__ void __launch_bounds__(256, 2) gemm_o_kernel(
    const float* __restrict__ bo, const float* __restrict__ resid,
    float* __restrict__ outF)
{
    extern __shared__ char smem[];
    uint32_t sbase = smem_u32(smem);
    int tid = threadIdx.x, lane = tid & 31, wid = tid >> 5;
    int warpM = wid & 1, warpN = wid >> 1;
    int m0 = blockIdx.y * BM, n0 = blockIdx.x * BN;

    float acc[4][4][4] = {};
    gemm_mainloop<1>(sbase, tid, lane, warpM, warpN, g_aoh, nullptr,
                     g_wh + 3 * (size_t)Dm * Dm, m0, n0, acc);

    int groupID = lane >> 2, tg = lane & 3;
    #pragma unroll
    for (int mf = 0; mf < 4; mf++) {
        #pragma unroll
        for (int half = 0; half < 2; half++) {
            int r = m0 + warpM * 64 + mf * 16 + groupID + half * 8;
            #pragma unroll
            for (int nf = 0; nf < 4; nf++) {
                int c = n0 + warpN * 32 + nf * 8 + 2 * tg;
                float x0 = acc[mf][nf][2 * half + 0];
                float x1 = acc[mf][nf][2 * half + 1];
                float2 bo2 = *(const float2*)(bo + c);
                float2 q2  = *(const float2*)(resid + (size_t)r * Dm + c);
                float2 o;
                o.x = x0 + bo2.x + q2.x;
                o.y = x1 + bo2.y + q2.y;
                *(float2*)(outF + (size_t)r * Dm + c) = o;
            }
        }
    }
}

// ============================================================
// 4) tensor-core causal attention, fp16.
//    S: 2 products. Softmax: packed-half2 exp. Row sums: MMA vs ones.
// ============================================================
__device__ __forceinline__ void loadKV(int bh, int t, uint32_t base, int tid) {
    int kt = t * 64;
    const __half* khp = g_kh + ((size_t)bh * Ss + kt) * DHd;
    const __half* vhp = g_vh + (size_t)bh * DHd * Ss + kt;
    #pragma unroll
    for (int l = 0; l < 2; l++) {
        int e = tid + l * 256;
        int row = e >> 3, c = e & 7;
        uint32_t d = row * 128 + ((c ^ (row & 7)) << 4);
        cp16(base + d,        khp + (size_t)row * DHd + c * 8);
        cp16(base + 8192 + d, vhp + (size_t)row * Ss + c * 8);
    }
}

#define KVB 16384
#define ONESF 0x3C003C00u

__global__ void __launch_bounds__(256, 2) attn_mma_kernel() {
    extern __shared__ char smraw[];
    uint32_t sb = smem_u32(smraw);
    const uint32_t QHs = sb;
    const uint32_t KVs = sb + 32768;
    int tid = threadIdx.x, lane = tid & 31, wid = tid >> 5;
    int groupID = lane >> 2, tg = lane & 3;
    int bh = blockIdx.y;
    int mt = (int)(gridDim.x - 1) - (int)blockIdx.x;
    int q0 = mt * 128;
    int numt = 2 * mt + 2;

    const __half* qhp = g_qh + ((size_t)bh * Ss + q0) * DHd;
    const __half* qlp = g_ql + ((size_t)bh * Ss + q0) * DHd;

    #pragma unroll
    for (int l = 0; l < 4; l++) {
        int e = tid + l * 256;
        int row = e >> 3, c = e & 7;
        uint32_t d = row * 128 + ((c ^ (row & 7)) << 4);
        cp16(QHs + d,         qhp + (size_t)row * DHd + c * 8);
        cp16(QHs + 16384 + d, qlp + (size_t)row * DHd + c * 8);
    }
    asm volatile("cp.async.commit_group;\n" ::: "memory");
    loadKV(bh, 0, KVs, tid);
    asm volatile("cp.async.commit_group;\n" ::: "memory");
    asm volatile("cp.async.wait_group 1;\n" ::: "memory");
    __syncthreads();

    uint32_t qh[4][4];
    #pragma unroll
    for (int kf = 0; kf < 4; kf++) {
        int row = wid * 16 + (lane & 15);
        int ch = 2 * kf + (lane >> 4);
        uint32_t ad = QHs + row * 128 + ((ch ^ (row & 7)) << 4);
        ldmA(ad, qh[kf][0], qh[kf][1], qh[kf][2], qh[kf][3]);
    }

    float m[2] = {-1e30f, -1e30f}, lsum[2] = {0.f, 0.f};
    float oacc[8][4] = {};

    for (int t = 0; t < numt; t++) {
        if (t + 1 < numt) loadKV(bh, t + 1, KVs + ((t + 1) & 1) * KVB, tid);
        asm volatile("cp.async.commit_group;\n" ::: "memory");
        asm volatile("cp.async.wait_group 1;\n" ::: "memory");
        __syncthreads();
        uint32_t KB = KVs + (t & 1) * KVB;

        // ---- S = Q K^T (2 products: (qh+ql)*Kh) ----
        float sacc[8][4] = {};
        #pragma unroll
        for (int kf = 0; kf < 4; kf++) {
            uint32_t qlf[4];
            {
                int row = wid * 16 + (lane & 15);
                int ch = 2 * kf + (lane >> 4);
                uint32_t ad = QHs + 16384 + row * 128 + ((ch ^ (row & 7)) << 4);
                ldmA(ad, qlf[0], qlf[1], qlf[2], qlf[3]);
            }
            #pragma unroll
            for (int nf2 = 0; nf2 < 4; nf2++) {
                int row = nf2 * 16 + (lane & 15);
                int ch = 2 * kf + (lane >> 4);
                uint32_t sw = row * 128 + ((ch ^ (row & 7)) << 4);
                uint32_t r0, r1, r2, r3;
                ldmA(KB + sw, r0, r1, r2, r3);               // Kh
                mma16816(sacc[2 * nf2],     qh[kf], r0, r2);
                mma16816(sacc[2 * nf2 + 1], qh[kf], r1, r3);
                mma16816(sacc[2 * nf2],     qlf,    r0, r2);
                mma16816(sacc[2 * nf2 + 1], qlf,    r1, r3);
            }
        }

        if (t >= numt - 2) {
            int kt = t * 64;
            int qrow = q0 + wid * 16 + groupID;
            #pragma unroll
            for (int nf = 0; nf < 8; nf++) {
                int k0 = kt + nf * 8 + 2 * tg;
                if (k0     > qrow)     sacc[nf][0] = -1e30f;
                if (k0 + 1 > qrow)     sacc[nf][1] = -1e30f;
                if (k0     > qrow + 8) sacc[nf][2] = -1e30f;
                if (k0 + 1 > qrow + 8) sacc[nf][3] = -1e30f;
            }
        }

        // ---- online max + rescale ----
        float alpha[2];
        #pragma unroll
        for (int h = 0; h < 2; h++) {
            float rm = -1e30f;
            #pragma unroll
            for (int nf = 0; nf < 8; nf++)
                rm = fmaxf(rm, fmaxf(sacc[nf][2 * h], sacc[nf][2 * h + 1]));
            rm = fmaxf(rm, __shfl_xor_sync(0xffffffffu, rm, 1));
            rm = fmaxf(rm, __shfl_xor_sync(0xffffffffu, rm, 2));
            float mn = fmaxf(m[h], rm);
            alpha[h] = ex2f(m[h] - mn);
            m[h] = mn;
            lsum[h] *= alpha[h];
        }
        #pragma unroll
        for (int nd = 0; nd < 8; nd++) {
            oacc[nd][0] *= alpha[0]; oacc[nd][1] *= alpha[0];
            oacc[nd][2] *= alpha[1]; oacc[nd][3] *= alpha[1];
        }

        // ---- P = exp2(S - m), packed fp16 directly ----
        uint32_t pah[4][4];
        #pragma unroll
        for (int kf = 0; kf < 4; kf++) {
            #pragma unroll
            for (int q = 0; q < 4; q++) {
                int nf = 2 * kf + (q >> 1);
                int h = q & 1;
                pah[kf][q] = exp2_h2(sacc[nf][2 * h] - m[h],
                                     sacc[nf][2 * h + 1] - m[h]);
            }
        }

        // ---- row sums via MMA against ones ----
        float osum[4] = {};
        #pragma unroll
        for (int kf = 0; kf < 4; kf++)
            mma16816(osum, pah[kf], ONESF, ONESF);

        // ---- O += P V ----
        #pragma unroll
        for (int kf = 0; kf < 4; kf++) {
            #pragma unroll
            for (int nd2 = 0; nd2 < 4; nd2++) {
                int row = nd2 * 16 + (lane & 15);
                int ch = 2 * kf + (lane >> 4);
                uint32_t sw = row * 128 + ((ch ^ (row & 7)) << 4);
                uint32_t r0, r1, r2, r3;
                ldmA(KB + 8192 + sw, r0, r1, r2, r3);         // Vh
                mma16816(oacc[2 * nd2],     pah[kf], r0, r2);
                mma16816(oacc[2 * nd2 + 1], pah[kf], r1, r3);
            }
        }
        lsum[0] += osum[0];
        lsum[1] += osum[2];
        __syncthreads();
    }

    int b = bh >> 4, hd = bh & 15;
    #pragma unroll
    for (int h = 0; h < 2; h++) {
        int q = q0 + wid * 16 + groupID + 8 * h;
        float inv = 1.f / lsum[h];
        size_t rowbase = ((size_t)(b * Ss + q)) * Dm + hd * 64;
        #pragma unroll
        for (int nd = 0; nd < 8; nd++) {
            float x0 = oacc[nd][2 * h] * inv, x1 = oacc[nd][2 * h + 1] * inv;
            size_t ad = rowbase + nd * 8 + 2 * tg;
            *(uint32_t*)(g_aoh + ad) = packh2(x0, x1);
        }
    }
}

// ============================================================
// launch — wprep forked onto a side stream (overlaps ln_split)
// ============================================================
extern "C" void kernel_launch(void* const* d_in, const int* in_sizes, int n_in,
                              void* d_out, int out_size) {
    const float* Q     = (const float*)d_in[0];
    const float* K     = (const float*)d_in[1];
    const float* V     = (const float*)d_in[2];
    const float* Wq    = (const float*)d_in[3];
    const float* bq    = (const float*)d_in[4];
    const float* Wk    = (const float*)d_in[5];
    const float* bk    = (const float*)d_in[6];
    const float* Wv    = (const float*)d_in[7];
    const float* bv    = (const float*)d_in[8];
    const float* Wo    = (const float*)d_in[9];
    const float* bo    = (const float*)d_in[10];
    const float* gamma = (const float*)d_in[11];
    const float* beta  = (const float*)d_in[12];
    float* out = (float*)d_out;

    float *c1_p, *c2_p;
    cudaGetSymbolAddress((void**)&c1_p, g_c1);
    cudaGetSymbolAddress((void**)&c2_p, g_c2);

    cudaMemsetAsync(c1_p, 0, 3 * Dm * sizeof(float));
    cudaMemsetAsync(c2_p, 0, 3 * Dm * sizeof(float));

    cudaStream_t side;
    cudaEvent_t evFork, evJoin;
    cudaStreamCreateWithFlags(&side, cudaStreamNonBlocking);
    cudaEventCreateWithFlags(&evFork, cudaEventDisableTiming);
    cudaEventCreateWithFlags(&evJoin, cudaEventDisableTiming);

    cudaEventRecord(evFork, 0);
    cudaStreamWaitEvent(side, evFork, 0);
    wprep_kernel<<<dim3(16, 16, 4), 256, 0, side>>>(Wq, Wk, Wv, Wo, gamma, beta,
                                                    bq, bk, bv);
    cudaEventRecord(evJoin, side);

    ln_split_kernel<<<3 * NROWS / 8, 256>>>(Q, K, V);
    cudaStreamWaitEvent(0, evJoin, 0);

    size_t qkv_smem = NSTG * 3 * 8192;   // 72K
    size_t o_smem   = NSTG * 2 * 8192;   // 48K
    cudaFuncSetAttribute(gemm_qkv_kernel, cudaFuncAttributeMaxDynamicSharedMemorySize, (int)qkv_smem);
    cudaFuncSetAttribute(gemm_o_kernel,   cudaFuncAttributeMaxDynamicSharedMemorySize, (int)o_smem);

    gemm_qkv_kernel<<<dim3(Dm / BN, NROWS / BM, 3), 256, qkv_smem>>>();

    size_t asmem = 32768 + 2 * KVB;   // 65536
    cudaFuncSetAttribute(attn_mma_kernel, cudaFuncAttributeMaxDynamicSharedMemorySize, (int)asmem);
    attn_mma_kernel<<<dim3(16, 64), 256, asmem>>>();

    gemm_o_kernel<<<dim3(Dm / BN, NROWS / BM), 256, o_smem>>>(bo, Q, out);
}